// round 10
// baseline (speedup 1.0000x reference)
#include <cuda_runtime.h>
#include <cuda_bf16.h>
#include <math.h>

#define NMAX 50000
#define EMAX 600000

// ---------------- scratch (device globals; no allocation allowed) ----------
__device__ __align__(16) float g_supp1[NMAX * 128];
__device__ __align__(16) float g_acc1 [NMAX * 128];
__device__ __align__(16) float g_supp2[NMAX * 128];
__device__ __align__(16) float g_Kb   [128 * 64];
__device__ __align__(16) float g_Vb   [128 * 64];
// CSR build (g_cnt starts zeroed at module load; scanA re-zeros it each call)
__device__ int   g_cnt [NMAX];
__device__ int   g_off [NMAX + 1];
__device__ int   g_cur [NMAX];
__device__ int   g_bsum[256];
__device__ int   g_boff[256];
__device__ __align__(16) int   g_ecol[EMAX];
__device__ __align__(16) float g_eval[EMAX];
// pre-split bf16 weights (hi/lo)
__device__ __align__(16) __nv_bfloat16 g_Mh [128 * 256], g_Ml [128 * 256];
__device__ __align__(16) __nv_bfloat16 g_Ph [256 * 128], g_Pl [256 * 128];
__device__ __align__(16) __nv_bfloat16 g_Wch[128 * 128], g_Wcl[128 * 128];

__device__ __forceinline__ float lrelu(float x) { return x > 0.f ? x : 0.01f * x; }

__device__ __forceinline__ void split_bf16(float x, __nv_bfloat16& h, __nv_bfloat16& l) {
    h = __float2bfloat16(x);
    l = __float2bfloat16(x - __bfloat162float(h));
}

__device__ __forceinline__ void mma_bf16(float* d, const unsigned* a, const unsigned* b) {
    asm volatile(
        "mma.sync.aligned.m16n8k16.row.col.f32.bf16.bf16.f32 "
        "{%0,%1,%2,%3}, {%4,%5,%6,%7}, {%8,%9}, {%0,%1,%2,%3};\n"
        : "+f"(d[0]), "+f"(d[1]), "+f"(d[2]), "+f"(d[3])
        : "r"(a[0]), "r"(a[1]), "r"(a[2]), "r"(a[3]), "r"(b[0]), "r"(b[1]));
}

__device__ __forceinline__ void ldsm_x4(unsigned* r, const __nv_bfloat16* p) {
    unsigned addr = (unsigned)__cvta_generic_to_shared(p);
    asm volatile("ldmatrix.sync.aligned.m8n8.x4.shared.b16 {%0,%1,%2,%3}, [%4];\n"
                 : "=r"(r[0]), "=r"(r[1]), "=r"(r[2]), "=r"(r[3]) : "r"(addr));
}

__device__ __forceinline__ void ldsm_x2t(unsigned* r, const __nv_bfloat16* p) {
    unsigned addr = (unsigned)__cvta_generic_to_shared(p);
    asm volatile("ldmatrix.sync.aligned.m8n8.x2.trans.shared.b16 {%0,%1}, [%2];\n"
                 : "=r"(r[0]), "=r"(r[1]) : "r"(addr));
}

// ---------------- prep: K/V projections + Wcat pack (one kernel) ------------
__global__ void prep_kernel(const float* __restrict__ cond,
                            const float* __restrict__ Wk,
                            const float* __restrict__ Wv,
                            const float* __restrict__ Wmu,
                            const float* __restrict__ Wvar) {
    int o = blockIdx.x * blockDim.x + threadIdx.x;  // 32768 threads
    if (o < 8192) {
        int key = o >> 6, d = o & 63;
        float s = 0.f;
        #pragma unroll 4
        for (int m = 0; m < 128; m++) s += cond[key * 128 + m] * Wk[m * 64 + d];
        g_Kb[o] = s;
    } else if (o < 16384) {
        int o2 = o - 8192;
        int key = o2 >> 6, d = o2 & 63;
        float s = 0.f;
        #pragma unroll 4
        for (int m = 0; m < 128; m++) s += cond[key * 128 + m] * Wv[m * 64 + d];
        g_Vb[o2] = s;
    } else {
        int i = o - 16384;  // 0..16383 = 128*128
        int k = i >> 7, n = i & 127;
        float w = (n < 64) ? Wmu[k * 64 + n] : Wvar[k * 64 + (n - 64)];
        split_bf16(w, g_Wch[i], g_Wcl[i]);
    }
}

// ---------------- fold heads -> split bf16 Mcat, Pcat -----------------------
__global__ void fold_kernel(const float* __restrict__ Wq,
                            const float* __restrict__ Wo) {
    const float scale = 0.17677669529663687f;  // 1/sqrt(32)
    int o = blockIdx.x * blockDim.x + threadIdx.x;  // 65536
    if (o < 32768) {
        int c = o >> 8, hk = o & 255;
        int h = hk >> 7, key = hk & 127;
        float s = 0.f;
        #pragma unroll 8
        for (int d = 0; d < 32; d++)
            s += Wq[c * 64 + h * 32 + d] * g_Kb[key * 64 + h * 32 + d];
        split_bf16(s * scale, g_Mh[o], g_Ml[o]);
    } else {
        int o2 = o - 32768;
        int hk = o2 >> 7, j = o2 & 127;
        int h = hk >> 7, key = hk & 127;
        float s = 0.f;
        #pragma unroll 8
        for (int d = 0; d < 32; d++)
            s += g_Vb[key * 64 + h * 32 + d] * Wo[(h * 32 + d) * 128 + j];
        split_bf16(s, g_Ph[o2], g_Pl[o2]);
    }
}

// ---------------- CSR build -------------------------------------------------
__global__ void hist_kernel(const int* __restrict__ rows, int E) {
    int idx = blockIdx.x * blockDim.x + threadIdx.x;
    int stride = gridDim.x * blockDim.x;
    for (int i = idx; i < E; i += stride) atomicAdd(&g_cnt[rows[i]], 1);
}

__global__ void scanA_kernel(int Nn) {
    __shared__ int s[256];
    int t = threadIdx.x, i = blockIdx.x * 256 + t;
    int v = (i < Nn) ? g_cnt[i] : 0;
    s[t] = v;
    __syncthreads();
    #pragma unroll
    for (int o = 1; o < 256; o <<= 1) {
        int x = (t >= o) ? s[t - o] : 0;
        __syncthreads();
        s[t] += x;
        __syncthreads();
    }
    if (i < Nn) {
        g_off[i] = s[t] - v;
        g_cnt[i] = 0;  // re-zero for next call (invariant across graph replays)
    }
    if (t == 255) g_bsum[blockIdx.x] = s[255];
}

__global__ void scanB_kernel(int nb) {
    __shared__ int s[256];
    int t = threadIdx.x;
    int v = (t < nb) ? g_bsum[t] : 0;
    s[t] = v;
    __syncthreads();
    #pragma unroll
    for (int o = 1; o < 256; o <<= 1) {
        int x = (t >= o) ? s[t - o] : 0;
        __syncthreads();
        s[t] += x;
        __syncthreads();
    }
    g_boff[t] = s[t] - v;
}

__global__ void scanC_kernel(int Nn, int E) {
    int idx = blockIdx.x * blockDim.x + threadIdx.x;
    int stride = gridDim.x * blockDim.x;
    for (int i = idx; i < Nn; i += stride) {
        int o = g_off[i] + g_boff[i >> 8];
        g_off[i] = o;
        g_cur[i] = o;
    }
    if (idx == 0) g_off[Nn] = E;
}

__global__ void scatter_kernel(const int* __restrict__ rows,
                               const int* __restrict__ cols,
                               const float* __restrict__ vals, int E) {
    int idx = blockIdx.x * blockDim.x + threadIdx.x;
    int stride = gridDim.x * blockDim.x;
    for (int i = idx; i < E; i += stride) {
        int r = rows[i];
        int p = atomicAdd(&g_cur[r], 1);
        g_ecol[p] = cols[i];
        g_eval[p] = vals[i];
    }
}

// ============================================================================
// GEMM1: supp1 = leaky(ns_emb[M,256] @ Wh[256,128])
// ============================================================================
__global__ void __launch_bounds__(512) gemm1_kernel(const float* __restrict__ A,
                                                    const float* __restrict__ Wg,
                                                    float* __restrict__ C, int M) {
    constexpr int K = 256, NC = 128, LDA = 40, LDB = 136;
    __shared__ __nv_bfloat16 Ah[128][LDA], Al[128][LDA];
    __shared__ __nv_bfloat16 Bh[32][LDB], Bl[32][LDB];
    int tid = threadIdx.x;
    int warp = tid >> 5, lane = tid & 31;
    int wm = (warp & 3) * 32;
    int wn = (warp >> 2) * 32;
    int row0 = blockIdx.x * 128;
    int r_l = lane & 15, c_l = (lane >> 4) << 3;

    float acc[2][4][4];
    #pragma unroll
    for (int mi = 0; mi < 2; mi++)
        #pragma unroll
        for (int ni = 0; ni < 4; ni++)
            #pragma unroll
            for (int t = 0; t < 4; t++) acc[mi][ni][t] = 0.f;

    float4 pa[2], pb[2];

    auto loadA = [&](int k0) {
        #pragma unroll
        for (int i = 0; i < 2; i++) {
            int v = tid + i * 512;
            int row = v >> 3, q = (v & 7) << 2;
            int gr = row0 + row;
            pa[i] = make_float4(0.f, 0.f, 0.f, 0.f);
            if (gr < M) pa[i] = *(const float4*)(A + (size_t)gr * K + k0 + q);
        }
    };
    auto loadB = [&](int k0) {
        #pragma unroll
        for (int i = 0; i < 2; i++) {
            int v = tid + i * 512;
            int br = v >> 5, bc = (v & 31) << 2;
            pb[i] = *(const float4*)(Wg + (size_t)(k0 + br) * NC + bc);
        }
    };

    loadA(0);
    loadB(0);
    for (int it = 0; it < K / 32; it++) {
        #pragma unroll
        for (int i = 0; i < 2; i++) {
            int v = tid + i * 512;
            int row = v >> 3, q = (v & 7) << 2;
            split_bf16(pa[i].x, Ah[row][q + 0], Al[row][q + 0]);
            split_bf16(pa[i].y, Ah[row][q + 1], Al[row][q + 1]);
            split_bf16(pa[i].z, Ah[row][q + 2], Al[row][q + 2]);
            split_bf16(pa[i].w, Ah[row][q + 3], Al[row][q + 3]);
        }
        #pragma unroll
        for (int i = 0; i < 2; i++) {
            int v = tid + i * 512;
            int br = v >> 5, bc = (v & 31) << 2;
            split_bf16(pb[i].x, Bh[br][bc + 0], Bl[br][bc + 0]);
            split_bf16(pb[i].y, Bh[br][bc + 1], Bl[br][bc + 1]);
            split_bf16(pb[i].z, Bh[br][bc + 2], Bl[br][bc + 2]);
            split_bf16(pb[i].w, Bh[br][bc + 3], Bl[br][bc + 3]);
        }
        __syncthreads();
        if (it < K / 32 - 1) {
            loadA((it + 1) * 32);
            loadB((it + 1) * 32);
        }
        #pragma unroll
        for (int s = 0; s < 2; s++) {
            int ks = s * 16;
            unsigned afh[2][4], afl[2][4];
            #pragma unroll
            for (int mi = 0; mi < 2; mi++) {
                ldsm_x4(afh[mi], &Ah[wm + mi * 16 + r_l][ks + c_l]);
                ldsm_x4(afl[mi], &Al[wm + mi * 16 + r_l][ks + c_l]);
            }
            #pragma unroll
            for (int ni = 0; ni < 4; ni++) {
                unsigned bfh[2], bfl[2];
                ldsm_x2t(bfh, &Bh[ks + r_l][wn + ni * 8]);
                ldsm_x2t(bfl, &Bl[ks + r_l][wn + ni * 8]);
                #pragma unroll
                for (int mi = 0; mi < 2; mi++) {
                    mma_bf16(acc[mi][ni], afh[mi], bfh);
                    mma_bf16(acc[mi][ni], afh[mi], bfl);
                    mma_bf16(acc[mi][ni], afl[mi], bfh);
                }
            }
        }
        __syncthreads();
    }
    #pragma unroll
    for (int mi = 0; mi < 2; mi++)
        #pragma unroll
        for (int ni = 0; ni < 4; ni++) {
            int r = row0 + wm + mi * 16 + (lane >> 2);
            int c = wn + ni * 8 + (lane & 3) * 2;
            float v0 = lrelu(acc[mi][ni][0]), v1 = lrelu(acc[mi][ni][1]);
            float v2 = lrelu(acc[mi][ni][2]), v3 = lrelu(acc[mi][ni][3]);
            if (r < M) *(float2*)(C + (size_t)r * NC + c) = make_float2(v0, v1);
            if (r + 8 < M) *(float2*)(C + (size_t)(r + 8) * NC + c) = make_float2(v2, v3);
        }
}

// ============================================================================
// FUSED: supp2 = leaky( softmax( leaky(acc1)@Mcat ) @ Pcat @ Wcat )
// 64-row tiles, 2 CTAs/SM. tile0 = chunk tile offset for pipelining.
// ============================================================================
#define SMEM_FUSED 103424

__global__ void __launch_bounds__(256, 2) attn_fused_kernel(const float* __restrict__ ACC1,
                                                            float* __restrict__ OUT,
                                                            int M, int tile0) {
    extern __shared__ char smem_raw[];
    __nv_bfloat16* Sh = (__nv_bfloat16*)smem_raw;               // [64][264]
    __nv_bfloat16* Sl = Sh + 64 * 264;
    __nv_bfloat16* Bh = (__nv_bfloat16*)(smem_raw + 67584);     // [32][264]
    __nv_bfloat16* Bl = Bh + 32 * 264;
    float* smax = (float*)(smem_raw + 101376);                  // [64][4]
    float* ssum = smax + 256;
    __nv_bfloat16* Xh = Sh;                                     // overlay [64][136]
    __nv_bfloat16* Xl = Sh + 64 * 136;

    int tid = threadIdx.x;
    int warp = tid >> 5, lane = tid & 31;
    int wm = (warp >> 2) * 32;
    int wc = warp & 3;
    int row0 = (tile0 + blockIdx.x) * 64;
    int r_l = lane & 15, c_l = (lane >> 4) << 3;

    // ---------- load X = leaky(acc1 tile), split bf16 ----------
    #pragma unroll
    for (int i = 0; i < 8; i++) {
        int v = tid + i * 256;
        int row = v >> 5, q = (v & 31) << 2;
        int gr = row0 + row;
        float4 a4 = make_float4(0.f, 0.f, 0.f, 0.f);
        if (gr < M) a4 = *(const float4*)(ACC1 + (size_t)gr * 128 + q);
        a4.x = lrelu(a4.x); a4.y = lrelu(a4.y);
        a4.z = lrelu(a4.z); a4.w = lrelu(a4.w);
        split_bf16(a4.x, Xh[row * 136 + q + 0], Xl[row * 136 + q + 0]);
        split_bf16(a4.y, Xh[row * 136 + q + 1], Xl[row * 136 + q + 1]);
        split_bf16(a4.z, Xh[row * 136 + q + 2], Xl[row * 136 + q + 2]);
        split_bf16(a4.w, Xh[row * 136 + q + 3], Xl[row * 136 + q + 3]);
    }
    __syncthreads();

    // GEMM2: L = X @ Mcat   (64x256, K=128)
    int wn2 = wc * 64;
    float accA[2][8][4];
    #pragma unroll
    for (int mi = 0; mi < 2; mi++)
        #pragma unroll
        for (int ni = 0; ni < 8; ni++)
            #pragma unroll
            for (int t = 0; t < 4; t++) accA[mi][ni][t] = 0.f;

    for (int it = 0; it < 4; it++) {
        int k0 = it * 32;
        #pragma unroll
        for (int i = 0; i < 4; i++) {
            int s = tid + i * 256;
            int br = s >> 5, bc = (s & 31) << 3;
            *(uint4*)&Bh[br * 264 + bc] = *(const uint4*)(g_Mh + (size_t)(k0 + br) * 256 + bc);
            *(uint4*)&Bl[br * 264 + bc] = *(const uint4*)(g_Ml + (size_t)(k0 + br) * 256 + bc);
        }
        __syncthreads();
        #pragma unroll
        for (int s = 0; s < 2; s++) {
            int ks = k0 + s * 16;
            unsigned afh[2][4], afl[2][4];
            #pragma unroll
            for (int mi = 0; mi < 2; mi++) {
                ldsm_x4(afh[mi], &Xh[(wm + mi * 16 + r_l) * 136 + ks + c_l]);
                ldsm_x4(afl[mi], &Xl[(wm + mi * 16 + r_l) * 136 + ks + c_l]);
            }
            #pragma unroll
            for (int ni = 0; ni < 8; ni++) {
                unsigned bfh[2], bfl[2];
                ldsm_x2t(bfh, &Bh[(s * 16 + r_l) * 264 + wn2 + ni * 8]);
                ldsm_x2t(bfl, &Bl[(s * 16 + r_l) * 264 + wn2 + ni * 8]);
                #pragma unroll
                for (int mi = 0; mi < 2; mi++) {
                    mma_bf16(accA[mi][ni], afh[mi], bfh);
                    mma_bf16(accA[mi][ni], afh[mi], bfl);
                    mma_bf16(accA[mi][ni], afl[mi], bfh);
                }
            }
        }
        __syncthreads();
    }

    // softmax
    int hbase = (wc >> 1) << 1;
    #pragma unroll
    for (int mi = 0; mi < 2; mi++)
        #pragma unroll
        for (int half = 0; half < 2; half++) {
            float m = -1e30f;
            #pragma unroll
            for (int ni = 0; ni < 8; ni++)
                m = fmaxf(m, fmaxf(accA[mi][ni][2 * half], accA[mi][ni][2 * half + 1]));
            m = fmaxf(m, __shfl_xor_sync(0xffffffffu, m, 1));
            m = fmaxf(m, __shfl_xor_sync(0xffffffffu, m, 2));
            if ((lane & 3) == 0) {
                int rowg = wm + mi * 16 + (lane >> 2) + 8 * half;
                smax[rowg * 4 + wc] = m;
            }
        }
    __syncthreads();
    #pragma unroll
    for (int mi = 0; mi < 2; mi++)
        #pragma unroll
        for (int half = 0; half < 2; half++) {
            int rowg = wm + mi * 16 + (lane >> 2) + 8 * half;
            float mh = fmaxf(smax[rowg * 4 + hbase], smax[rowg * 4 + hbase + 1]);
            float s = 0.f;
            #pragma unroll
            for (int ni = 0; ni < 8; ni++) {
                float e0 = __expf(accA[mi][ni][2 * half] - mh);
                float e1 = __expf(accA[mi][ni][2 * half + 1] - mh);
                accA[mi][ni][2 * half] = e0;
                accA[mi][ni][2 * half + 1] = e1;
                s += e0 + e1;
            }
            s += __shfl_xor_sync(0xffffffffu, s, 1);
            s += __shfl_xor_sync(0xffffffffu, s, 2);
            if ((lane & 3) == 0) ssum[rowg * 4 + wc] = s;
        }
    __syncthreads();
    #pragma unroll
    for (int mi = 0; mi < 2; mi++)
        #pragma unroll
        for (int half = 0; half < 2; half++) {
            int rowg = wm + mi * 16 + (lane >> 2) + 8 * half;
            float inv = 1.f / (ssum[rowg * 4 + hbase] + ssum[rowg * 4 + hbase + 1]);
            #pragma unroll
            for (int ni = 0; ni < 8; ni++) {
                float w0 = accA[mi][ni][2 * half] * inv;
                float w1 = accA[mi][ni][2 * half + 1] * inv;
                int colg = wn2 + ni * 8 + 2 * (lane & 3);
                __nv_bfloat16 h0, l0, h1, l1;
                split_bf16(w0, h0, l0);
                split_bf16(w1, h1, l1);
                *(__nv_bfloat162*)&Sh[rowg * 264 + colg] = __nv_bfloat162(h0, h1);
                *(__nv_bfloat162*)&Sl[rowg * 264 + colg] = __nv_bfloat162(l0, l1);
            }
        }
    __syncthreads();

    // GEMM3: h = S @ Pcat   (64x128, K=256)
    int wn3 = wc * 32;
    float acc3[2][4][4];
    #pragma unroll
    for (int mi = 0; mi < 2; mi++)
        #pragma unroll
        for (int ni = 0; ni < 4; ni++)
            #pragma unroll
            for (int t = 0; t < 4; t++) acc3[mi][ni][t] = 0.f;

    for (int it = 0; it < 8; it++) {
        int k0 = it * 32;
        #pragma unroll
        for (int i = 0; i < 2; i++) {
            int s = tid + i * 256;
            int br = s >> 4, bc = (s & 15) << 3;
            *(uint4*)&Bh[br * 264 + bc] = *(const uint4*)(g_Ph + (size_t)(k0 + br) * 128 + bc);
            *(uint4*)&Bl[br * 264 + bc] = *(const uint4*)(g_Pl + (size_t)(k0 + br) * 128 + bc);
        }
        __syncthreads();
        #pragma unroll
        for (int s = 0; s < 2; s++) {
            int ks = k0 + s * 16;
            unsigned afh[2][4], afl[2][4];
            #pragma unroll
            for (int mi = 0; mi < 2; mi++) {
                ldsm_x4(afh[mi], &Sh[(wm + mi * 16 + r_l) * 264 + ks + c_l]);
                ldsm_x4(afl[mi], &Sl[(wm + mi * 16 + r_l) * 264 + ks + c_l]);
            }
            #pragma unroll
            for (int ni = 0; ni < 4; ni++) {
                unsigned bfh[2], bfl[2];
                ldsm_x2t(bfh, &Bh[(s * 16 + r_l) * 264 + wn3 + ni * 8]);
                ldsm_x2t(bfl, &Bl[(s * 16 + r_l) * 264 + wn3 + ni * 8]);
                #pragma unroll
                for (int mi = 0; mi < 2; mi++) {
                    mma_bf16(acc3[mi][ni], afh[mi], bfh);
                    mma_bf16(acc3[mi][ni], afh[mi], bfl);
                    mma_bf16(acc3[mi][ni], afl[mi], bfh);
                }
            }
        }
        __syncthreads();
    }

    // store h (split bf16) into X overlay (S dead)
    #pragma unroll
    for (int mi = 0; mi < 2; mi++)
        #pragma unroll
        for (int half = 0; half < 2; half++) {
            int rowg = wm + mi * 16 + (lane >> 2) + 8 * half;
            #pragma unroll
            for (int ni = 0; ni < 4; ni++) {
                float v0 = acc3[mi][ni][2 * half];
                float v1 = acc3[mi][ni][2 * half + 1];
                int colg = wn3 + ni * 8 + 2 * (lane & 3);
                __nv_bfloat16 h0, l0, h1, l1;
                split_bf16(v0, h0, l0);
                split_bf16(v1, h1, l1);
                *(__nv_bfloat162*)&Xh[rowg * 136 + colg] = __nv_bfloat162(h0, h1);
                *(__nv_bfloat162*)&Xl[rowg * 136 + colg] = __nv_bfloat162(l0, l1);
            }
        }
    __syncthreads();

    // GEMM4: supp2 = leaky(h @ Wcat)   (64x128, K=128)
    float acc4[2][4][4];
    #pragma unroll
    for (int mi = 0; mi < 2; mi++)
        #pragma unroll
        for (int ni = 0; ni < 4; ni++)
            #pragma unroll
            for (int t = 0; t < 4; t++) acc4[mi][ni][t] = 0.f;

    for (int it = 0; it < 4; it++) {
        int k0 = it * 32;
        #pragma unroll
        for (int i = 0; i < 2; i++) {
            int s = tid + i * 256;
            int br = s >> 4, bc = (s & 15) << 3;
            *(uint4*)&Bh[br * 264 + bc] = *(const uint4*)(g_Wch + (size_t)(k0 + br) * 128 + bc);
            *(uint4*)&Bl[br * 264 + bc] = *(const uint4*)(g_Wcl + (size_t)(k0 + br) * 128 + bc);
        }
        __syncthreads();
        #pragma unroll
        for (int s = 0; s < 2; s++) {
            int ks = k0 + s * 16;
            unsigned afh[2][4], afl[2][4];
            #pragma unroll
            for (int mi = 0; mi < 2; mi++) {
                ldsm_x4(afh[mi], &Xh[(wm + mi * 16 + r_l) * 136 + ks + c_l]);
                ldsm_x4(afl[mi], &Xl[(wm + mi * 16 + r_l) * 136 + ks + c_l]);
            }
            #pragma unroll
            for (int ni = 0; ni < 4; ni++) {
                unsigned bfh[2], bfl[2];
                ldsm_x2t(bfh, &Bh[(s * 16 + r_l) * 264 + wn3 + ni * 8]);
                ldsm_x2t(bfl, &Bl[(s * 16 + r_l) * 264 + wn3 + ni * 8]);
                #pragma unroll
                for (int mi = 0; mi < 2; mi++) {
                    mma_bf16(acc4[mi][ni], afh[mi], bfh);
                    mma_bf16(acc4[mi][ni], afh[mi], bfl);
                    mma_bf16(acc4[mi][ni], afl[mi], bfh);
                }
            }
        }
        __syncthreads();
    }

    #pragma unroll
    for (int mi = 0; mi < 2; mi++)
        #pragma unroll
        for (int ni = 0; ni < 4; ni++) {
            int r = row0 + wm + mi * 16 + (lane >> 2);
            int c = wn3 + ni * 8 + (lane & 3) * 2;
            float v0 = lrelu(acc4[mi][ni][0]), v1 = lrelu(acc4[mi][ni][1]);
            float v2 = lrelu(acc4[mi][ni][2]), v3 = lrelu(acc4[mi][ni][3]);
            if (r < M) *(float2*)(OUT + (size_t)r * 128 + c) = make_float2(v0, v1);
            if (r + 8 < M) *(float2*)(OUT + (size_t)(r + 8) * 128 + c) = make_float2(v2, v3);
        }
}

// ---------------- CSR SpMM: warp per row, rows [w0, w1) ---------------------
template <bool FINAL>
__global__ void __launch_bounds__(256) csr_spmm_kernel(const float* __restrict__ x,
                                                       float* __restrict__ out,
                                                       int w0, int w1, int Nn) {
    int w = w0 + ((blockIdx.x * blockDim.x + threadIdx.x) >> 5);
    int lane = threadIdx.x & 31;
    if (w >= w1) return;
    int s = g_off[w], e = g_off[w + 1];
    float4 acc = make_float4(0.f, 0.f, 0.f, 0.f);
    for (int base = s; base < e; base += 32) {
        int idx = base + lane;
        int c = 0;
        float v = 0.f;
        if (idx < e) {
            c = g_ecol[idx];
            v = g_eval[idx];
        }
        int n = min(32, e - base);
        for (int j = 0; j < n; j++) {
            int cj = __shfl_sync(0xffffffffu, c, j);
            float vj = __shfl_sync(0xffffffffu, v, j);
            float4 g = *(const float4*)(x + (size_t)cj * 128 + lane * 4);
            acc.x += vj * g.x;
            acc.y += vj * g.y;
            acc.z += vj * g.z;
            acc.w += vj * g.w;
        }
    }
    if (FINAL) {
        acc.x = lrelu(acc.x); acc.y = lrelu(acc.y);
        acc.z = lrelu(acc.z); acc.w = lrelu(acc.w);
        if (lane < 16)
            *(float4*)(out + (size_t)w * 64 + lane * 4) = acc;
        else
            *(float4*)(out + (size_t)Nn * 64 + (size_t)w * 64 + (lane - 16) * 4) = acc;
    } else {
        *(float4*)(out + (size_t)w * 128 + lane * 4) = acc;
    }
}

// ---------------------------------------------------------------------------
extern "C" void kernel_launch(void* const* d_in, const int* in_sizes, int n_in,
                              void* d_out, int out_size) {
    const float* ns_emb = (const float*)d_in[0];
    const int* erow = (const int*)d_in[1];
    const int* ecol = (const int*)d_in[2];
    const float* eval_ = (const float*)d_in[3];
    const float* cond = (const float*)d_in[4];
    const float* Wh = (const float*)d_in[5];
    const float* Wmu = (const float*)d_in[6];
    const float* Wvar = (const float*)d_in[7];
    const float* Wq = (const float*)d_in[8];
    const float* Wk = (const float*)d_in[9];
    const float* Wv = (const float*)d_in[10];
    const float* Wo = (const float*)d_in[11];

    int N = in_sizes[0] / 256;
    int E = in_sizes[1];

    float *supp1, *acc1, *supp2;
    cudaGetSymbolAddress((void**)&supp1, g_supp1);
    cudaGetSymbolAddress((void**)&acc1, g_acc1);
    cudaGetSymbolAddress((void**)&supp2, g_supp2);

    cudaFuncSetAttribute(attn_fused_kernel,
                         cudaFuncAttributeMaxDynamicSharedMemorySize, SMEM_FUSED);

    int gm = (N + 127) / 128;
    int gm64 = (N + 63) / 64;       // total 64-row tiles
    int nchunks = (N + 255) / 256;

    // ---- streams + events -------------------------------------------------
    cudaStream_t s2, s3;
    cudaStreamCreate(&s2);
    cudaStreamCreate(&s3);
    cudaEvent_t e1, e2, ef;
    cudaEvent_t ev[4];
    cudaEventCreateWithFlags(&e1, cudaEventDisableTiming);
    cudaEventCreateWithFlags(&e2, cudaEventDisableTiming);
    cudaEventCreateWithFlags(&ef, cudaEventDisableTiming);
    for (int i = 0; i < 4; i++) cudaEventCreateWithFlags(&ev[i], cudaEventDisableTiming);

    cudaEventRecord(e1, 0);
    cudaStreamWaitEvent(s2, e1, 0);

    // side stream: prep + CSR build (g_cnt is zero on entry; scanA re-zeros)
    hist_kernel<<<1024, 256, 0, s2>>>(erow, E);
    prep_kernel<<<128, 256, 0, s2>>>(cond, Wk, Wv, Wmu, Wvar);
    fold_kernel<<<256, 256, 0, s2>>>(Wq, Wo);
    scanA_kernel<<<nchunks, 256, 0, s2>>>(N);
    scanB_kernel<<<1, 256, 0, s2>>>(nchunks);
    scanC_kernel<<<256, 256, 0, s2>>>(N, E);
    scatter_kernel<<<1024, 256, 0, s2>>>(erow, ecol, eval_, E);
    cudaEventRecord(e2, s2);

    // main stream: gemm1 (Wh split inline)
    gemm1_kernel<<<gm, 512>>>(ns_emb, Wh, supp1, N);

    // join: spmm needs CSR + supp1
    cudaStreamWaitEvent(0, e2, 0);

    // ---- pipelined spmm1 (stream 0) + fused (stream s3), 4 chunks ---------
    // chunk boundaries in 64-row tiles
    int tchunk = (gm64 + 3) / 4;
    for (int i = 0; i < 4; i++) {
        int t0 = i * tchunk;
        int t1 = (i + 1) * tchunk;
        if (t0 >= gm64) { cudaEventRecord(ev[i], 0); continue; }
        if (t1 > gm64) t1 = gm64;
        int r0 = t0 * 64;
        int r1 = t1 * 64;
        if (r1 > N) r1 = N;
        int nb = ((r1 - r0) * 32 + 255) / 256;
        csr_spmm_kernel<false><<<nb, 256>>>(supp1, acc1, r0, r1, N);
        cudaEventRecord(ev[i], 0);
        cudaStreamWaitEvent(s3, ev[i], 0);
        attn_fused_kernel<<<t1 - t0, 256, SMEM_FUSED, s3>>>(acc1, supp2, N, t0);
    }
    cudaEventRecord(ef, s3);
    cudaStreamWaitEvent(0, ef, 0);

    // out = leaky(spmm(supp2)) split into mu|var   (needs full supp2)
    {
        int nb = (N * 32 + 255) / 256;
        csr_spmm_kernel<true><<<nb, 256>>>(supp2, (float*)d_out, 0, N, N);
    }

    cudaEventDestroy(e1);
    cudaEventDestroy(e2);
    cudaEventDestroy(ef);
    for (int i = 0; i < 4; i++) cudaEventDestroy(ev[i]);
    cudaStreamDestroy(s2);
    cudaStreamDestroy(s3);
}

// round 11
// speedup vs baseline: 1.1146x; 1.1146x over previous
#include <cuda_runtime.h>
#include <cuda_bf16.h>
#include <math.h>

#define NMAX 50000
#define EMAX 600000

// ---------------- scratch (device globals; no allocation allowed) ----------
__device__ __align__(16) float g_supp1[NMAX * 128];
__device__ __align__(16) float g_acc1 [NMAX * 128];
__device__ __align__(16) float g_supp2[NMAX * 128];
__device__ __align__(16) float g_Kb   [128 * 64];
__device__ __align__(16) float g_Vb   [128 * 64];
// CSR build (g_cnt starts zeroed at module load; scanA re-zeros it each call)
__device__ int   g_cnt [NMAX];
__device__ int   g_off [NMAX + 1];
__device__ int   g_cur [NMAX];
__device__ int   g_bsum[256];
__device__ int   g_boff[256];
__device__ __align__(16) int   g_ecol[EMAX];
__device__ __align__(16) float g_eval[EMAX];
// pre-split bf16 weights (hi/lo)
__device__ __align__(16) __nv_bfloat16 g_Mh [128 * 256], g_Ml [128 * 256];
__device__ __align__(16) __nv_bfloat16 g_Ph [256 * 128], g_Pl [256 * 128];
__device__ __align__(16) __nv_bfloat16 g_Wch[128 * 128], g_Wcl[128 * 128];

__device__ __forceinline__ float lrelu(float x) { return x > 0.f ? x : 0.01f * x; }

__device__ __forceinline__ void split_bf16(float x, __nv_bfloat16& h, __nv_bfloat16& l) {
    h = __float2bfloat16(x);
    l = __float2bfloat16(x - __bfloat162float(h));
}

__device__ __forceinline__ void mma_bf16(float* d, const unsigned* a, const unsigned* b) {
    asm volatile(
        "mma.sync.aligned.m16n8k16.row.col.f32.bf16.bf16.f32 "
        "{%0,%1,%2,%3}, {%4,%5,%6,%7}, {%8,%9}, {%0,%1,%2,%3};\n"
        : "+f"(d[0]), "+f"(d[1]), "+f"(d[2]), "+f"(d[3])
        : "r"(a[0]), "r"(a[1]), "r"(a[2]), "r"(a[3]), "r"(b[0]), "r"(b[1]));
}

__device__ __forceinline__ void ldsm_x4(unsigned* r, const __nv_bfloat16* p) {
    unsigned addr = (unsigned)__cvta_generic_to_shared(p);
    asm volatile("ldmatrix.sync.aligned.m8n8.x4.shared.b16 {%0,%1,%2,%3}, [%4];\n"
                 : "=r"(r[0]), "=r"(r[1]), "=r"(r[2]), "=r"(r[3]) : "r"(addr));
}

__device__ __forceinline__ void ldsm_x2t(unsigned* r, const __nv_bfloat16* p) {
    unsigned addr = (unsigned)__cvta_generic_to_shared(p);
    asm volatile("ldmatrix.sync.aligned.m8n8.x2.trans.shared.b16 {%0,%1}, [%2];\n"
                 : "=r"(r[0]), "=r"(r[1]) : "r"(addr));
}

// ---------------- prep: K/V projections + Wcat pack (one kernel) ------------
__global__ void prep_kernel(const float* __restrict__ cond,
                            const float* __restrict__ Wk,
                            const float* __restrict__ Wv,
                            const float* __restrict__ Wmu,
                            const float* __restrict__ Wvar) {
    int o = blockIdx.x * blockDim.x + threadIdx.x;  // 32768 threads
    if (o < 8192) {
        int key = o >> 6, d = o & 63;
        float s = 0.f;
        #pragma unroll 4
        for (int m = 0; m < 128; m++) s += cond[key * 128 + m] * Wk[m * 64 + d];
        g_Kb[o] = s;
    } else if (o < 16384) {
        int o2 = o - 8192;
        int key = o2 >> 6, d = o2 & 63;
        float s = 0.f;
        #pragma unroll 4
        for (int m = 0; m < 128; m++) s += cond[key * 128 + m] * Wv[m * 64 + d];
        g_Vb[o2] = s;
    } else {
        int i = o - 16384;  // 0..16383 = 128*128
        int k = i >> 7, n = i & 127;
        float w = (n < 64) ? Wmu[k * 64 + n] : Wvar[k * 64 + (n - 64)];
        split_bf16(w, g_Wch[i], g_Wcl[i]);
    }
}

// ---------------- fold heads -> split bf16 Mcat, Pcat -----------------------
__global__ void fold_kernel(const float* __restrict__ Wq,
                            const float* __restrict__ Wo) {
    const float scale = 0.17677669529663687f;  // 1/sqrt(32)
    int o = blockIdx.x * blockDim.x + threadIdx.x;  // 65536
    if (o < 32768) {
        int c = o >> 8, hk = o & 255;
        int h = hk >> 7, key = hk & 127;
        float s = 0.f;
        #pragma unroll 8
        for (int d = 0; d < 32; d++)
            s += Wq[c * 64 + h * 32 + d] * g_Kb[key * 64 + h * 32 + d];
        split_bf16(s * scale, g_Mh[o], g_Ml[o]);
    } else {
        int o2 = o - 32768;
        int hk = o2 >> 7, j = o2 & 127;
        int h = hk >> 7, key = hk & 127;
        float s = 0.f;
        #pragma unroll 8
        for (int d = 0; d < 32; d++)
            s += g_Vb[key * 64 + h * 32 + d] * Wo[(h * 32 + d) * 128 + j];
        split_bf16(s, g_Ph[o2], g_Pl[o2]);
    }
}

// ---------------- CSR build -------------------------------------------------
__global__ void hist_kernel(const int* __restrict__ rows, int E) {
    int idx = blockIdx.x * blockDim.x + threadIdx.x;
    int stride = gridDim.x * blockDim.x;
    for (int i = idx; i < E; i += stride) atomicAdd(&g_cnt[rows[i]], 1);
}

__global__ void scanA_kernel(int Nn) {
    __shared__ int s[256];
    int t = threadIdx.x, i = blockIdx.x * 256 + t;
    int v = (i < Nn) ? g_cnt[i] : 0;
    s[t] = v;
    __syncthreads();
    #pragma unroll
    for (int o = 1; o < 256; o <<= 1) {
        int x = (t >= o) ? s[t - o] : 0;
        __syncthreads();
        s[t] += x;
        __syncthreads();
    }
    if (i < Nn) {
        g_off[i] = s[t] - v;
        g_cnt[i] = 0;  // re-zero for next call (invariant across graph replays)
    }
    if (t == 255) g_bsum[blockIdx.x] = s[255];
}

__global__ void scanB_kernel(int nb) {
    __shared__ int s[256];
    int t = threadIdx.x;
    int v = (t < nb) ? g_bsum[t] : 0;
    s[t] = v;
    __syncthreads();
    #pragma unroll
    for (int o = 1; o < 256; o <<= 1) {
        int x = (t >= o) ? s[t - o] : 0;
        __syncthreads();
        s[t] += x;
        __syncthreads();
    }
    g_boff[t] = s[t] - v;
}

__global__ void scanC_kernel(int Nn, int E) {
    int idx = blockIdx.x * blockDim.x + threadIdx.x;
    int stride = gridDim.x * blockDim.x;
    for (int i = idx; i < Nn; i += stride) {
        int o = g_off[i] + g_boff[i >> 8];
        g_off[i] = o;
        g_cur[i] = o;
    }
    if (idx == 0) g_off[Nn] = E;
}

__global__ void scatter_kernel(const int* __restrict__ rows,
                               const int* __restrict__ cols,
                               const float* __restrict__ vals, int E) {
    int idx = blockIdx.x * blockDim.x + threadIdx.x;
    int stride = gridDim.x * blockDim.x;
    for (int i = idx; i < E; i += stride) {
        int r = rows[i];
        int p = atomicAdd(&g_cur[r], 1);
        g_ecol[p] = cols[i];
        g_eval[p] = vals[i];
    }
}

// ============================================================================
// GEMM1: supp1 = leaky(ns_emb[M,256] @ Wh[256,128])
// ============================================================================
__global__ void __launch_bounds__(512) gemm1_kernel(const float* __restrict__ A,
                                                    const float* __restrict__ Wg,
                                                    float* __restrict__ C, int M) {
    constexpr int K = 256, NC = 128, LDA = 40, LDB = 136;
    __shared__ __nv_bfloat16 Ah[128][LDA], Al[128][LDA];
    __shared__ __nv_bfloat16 Bh[32][LDB], Bl[32][LDB];
    int tid = threadIdx.x;
    int warp = tid >> 5, lane = tid & 31;
    int wm = (warp & 3) * 32;
    int wn = (warp >> 2) * 32;
    int row0 = blockIdx.x * 128;
    int r_l = lane & 15, c_l = (lane >> 4) << 3;

    float acc[2][4][4];
    #pragma unroll
    for (int mi = 0; mi < 2; mi++)
        #pragma unroll
        for (int ni = 0; ni < 4; ni++)
            #pragma unroll
            for (int t = 0; t < 4; t++) acc[mi][ni][t] = 0.f;

    float4 pa[2], pb[2];

    auto loadA = [&](int k0) {
        #pragma unroll
        for (int i = 0; i < 2; i++) {
            int v = tid + i * 512;
            int row = v >> 3, q = (v & 7) << 2;
            int gr = row0 + row;
            pa[i] = make_float4(0.f, 0.f, 0.f, 0.f);
            if (gr < M) pa[i] = *(const float4*)(A + (size_t)gr * K + k0 + q);
        }
    };
    auto loadB = [&](int k0) {
        #pragma unroll
        for (int i = 0; i < 2; i++) {
            int v = tid + i * 512;
            int br = v >> 5, bc = (v & 31) << 2;
            pb[i] = *(const float4*)(Wg + (size_t)(k0 + br) * NC + bc);
        }
    };

    loadA(0);
    loadB(0);
    for (int it = 0; it < K / 32; it++) {
        #pragma unroll
        for (int i = 0; i < 2; i++) {
            int v = tid + i * 512;
            int row = v >> 3, q = (v & 7) << 2;
            split_bf16(pa[i].x, Ah[row][q + 0], Al[row][q + 0]);
            split_bf16(pa[i].y, Ah[row][q + 1], Al[row][q + 1]);
            split_bf16(pa[i].z, Ah[row][q + 2], Al[row][q + 2]);
            split_bf16(pa[i].w, Ah[row][q + 3], Al[row][q + 3]);
        }
        #pragma unroll
        for (int i = 0; i < 2; i++) {
            int v = tid + i * 512;
            int br = v >> 5, bc = (v & 31) << 2;
            split_bf16(pb[i].x, Bh[br][bc + 0], Bl[br][bc + 0]);
            split_bf16(pb[i].y, Bh[br][bc + 1], Bl[br][bc + 1]);
            split_bf16(pb[i].z, Bh[br][bc + 2], Bl[br][bc + 2]);
            split_bf16(pb[i].w, Bh[br][bc + 3], Bl[br][bc + 3]);
        }
        __syncthreads();
        if (it < K / 32 - 1) {
            loadA((it + 1) * 32);
            loadB((it + 1) * 32);
        }
        #pragma unroll
        for (int s = 0; s < 2; s++) {
            int ks = s * 16;
            unsigned afh[2][4], afl[2][4];
            #pragma unroll
            for (int mi = 0; mi < 2; mi++) {
                ldsm_x4(afh[mi], &Ah[wm + mi * 16 + r_l][ks + c_l]);
                ldsm_x4(afl[mi], &Al[wm + mi * 16 + r_l][ks + c_l]);
            }
            #pragma unroll
            for (int ni = 0; ni < 4; ni++) {
                unsigned bfh[2], bfl[2];
                ldsm_x2t(bfh, &Bh[ks + r_l][wn + ni * 8]);
                ldsm_x2t(bfl, &Bl[ks + r_l][wn + ni * 8]);
                #pragma unroll
                for (int mi = 0; mi < 2; mi++) {
                    mma_bf16(acc[mi][ni], afh[mi], bfh);
                    mma_bf16(acc[mi][ni], afh[mi], bfl);
                    mma_bf16(acc[mi][ni], afl[mi], bfh);
                }
            }
        }
        __syncthreads();
    }
    #pragma unroll
    for (int mi = 0; mi < 2; mi++)
        #pragma unroll
        for (int ni = 0; ni < 4; ni++) {
            int r = row0 + wm + mi * 16 + (lane >> 2);
            int c = wn + ni * 8 + (lane & 3) * 2;
            float v0 = lrelu(acc[mi][ni][0]), v1 = lrelu(acc[mi][ni][1]);
            float v2 = lrelu(acc[mi][ni][2]), v3 = lrelu(acc[mi][ni][3]);
            if (r < M) *(float2*)(C + (size_t)r * NC + c) = make_float2(v0, v1);
            if (r + 8 < M) *(float2*)(C + (size_t)(r + 8) * NC + c) = make_float2(v2, v3);
        }
}

// ============================================================================
// FUSED: supp2 = leaky( softmax( leaky(acc1)@Mcat ) @ Pcat @ Wcat )
// 64-row tiles, 2 CTAs/SM. Register prefetch on GEMM3/GEMM4 B tiles.
// ============================================================================
#define SMEM_FUSED 103424

__global__ void __launch_bounds__(256, 2) attn_fused_kernel(const float* __restrict__ ACC1,
                                                            float* __restrict__ OUT, int M) {
    extern __shared__ char smem_raw[];
    __nv_bfloat16* Sh = (__nv_bfloat16*)smem_raw;               // [64][264]
    __nv_bfloat16* Sl = Sh + 64 * 264;
    __nv_bfloat16* Bh = (__nv_bfloat16*)(smem_raw + 67584);     // [32][264]
    __nv_bfloat16* Bl = Bh + 32 * 264;
    float* smax = (float*)(smem_raw + 101376);                  // [64][4]
    float* ssum = smax + 256;
    __nv_bfloat16* Xh = Sh;                                     // overlay [64][136]
    __nv_bfloat16* Xl = Sh + 64 * 136;

    int tid = threadIdx.x;
    int warp = tid >> 5, lane = tid & 31;
    int wm = (warp >> 2) * 32;
    int wc = warp & 3;
    int row0 = blockIdx.x * 64;
    int r_l = lane & 15, c_l = (lane >> 4) << 3;

    // ---------- load X = leaky(acc1 tile), split bf16 ----------
    #pragma unroll
    for (int i = 0; i < 8; i++) {
        int v = tid + i * 256;
        int row = v >> 5, q = (v & 31) << 2;
        int gr = row0 + row;
        float4 a4 = make_float4(0.f, 0.f, 0.f, 0.f);
        if (gr < M) a4 = *(const float4*)(ACC1 + (size_t)gr * 128 + q);
        a4.x = lrelu(a4.x); a4.y = lrelu(a4.y);
        a4.z = lrelu(a4.z); a4.w = lrelu(a4.w);
        split_bf16(a4.x, Xh[row * 136 + q + 0], Xl[row * 136 + q + 0]);
        split_bf16(a4.y, Xh[row * 136 + q + 1], Xl[row * 136 + q + 1]);
        split_bf16(a4.z, Xh[row * 136 + q + 2], Xl[row * 136 + q + 2]);
        split_bf16(a4.w, Xh[row * 136 + q + 3], Xl[row * 136 + q + 3]);
    }
    __syncthreads();

    // GEMM2: L = X @ Mcat   (64x256, K=128)  [no prefetch: accA live = 64 regs]
    int wn2 = wc * 64;
    float accA[2][8][4];
    #pragma unroll
    for (int mi = 0; mi < 2; mi++)
        #pragma unroll
        for (int ni = 0; ni < 8; ni++)
            #pragma unroll
            for (int t = 0; t < 4; t++) accA[mi][ni][t] = 0.f;

    for (int it = 0; it < 4; it++) {
        int k0 = it * 32;
        #pragma unroll
        for (int i = 0; i < 4; i++) {
            int s = tid + i * 256;
            int br = s >> 5, bc = (s & 31) << 3;
            *(uint4*)&Bh[br * 264 + bc] = *(const uint4*)(g_Mh + (size_t)(k0 + br) * 256 + bc);
            *(uint4*)&Bl[br * 264 + bc] = *(const uint4*)(g_Ml + (size_t)(k0 + br) * 256 + bc);
        }
        __syncthreads();
        #pragma unroll
        for (int s = 0; s < 2; s++) {
            int ks = k0 + s * 16;
            unsigned afh[2][4], afl[2][4];
            #pragma unroll
            for (int mi = 0; mi < 2; mi++) {
                ldsm_x4(afh[mi], &Xh[(wm + mi * 16 + r_l) * 136 + ks + c_l]);
                ldsm_x4(afl[mi], &Xl[(wm + mi * 16 + r_l) * 136 + ks + c_l]);
            }
            #pragma unroll
            for (int ni = 0; ni < 8; ni++) {
                unsigned bfh[2], bfl[2];
                ldsm_x2t(bfh, &Bh[(s * 16 + r_l) * 264 + wn2 + ni * 8]);
                ldsm_x2t(bfl, &Bl[(s * 16 + r_l) * 264 + wn2 + ni * 8]);
                #pragma unroll
                for (int mi = 0; mi < 2; mi++) {
                    mma_bf16(accA[mi][ni], afh[mi], bfh);
                    mma_bf16(accA[mi][ni], afh[mi], bfl);
                    mma_bf16(accA[mi][ni], afl[mi], bfh);
                }
            }
        }
        __syncthreads();
    }

    // softmax
    int hbase = (wc >> 1) << 1;
    #pragma unroll
    for (int mi = 0; mi < 2; mi++)
        #pragma unroll
        for (int half = 0; half < 2; half++) {
            float m = -1e30f;
            #pragma unroll
            for (int ni = 0; ni < 8; ni++)
                m = fmaxf(m, fmaxf(accA[mi][ni][2 * half], accA[mi][ni][2 * half + 1]));
            m = fmaxf(m, __shfl_xor_sync(0xffffffffu, m, 1));
            m = fmaxf(m, __shfl_xor_sync(0xffffffffu, m, 2));
            if ((lane & 3) == 0) {
                int rowg = wm + mi * 16 + (lane >> 2) + 8 * half;
                smax[rowg * 4 + wc] = m;
            }
        }
    __syncthreads();
    #pragma unroll
    for (int mi = 0; mi < 2; mi++)
        #pragma unroll
        for (int half = 0; half < 2; half++) {
            int rowg = wm + mi * 16 + (lane >> 2) + 8 * half;
            float mh = fmaxf(smax[rowg * 4 + hbase], smax[rowg * 4 + hbase + 1]);
            float s = 0.f;
            #pragma unroll
            for (int ni = 0; ni < 8; ni++) {
                float e0 = __expf(accA[mi][ni][2 * half] - mh);
                float e1 = __expf(accA[mi][ni][2 * half + 1] - mh);
                accA[mi][ni][2 * half] = e0;
                accA[mi][ni][2 * half + 1] = e1;
                s += e0 + e1;
            }
            s += __shfl_xor_sync(0xffffffffu, s, 1);
            s += __shfl_xor_sync(0xffffffffu, s, 2);
            if ((lane & 3) == 0) ssum[rowg * 4 + wc] = s;
        }
    __syncthreads();
    #pragma unroll
    for (int mi = 0; mi < 2; mi++)
        #pragma unroll
        for (int half = 0; half < 2; half++) {
            int rowg = wm + mi * 16 + (lane >> 2) + 8 * half;
            float inv = 1.f / (ssum[rowg * 4 + hbase] + ssum[rowg * 4 + hbase + 1]);
            #pragma unroll
            for (int ni = 0; ni < 8; ni++) {
                float w0 = accA[mi][ni][2 * half] * inv;
                float w1 = accA[mi][ni][2 * half + 1] * inv;
                int colg = wn2 + ni * 8 + 2 * (lane & 3);
                __nv_bfloat16 h0, l0, h1, l1;
                split_bf16(w0, h0, l0);
                split_bf16(w1, h1, l1);
                *(__nv_bfloat162*)&Sh[rowg * 264 + colg] = __nv_bfloat162(h0, h1);
                *(__nv_bfloat162*)&Sl[rowg * 264 + colg] = __nv_bfloat162(l0, l1);
            }
        }
    __syncthreads();

    // GEMM3: h = S @ Pcat   (64x128, K=256)  [register prefetch on B]
    int wn3 = wc * 32;
    int brw = tid >> 4, bcw = (tid & 15) << 3;  // B-load coords (2 rounds)
    float acc3[2][4][4];
    #pragma unroll
    for (int mi = 0; mi < 2; mi++)
        #pragma unroll
        for (int ni = 0; ni < 4; ni++)
            #pragma unroll
            for (int t = 0; t < 4; t++) acc3[mi][ni][t] = 0.f;

    uint4 pph[2], ppl[2];
    auto loadP = [&](int k0) {
        #pragma unroll
        for (int i = 0; i < 2; i++) {
            int br = brw + i * 16;
            pph[i] = *(const uint4*)(g_Ph + (size_t)(k0 + br) * 128 + bcw);
            ppl[i] = *(const uint4*)(g_Pl + (size_t)(k0 + br) * 128 + bcw);
        }
    };

    loadP(0);
    for (int it = 0; it < 8; it++) {
        #pragma unroll
        for (int i = 0; i < 2; i++) {
            int br = brw + i * 16;
            *(uint4*)&Bh[br * 264 + bcw] = pph[i];
            *(uint4*)&Bl[br * 264 + bcw] = ppl[i];
        }
        __syncthreads();
        if (it < 7) loadP((it + 1) * 32);
        #pragma unroll
        for (int s = 0; s < 2; s++) {
            int ks = it * 32 + s * 16;
            unsigned afh[2][4], afl[2][4];
            #pragma unroll
            for (int mi = 0; mi < 2; mi++) {
                ldsm_x4(afh[mi], &Sh[(wm + mi * 16 + r_l) * 264 + ks + c_l]);
                ldsm_x4(afl[mi], &Sl[(wm + mi * 16 + r_l) * 264 + ks + c_l]);
            }
            #pragma unroll
            for (int ni = 0; ni < 4; ni++) {
                unsigned bfh[2], bfl[2];
                ldsm_x2t(bfh, &Bh[(s * 16 + r_l) * 264 + wn3 + ni * 8]);
                ldsm_x2t(bfl, &Bl[(s * 16 + r_l) * 264 + wn3 + ni * 8]);
                #pragma unroll
                for (int mi = 0; mi < 2; mi++) {
                    mma_bf16(acc3[mi][ni], afh[mi], bfh);
                    mma_bf16(acc3[mi][ni], afh[mi], bfl);
                    mma_bf16(acc3[mi][ni], afl[mi], bfh);
                }
            }
        }
        __syncthreads();
    }

    // store h (split bf16) into X overlay (S dead)
    #pragma unroll
    for (int mi = 0; mi < 2; mi++)
        #pragma unroll
        for (int half = 0; half < 2; half++) {
            int rowg = wm + mi * 16 + (lane >> 2) + 8 * half;
            #pragma unroll
            for (int ni = 0; ni < 4; ni++) {
                float v0 = acc3[mi][ni][2 * half];
                float v1 = acc3[mi][ni][2 * half + 1];
                int colg = wn3 + ni * 8 + 2 * (lane & 3);
                __nv_bfloat16 h0, l0, h1, l1;
                split_bf16(v0, h0, l0);
                split_bf16(v1, h1, l1);
                *(__nv_bfloat162*)&Xh[rowg * 136 + colg] = __nv_bfloat162(h0, h1);
                *(__nv_bfloat162*)&Xl[rowg * 136 + colg] = __nv_bfloat162(l0, l1);
            }
        }
    __syncthreads();

    // GEMM4: supp2 = leaky(h @ Wcat)   (64x128, K=128)  [register prefetch]
    float acc4[2][4][4];
    #pragma unroll
    for (int mi = 0; mi < 2; mi++)
        #pragma unroll
        for (int ni = 0; ni < 4; ni++)
            #pragma unroll
            for (int t = 0; t < 4; t++) acc4[mi][ni][t] = 0.f;

    auto loadW = [&](int k0) {
        #pragma unroll
        for (int i = 0; i < 2; i++) {
            int br = brw + i * 16;
            pph[i] = *(const uint4*)(g_Wch + (size_t)(k0 + br) * 128 + bcw);
            ppl[i] = *(const uint4*)(g_Wcl + (size_t)(k0 + br) * 128 + bcw);
        }
    };

    loadW(0);
    for (int it = 0; it < 4; it++) {
        #pragma unroll
        for (int i = 0; i < 2; i++) {
            int br = brw + i * 16;
            *(uint4*)&Bh[br * 264 + bcw] = pph[i];
            *(uint4*)&Bl[br * 264 + bcw] = ppl[i];
        }
        __syncthreads();
        if (it < 3) loadW((it + 1) * 32);
        #pragma unroll
        for (int s = 0; s < 2; s++) {
            int ks = it * 32 + s * 16;
            unsigned afh[2][4], afl[2][4];
            #pragma unroll
            for (int mi = 0; mi < 2; mi++) {
                ldsm_x4(afh[mi], &Xh[(wm + mi * 16 + r_l) * 136 + ks + c_l]);
                ldsm_x4(afl[mi], &Xl[(wm + mi * 16 + r_l) * 136 + ks + c_l]);
            }
            #pragma unroll
            for (int ni = 0; ni < 4; ni++) {
                unsigned bfh[2], bfl[2];
                ldsm_x2t(bfh, &Bh[(s * 16 + r_l) * 264 + wn3 + ni * 8]);
                ldsm_x2t(bfl, &Bl[(s * 16 + r_l) * 264 + wn3 + ni * 8]);
                #pragma unroll
                for (int mi = 0; mi < 2; mi++) {
                    mma_bf16(acc4[mi][ni], afh[mi], bfh);
                    mma_bf16(acc4[mi][ni], afh[mi], bfl);
                    mma_bf16(acc4[mi][ni], afl[mi], bfh);
                }
            }
        }
        __syncthreads();
    }

    #pragma unroll
    for (int mi = 0; mi < 2; mi++)
        #pragma unroll
        for (int ni = 0; ni < 4; ni++) {
            int r = row0 + wm + mi * 16 + (lane >> 2);
            int c = wn3 + ni * 8 + (lane & 3) * 2;
            float v0 = lrelu(acc4[mi][ni][0]), v1 = lrelu(acc4[mi][ni][1]);
            float v2 = lrelu(acc4[mi][ni][2]), v3 = lrelu(acc4[mi][ni][3]);
            if (r < M) *(float2*)(OUT + (size_t)r * 128 + c) = make_float2(v0, v1);
            if (r + 8 < M) *(float2*)(OUT + (size_t)(r + 8) * 128 + c) = make_float2(v2, v3);
        }
}

// ---------------- CSR SpMM: warp per row, no atomics ------------------------
template <bool FINAL>
__global__ void __launch_bounds__(256) csr_spmm_kernel(const float* __restrict__ x,
                                                       float* __restrict__ out, int Nn) {
    int w = (blockIdx.x * blockDim.x + threadIdx.x) >> 5;
    int lane = threadIdx.x & 31;
    if (w >= Nn) return;
    int s = g_off[w], e = g_off[w + 1];
    float4 acc = make_float4(0.f, 0.f, 0.f, 0.f);
    for (int base = s; base < e; base += 32) {
        int idx = base + lane;
        int c = 0;
        float v = 0.f;
        if (idx < e) {
            c = g_ecol[idx];
            v = g_eval[idx];
        }
        int n = min(32, e - base);
        for (int j = 0; j < n; j++) {
            int cj = __shfl_sync(0xffffffffu, c, j);
            float vj = __shfl_sync(0xffffffffu, v, j);
            float4 g = *(const float4*)(x + (size_t)cj * 128 + lane * 4);
            acc.x += vj * g.x;
            acc.y += vj * g.y;
            acc.z += vj * g.z;
            acc.w += vj * g.w;
        }
    }
    if (FINAL) {
        acc.x = lrelu(acc.x); acc.y = lrelu(acc.y);
        acc.z = lrelu(acc.z); acc.w = lrelu(acc.w);
        if (lane < 16)
            *(float4*)(out + (size_t)w * 64 + lane * 4) = acc;
        else
            *(float4*)(out + (size_t)Nn * 64 + (size_t)w * 64 + (lane - 16) * 4) = acc;
    } else {
        *(float4*)(out + (size_t)w * 128 + lane * 4) = acc;
    }
}

// ---------------------------------------------------------------------------
extern "C" void kernel_launch(void* const* d_in, const int* in_sizes, int n_in,
                              void* d_out, int out_size) {
    const float* ns_emb = (const float*)d_in[0];
    const int* erow = (const int*)d_in[1];
    const int* ecol = (const int*)d_in[2];
    const float* eval_ = (const float*)d_in[3];
    const float* cond = (const float*)d_in[4];
    const float* Wh = (const float*)d_in[5];
    const float* Wmu = (const float*)d_in[6];
    const float* Wvar = (const float*)d_in[7];
    const float* Wq = (const float*)d_in[8];
    const float* Wk = (const float*)d_in[9];
    const float* Wv = (const float*)d_in[10];
    const float* Wo = (const float*)d_in[11];

    int N = in_sizes[0] / 256;
    int E = in_sizes[1];

    float *supp1, *acc1, *supp2;
    cudaGetSymbolAddress((void**)&supp1, g_supp1);
    cudaGetSymbolAddress((void**)&acc1, g_acc1);
    cudaGetSymbolAddress((void**)&supp2, g_supp2);

    cudaFuncSetAttribute(attn_fused_kernel,
                         cudaFuncAttributeMaxDynamicSharedMemorySize, SMEM_FUSED);

    int gm = (N + 127) / 128;
    int gm64 = (N + 63) / 64;
    int nchunks = (N + 255) / 256;
    int spmm_blocks = (N * 32 + 255) / 256;

    // ---- fork a side stream (prep + CSR build) overlapping gemm1 ----------
    cudaStream_t s2;
    cudaStreamCreate(&s2);
    cudaEvent_t e1, e2;
    cudaEventCreateWithFlags(&e1, cudaEventDisableTiming);
    cudaEventCreateWithFlags(&e2, cudaEventDisableTiming);

    cudaEventRecord(e1, 0);
    cudaStreamWaitEvent(s2, e1, 0);

    // side stream: prep + CSR build (g_cnt is zero on entry; scanA re-zeros)
    hist_kernel<<<1024, 256, 0, s2>>>(erow, E);
    prep_kernel<<<128, 256, 0, s2>>>(cond, Wk, Wv, Wmu, Wvar);
    fold_kernel<<<256, 256, 0, s2>>>(Wq, Wo);
    scanA_kernel<<<nchunks, 256, 0, s2>>>(N);
    scanB_kernel<<<1, 256, 0, s2>>>(nchunks);
    scanC_kernel<<<256, 256, 0, s2>>>(N, E);
    scatter_kernel<<<1024, 256, 0, s2>>>(erow, ecol, eval_, E);
    cudaEventRecord(e2, s2);

    // main stream: gemm1 (Wh split inline)
    gemm1_kernel<<<gm, 512>>>(ns_emb, Wh, supp1, N);

    // join: spmm needs CSR + supp1
    cudaStreamWaitEvent(0, e2, 0);

    // acc1 = spmm(supp1)  -- standalone, high occupancy
    csr_spmm_kernel<false><<<spmm_blocks, 256>>>(supp1, acc1, N);
    // supp2 = leaky( softmax(leaky(acc1)@Mcat) @ Pcat @ Wcat )  -- 64-row tiles
    attn_fused_kernel<<<gm64, 256, SMEM_FUSED>>>(acc1, supp2, N);
    // out = leaky(spmm(supp2)) split into mu|var
    csr_spmm_kernel<true><<<spmm_blocks, 256>>>(supp2, (float*)d_out, N);

    cudaEventDestroy(e1);
    cudaEventDestroy(e2);
    cudaStreamDestroy(s2);
}

// round 12
// speedup vs baseline: 1.1801x; 1.0587x over previous
#include <cuda_runtime.h>
#include <cuda_bf16.h>
#include <cuda_fp16.h>
#include <math.h>

#define NMAX 50000
#define EMAX 600000

// ---------------- scratch (device globals; no allocation allowed) ----------
__device__ __align__(16) __half g_supp1[NMAX * 128];   // fp16: halves gather BW
__device__ __align__(16) float  g_acc1 [NMAX * 128];
__device__ __align__(16) __half g_supp2[NMAX * 128];   // fp16
__device__ __align__(16) float  g_Kb   [128 * 64];
__device__ __align__(16) float  g_Vb   [128 * 64];
// CSR build (g_cnt starts zeroed at module load; scanA re-zeros it each call)
__device__ int   g_cnt [NMAX];
__device__ int   g_off [NMAX + 1];
__device__ int   g_cur [NMAX];
__device__ int   g_bsum[256];
__device__ int   g_boff[256];
__device__ __align__(16) int   g_ecol[EMAX];
__device__ __align__(16) float g_eval[EMAX];
// pre-split bf16 weights (hi/lo)
__device__ __align__(16) __nv_bfloat16 g_Mh [128 * 256], g_Ml [128 * 256];
__device__ __align__(16) __nv_bfloat16 g_Ph [256 * 128], g_Pl [256 * 128];
__device__ __align__(16) __nv_bfloat16 g_Wch[128 * 128], g_Wcl[128 * 128];

__device__ __forceinline__ float lrelu(float x) { return x > 0.f ? x : 0.01f * x; }

__device__ __forceinline__ void split_bf16(float x, __nv_bfloat16& h, __nv_bfloat16& l) {
    h = __float2bfloat16(x);
    l = __float2bfloat16(x - __bfloat162float(h));
}

__device__ __forceinline__ void mma_bf16(float* d, const unsigned* a, const unsigned* b) {
    asm volatile(
        "mma.sync.aligned.m16n8k16.row.col.f32.bf16.bf16.f32 "
        "{%0,%1,%2,%3}, {%4,%5,%6,%7}, {%8,%9}, {%0,%1,%2,%3};\n"
        : "+f"(d[0]), "+f"(d[1]), "+f"(d[2]), "+f"(d[3])
        : "r"(a[0]), "r"(a[1]), "r"(a[2]), "r"(a[3]), "r"(b[0]), "r"(b[1]));
}

__device__ __forceinline__ void ldsm_x4(unsigned* r, const __nv_bfloat16* p) {
    unsigned addr = (unsigned)__cvta_generic_to_shared(p);
    asm volatile("ldmatrix.sync.aligned.m8n8.x4.shared.b16 {%0,%1,%2,%3}, [%4];\n"
                 : "=r"(r[0]), "=r"(r[1]), "=r"(r[2]), "=r"(r[3]) : "r"(addr));
}

__device__ __forceinline__ void ldsm_x2t(unsigned* r, const __nv_bfloat16* p) {
    unsigned addr = (unsigned)__cvta_generic_to_shared(p);
    asm volatile("ldmatrix.sync.aligned.m8n8.x2.trans.shared.b16 {%0,%1}, [%2];\n"
                 : "=r"(r[0]), "=r"(r[1]) : "r"(addr));
}

// ---------------- prep: K/V projections + Wcat pack (one kernel) ------------
__global__ void prep_kernel(const float* __restrict__ cond,
                            const float* __restrict__ Wk,
                            const float* __restrict__ Wv,
                            const float* __restrict__ Wmu,
                            const float* __restrict__ Wvar) {
    int o = blockIdx.x * blockDim.x + threadIdx.x;  // 32768 threads
    if (o < 8192) {
        int key = o >> 6, d = o & 63;
        float s = 0.f;
        #pragma unroll 4
        for (int m = 0; m < 128; m++) s += cond[key * 128 + m] * Wk[m * 64 + d];
        g_Kb[o] = s;
    } else if (o < 16384) {
        int o2 = o - 8192;
        int key = o2 >> 6, d = o2 & 63;
        float s = 0.f;
        #pragma unroll 4
        for (int m = 0; m < 128; m++) s += cond[key * 128 + m] * Wv[m * 64 + d];
        g_Vb[o2] = s;
    } else {
        int i = o - 16384;  // 0..16383 = 128*128
        int k = i >> 7, n = i & 127;
        float w = (n < 64) ? Wmu[k * 64 + n] : Wvar[k * 64 + (n - 64)];
        split_bf16(w, g_Wch[i], g_Wcl[i]);
    }
}

// ---------------- fold heads -> split bf16 Mcat, Pcat -----------------------
__global__ void fold_kernel(const float* __restrict__ Wq,
                            const float* __restrict__ Wo) {
    const float scale = 0.17677669529663687f;  // 1/sqrt(32)
    int o = blockIdx.x * blockDim.x + threadIdx.x;  // 65536
    if (o < 32768) {
        int c = o >> 8, hk = o & 255;
        int h = hk >> 7, key = hk & 127;
        float s = 0.f;
        #pragma unroll 8
        for (int d = 0; d < 32; d++)
            s += Wq[c * 64 + h * 32 + d] * g_Kb[key * 64 + h * 32 + d];
        split_bf16(s * scale, g_Mh[o], g_Ml[o]);
    } else {
        int o2 = o - 32768;
        int hk = o2 >> 7, j = o2 & 127;
        int h = hk >> 7, key = hk & 127;
        float s = 0.f;
        #pragma unroll 8
        for (int d = 0; d < 32; d++)
            s += g_Vb[key * 64 + h * 32 + d] * Wo[(h * 32 + d) * 128 + j];
        split_bf16(s, g_Ph[o2], g_Pl[o2]);
    }
}

// ---------------- CSR build -------------------------------------------------
__global__ void hist_kernel(const int* __restrict__ rows, int E) {
    int idx = blockIdx.x * blockDim.x + threadIdx.x;
    int stride = gridDim.x * blockDim.x;
    for (int i = idx; i < E; i += stride) atomicAdd(&g_cnt[rows[i]], 1);
}

__global__ void scanA_kernel(int Nn) {
    __shared__ int s[256];
    int t = threadIdx.x, i = blockIdx.x * 256 + t;
    int v = (i < Nn) ? g_cnt[i] : 0;
    s[t] = v;
    __syncthreads();
    #pragma unroll
    for (int o = 1; o < 256; o <<= 1) {
        int x = (t >= o) ? s[t - o] : 0;
        __syncthreads();
        s[t] += x;
        __syncthreads();
    }
    if (i < Nn) {
        g_off[i] = s[t] - v;
        g_cnt[i] = 0;  // re-zero for next call (invariant across graph replays)
    }
    if (t == 255) g_bsum[blockIdx.x] = s[255];
}

__global__ void scanB_kernel(int nb) {
    __shared__ int s[256];
    int t = threadIdx.x;
    int v = (t < nb) ? g_bsum[t] : 0;
    s[t] = v;
    __syncthreads();
    #pragma unroll
    for (int o = 1; o < 256; o <<= 1) {
        int x = (t >= o) ? s[t - o] : 0;
        __syncthreads();
        s[t] += x;
        __syncthreads();
    }
    g_boff[t] = s[t] - v;
}

__global__ void scanC_kernel(int Nn, int E) {
    int idx = blockIdx.x * blockDim.x + threadIdx.x;
    int stride = gridDim.x * blockDim.x;
    for (int i = idx; i < Nn; i += stride) {
        int o = g_off[i] + g_boff[i >> 8];
        g_off[i] = o;
        g_cur[i] = o;
    }
    if (idx == 0) g_off[Nn] = E;
}

__global__ void scatter_kernel(const int* __restrict__ rows,
                               const int* __restrict__ cols,
                               const float* __restrict__ vals, int E) {
    int idx = blockIdx.x * blockDim.x + threadIdx.x;
    int stride = gridDim.x * blockDim.x;
    for (int i = idx; i < E; i += stride) {
        int r = rows[i];
        int p = atomicAdd(&g_cur[r], 1);
        g_ecol[p] = cols[i];
        g_eval[p] = vals[i];
    }
}

// ============================================================================
// GEMM1: supp1 = leaky(ns_emb[M,256] @ Wh[256,128]) -> fp16 output
// ============================================================================
__global__ void __launch_bounds__(512) gemm1_kernel(const float* __restrict__ A,
                                                    const float* __restrict__ Wg,
                                                    __half* __restrict__ C, int M) {
    constexpr int K = 256, NC = 128, LDA = 40, LDB = 136;
    __shared__ __nv_bfloat16 Ah[128][LDA], Al[128][LDA];
    __shared__ __nv_bfloat16 Bh[32][LDB], Bl[32][LDB];
    int tid = threadIdx.x;
    int warp = tid >> 5, lane = tid & 31;
    int wm = (warp & 3) * 32;
    int wn = (warp >> 2) * 32;
    int row0 = blockIdx.x * 128;
    int r_l = lane & 15, c_l = (lane >> 4) << 3;

    float acc[2][4][4];
    #pragma unroll
    for (int mi = 0; mi < 2; mi++)
        #pragma unroll
        for (int ni = 0; ni < 4; ni++)
            #pragma unroll
            for (int t = 0; t < 4; t++) acc[mi][ni][t] = 0.f;

    float4 pa[2], pb[2];

    auto loadA = [&](int k0) {
        #pragma unroll
        for (int i = 0; i < 2; i++) {
            int v = tid + i * 512;
            int row = v >> 3, q = (v & 7) << 2;
            int gr = row0 + row;
            pa[i] = make_float4(0.f, 0.f, 0.f, 0.f);
            if (gr < M) pa[i] = *(const float4*)(A + (size_t)gr * K + k0 + q);
        }
    };
    auto loadB = [&](int k0) {
        #pragma unroll
        for (int i = 0; i < 2; i++) {
            int v = tid + i * 512;
            int br = v >> 5, bc = (v & 31) << 2;
            pb[i] = *(const float4*)(Wg + (size_t)(k0 + br) * NC + bc);
        }
    };

    loadA(0);
    loadB(0);
    for (int it = 0; it < K / 32; it++) {
        #pragma unroll
        for (int i = 0; i < 2; i++) {
            int v = tid + i * 512;
            int row = v >> 3, q = (v & 7) << 2;
            split_bf16(pa[i].x, Ah[row][q + 0], Al[row][q + 0]);
            split_bf16(pa[i].y, Ah[row][q + 1], Al[row][q + 1]);
            split_bf16(pa[i].z, Ah[row][q + 2], Al[row][q + 2]);
            split_bf16(pa[i].w, Ah[row][q + 3], Al[row][q + 3]);
        }
        #pragma unroll
        for (int i = 0; i < 2; i++) {
            int v = tid + i * 512;
            int br = v >> 5, bc = (v & 31) << 2;
            split_bf16(pb[i].x, Bh[br][bc + 0], Bl[br][bc + 0]);
            split_bf16(pb[i].y, Bh[br][bc + 1], Bl[br][bc + 1]);
            split_bf16(pb[i].z, Bh[br][bc + 2], Bl[br][bc + 2]);
            split_bf16(pb[i].w, Bh[br][bc + 3], Bl[br][bc + 3]);
        }
        __syncthreads();
        if (it < K / 32 - 1) {
            loadA((it + 1) * 32);
            loadB((it + 1) * 32);
        }
        #pragma unroll
        for (int s = 0; s < 2; s++) {
            int ks = s * 16;
            unsigned afh[2][4], afl[2][4];
            #pragma unroll
            for (int mi = 0; mi < 2; mi++) {
                ldsm_x4(afh[mi], &Ah[wm + mi * 16 + r_l][ks + c_l]);
                ldsm_x4(afl[mi], &Al[wm + mi * 16 + r_l][ks + c_l]);
            }
            #pragma unroll
            for (int ni = 0; ni < 4; ni++) {
                unsigned bfh[2], bfl[2];
                ldsm_x2t(bfh, &Bh[ks + r_l][wn + ni * 8]);
                ldsm_x2t(bfl, &Bl[ks + r_l][wn + ni * 8]);
                #pragma unroll
                for (int mi = 0; mi < 2; mi++) {
                    mma_bf16(acc[mi][ni], afh[mi], bfh);
                    mma_bf16(acc[mi][ni], afh[mi], bfl);
                    mma_bf16(acc[mi][ni], afl[mi], bfh);
                }
            }
        }
        __syncthreads();
    }
    #pragma unroll
    for (int mi = 0; mi < 2; mi++)
        #pragma unroll
        for (int ni = 0; ni < 4; ni++) {
            int r = row0 + wm + mi * 16 + (lane >> 2);
            int c = wn + ni * 8 + (lane & 3) * 2;
            float v0 = lrelu(acc[mi][ni][0]), v1 = lrelu(acc[mi][ni][1]);
            float v2 = lrelu(acc[mi][ni][2]), v3 = lrelu(acc[mi][ni][3]);
            if (r < M)
                *(__half2*)(C + (size_t)r * NC + c) = __floats2half2_rn(v0, v1);
            if (r + 8 < M)
                *(__half2*)(C + (size_t)(r + 8) * NC + c) = __floats2half2_rn(v2, v3);
        }
}

// ============================================================================
// FUSED: supp2 = leaky( softmax( leaky(acc1)@Mcat ) @ Pcat @ Wcat ) -> fp16
// 64-row tiles, 2 CTAs/SM. Register prefetch on GEMM3/GEMM4 B tiles.
// ============================================================================
#define SMEM_FUSED 103424

__global__ void __launch_bounds__(256, 2) attn_fused_kernel(const float* __restrict__ ACC1,
                                                            __half* __restrict__ OUT, int M) {
    extern __shared__ char smem_raw[];
    __nv_bfloat16* Sh = (__nv_bfloat16*)smem_raw;               // [64][264]
    __nv_bfloat16* Sl = Sh + 64 * 264;
    __nv_bfloat16* Bh = (__nv_bfloat16*)(smem_raw + 67584);     // [32][264]
    __nv_bfloat16* Bl = Bh + 32 * 264;
    float* smax = (float*)(smem_raw + 101376);                  // [64][4]
    float* ssum = smax + 256;
    __nv_bfloat16* Xh = Sh;                                     // overlay [64][136]
    __nv_bfloat16* Xl = Sh + 64 * 136;

    int tid = threadIdx.x;
    int warp = tid >> 5, lane = tid & 31;
    int wm = (warp >> 2) * 32;
    int wc = warp & 3;
    int row0 = blockIdx.x * 64;
    int r_l = lane & 15, c_l = (lane >> 4) << 3;

    // ---------- load X = leaky(acc1 tile), split bf16 ----------
    #pragma unroll
    for (int i = 0; i < 8; i++) {
        int v = tid + i * 256;
        int row = v >> 5, q = (v & 31) << 2;
        int gr = row0 + row;
        float4 a4 = make_float4(0.f, 0.f, 0.f, 0.f);
        if (gr < M) a4 = *(const float4*)(ACC1 + (size_t)gr * 128 + q);
        a4.x = lrelu(a4.x); a4.y = lrelu(a4.y);
        a4.z = lrelu(a4.z); a4.w = lrelu(a4.w);
        split_bf16(a4.x, Xh[row * 136 + q + 0], Xl[row * 136 + q + 0]);
        split_bf16(a4.y, Xh[row * 136 + q + 1], Xl[row * 136 + q + 1]);
        split_bf16(a4.z, Xh[row * 136 + q + 2], Xl[row * 136 + q + 2]);
        split_bf16(a4.w, Xh[row * 136 + q + 3], Xl[row * 136 + q + 3]);
    }
    __syncthreads();

    // GEMM2: L = X @ Mcat   (64x256, K=128)
    int wn2 = wc * 64;
    float accA[2][8][4];
    #pragma unroll
    for (int mi = 0; mi < 2; mi++)
        #pragma unroll
        for (int ni = 0; ni < 8; ni++)
            #pragma unroll
            for (int t = 0; t < 4; t++) accA[mi][ni][t] = 0.f;

    for (int it = 0; it < 4; it++) {
        int k0 = it * 32;
        #pragma unroll
        for (int i = 0; i < 4; i++) {
            int s = tid + i * 256;
            int br = s >> 5, bc = (s & 31) << 3;
            *(uint4*)&Bh[br * 264 + bc] = *(const uint4*)(g_Mh + (size_t)(k0 + br) * 256 + bc);
            *(uint4*)&Bl[br * 264 + bc] = *(const uint4*)(g_Ml + (size_t)(k0 + br) * 256 + bc);
        }
        __syncthreads();
        #pragma unroll
        for (int s = 0; s < 2; s++) {
            int ks = k0 + s * 16;
            unsigned afh[2][4], afl[2][4];
            #pragma unroll
            for (int mi = 0; mi < 2; mi++) {
                ldsm_x4(afh[mi], &Xh[(wm + mi * 16 + r_l) * 136 + ks + c_l]);
                ldsm_x4(afl[mi], &Xl[(wm + mi * 16 + r_l) * 136 + ks + c_l]);
            }
            #pragma unroll
            for (int ni = 0; ni < 8; ni++) {
                unsigned bfh[2], bfl[2];
                ldsm_x2t(bfh, &Bh[(s * 16 + r_l) * 264 + wn2 + ni * 8]);
                ldsm_x2t(bfl, &Bl[(s * 16 + r_l) * 264 + wn2 + ni * 8]);
                #pragma unroll
                for (int mi = 0; mi < 2; mi++) {
                    mma_bf16(accA[mi][ni], afh[mi], bfh);
                    mma_bf16(accA[mi][ni], afh[mi], bfl);
                    mma_bf16(accA[mi][ni], afl[mi], bfh);
                }
            }
        }
        __syncthreads();
    }

    // softmax
    int hbase = (wc >> 1) << 1;
    #pragma unroll
    for (int mi = 0; mi < 2; mi++)
        #pragma unroll
        for (int half = 0; half < 2; half++) {
            float m = -1e30f;
            #pragma unroll
            for (int ni = 0; ni < 8; ni++)
                m = fmaxf(m, fmaxf(accA[mi][ni][2 * half], accA[mi][ni][2 * half + 1]));
            m = fmaxf(m, __shfl_xor_sync(0xffffffffu, m, 1));
            m = fmaxf(m, __shfl_xor_sync(0xffffffffu, m, 2));
            if ((lane & 3) == 0) {
                int rowg = wm + mi * 16 + (lane >> 2) + 8 * half;
                smax[rowg * 4 + wc] = m;
            }
        }
    __syncthreads();
    #pragma unroll
    for (int mi = 0; mi < 2; mi++)
        #pragma unroll
        for (int half = 0; half < 2; half++) {
            int rowg = wm + mi * 16 + (lane >> 2) + 8 * half;
            float mh = fmaxf(smax[rowg * 4 + hbase], smax[rowg * 4 + hbase + 1]);
            float s = 0.f;
            #pragma unroll
            for (int ni = 0; ni < 8; ni++) {
                float e0 = __expf(accA[mi][ni][2 * half] - mh);
                float e1 = __expf(accA[mi][ni][2 * half + 1] - mh);
                accA[mi][ni][2 * half] = e0;
                accA[mi][ni][2 * half + 1] = e1;
                s += e0 + e1;
            }
            s += __shfl_xor_sync(0xffffffffu, s, 1);
            s += __shfl_xor_sync(0xffffffffu, s, 2);
            if ((lane & 3) == 0) ssum[rowg * 4 + wc] = s;
        }
    __syncthreads();
    #pragma unroll
    for (int mi = 0; mi < 2; mi++)
        #pragma unroll
        for (int half = 0; half < 2; half++) {
            int rowg = wm + mi * 16 + (lane >> 2) + 8 * half;
            float inv = 1.f / (ssum[rowg * 4 + hbase] + ssum[rowg * 4 + hbase + 1]);
            #pragma unroll
            for (int ni = 0; ni < 8; ni++) {
                float w0 = accA[mi][ni][2 * half] * inv;
                float w1 = accA[mi][ni][2 * half + 1] * inv;
                int colg = wn2 + ni * 8 + 2 * (lane & 3);
                __nv_bfloat16 h0, l0, h1, l1;
                split_bf16(w0, h0, l0);
                split_bf16(w1, h1, l1);
                *(__nv_bfloat162*)&Sh[rowg * 264 + colg] = __nv_bfloat162(h0, h1);
                *(__nv_bfloat162*)&Sl[rowg * 264 + colg] = __nv_bfloat162(l0, l1);
            }
        }
    __syncthreads();

    // GEMM3: h = S @ Pcat   (64x128, K=256)  [register prefetch on B]
    int wn3 = wc * 32;
    int brw = tid >> 4, bcw = (tid & 15) << 3;
    float acc3[2][4][4];
    #pragma unroll
    for (int mi = 0; mi < 2; mi++)
        #pragma unroll
        for (int ni = 0; ni < 4; ni++)
            #pragma unroll
            for (int t = 0; t < 4; t++) acc3[mi][ni][t] = 0.f;

    uint4 pph[2], ppl[2];
    auto loadP = [&](int k0) {
        #pragma unroll
        for (int i = 0; i < 2; i++) {
            int br = brw + i * 16;
            pph[i] = *(const uint4*)(g_Ph + (size_t)(k0 + br) * 128 + bcw);
            ppl[i] = *(const uint4*)(g_Pl + (size_t)(k0 + br) * 128 + bcw);
        }
    };

    loadP(0);
    for (int it = 0; it < 8; it++) {
        #pragma unroll
        for (int i = 0; i < 2; i++) {
            int br = brw + i * 16;
            *(uint4*)&Bh[br * 264 + bcw] = pph[i];
            *(uint4*)&Bl[br * 264 + bcw] = ppl[i];
        }
        __syncthreads();
        if (it < 7) loadP((it + 1) * 32);
        #pragma unroll
        for (int s = 0; s < 2; s++) {
            int ks = it * 32 + s * 16;
            unsigned afh[2][4], afl[2][4];
            #pragma unroll
            for (int mi = 0; mi < 2; mi++) {
                ldsm_x4(afh[mi], &Sh[(wm + mi * 16 + r_l) * 264 + ks + c_l]);
                ldsm_x4(afl[mi], &Sl[(wm + mi * 16 + r_l) * 264 + ks + c_l]);
            }
            #pragma unroll
            for (int ni = 0; ni < 4; ni++) {
                unsigned bfh[2], bfl[2];
                ldsm_x2t(bfh, &Bh[(s * 16 + r_l) * 264 + wn3 + ni * 8]);
                ldsm_x2t(bfl, &Bl[(s * 16 + r_l) * 264 + wn3 + ni * 8]);
                #pragma unroll
                for (int mi = 0; mi < 2; mi++) {
                    mma_bf16(acc3[mi][ni], afh[mi], bfh);
                    mma_bf16(acc3[mi][ni], afh[mi], bfl);
                    mma_bf16(acc3[mi][ni], afl[mi], bfh);
                }
            }
        }
        __syncthreads();
    }

    // store h (split bf16) into X overlay (S dead)
    #pragma unroll
    for (int mi = 0; mi < 2; mi++)
        #pragma unroll
        for (int half = 0; half < 2; half++) {
            int rowg = wm + mi * 16 + (lane >> 2) + 8 * half;
            #pragma unroll
            for (int ni = 0; ni < 4; ni++) {
                float v0 = acc3[mi][ni][2 * half];
                float v1 = acc3[mi][ni][2 * half + 1];
                int colg = wn3 + ni * 8 + 2 * (lane & 3);
                __nv_bfloat16 h0, l0, h1, l1;
                split_bf16(v0, h0, l0);
                split_bf16(v1, h1, l1);
                *(__nv_bfloat162*)&Xh[rowg * 136 + colg] = __nv_bfloat162(h0, h1);
                *(__nv_bfloat162*)&Xl[rowg * 136 + colg] = __nv_bfloat162(l0, l1);
            }
        }
    __syncthreads();

    // GEMM4: supp2 = leaky(h @ Wcat)   (64x128, K=128)  [register prefetch]
    float acc4[2][4][4];
    #pragma unroll
    for (int mi = 0; mi < 2; mi++)
        #pragma unroll
        for (int ni = 0; ni < 4; ni++)
            #pragma unroll
            for (int t = 0; t < 4; t++) acc4[mi][ni][t] = 0.f;

    auto loadW = [&](int k0) {
        #pragma unroll
        for (int i = 0; i < 2; i++) {
            int br = brw + i * 16;
            pph[i] = *(const uint4*)(g_Wch + (size_t)(k0 + br) * 128 + bcw);
            ppl[i] = *(const uint4*)(g_Wcl + (size_t)(k0 + br) * 128 + bcw);
        }
    };

    loadW(0);
    for (int it = 0; it < 4; it++) {
        #pragma unroll
        for (int i = 0; i < 2; i++) {
            int br = brw + i * 16;
            *(uint4*)&Bh[br * 264 + bcw] = pph[i];
            *(uint4*)&Bl[br * 264 + bcw] = ppl[i];
        }
        __syncthreads();
        if (it < 3) loadW((it + 1) * 32);
        #pragma unroll
        for (int s = 0; s < 2; s++) {
            int ks = it * 32 + s * 16;
            unsigned afh[2][4], afl[2][4];
            #pragma unroll
            for (int mi = 0; mi < 2; mi++) {
                ldsm_x4(afh[mi], &Xh[(wm + mi * 16 + r_l) * 136 + ks + c_l]);
                ldsm_x4(afl[mi], &Xl[(wm + mi * 16 + r_l) * 136 + ks + c_l]);
            }
            #pragma unroll
            for (int ni = 0; ni < 4; ni++) {
                unsigned bfh[2], bfl[2];
                ldsm_x2t(bfh, &Bh[(s * 16 + r_l) * 264 + wn3 + ni * 8]);
                ldsm_x2t(bfl, &Bl[(s * 16 + r_l) * 264 + wn3 + ni * 8]);
                #pragma unroll
                for (int mi = 0; mi < 2; mi++) {
                    mma_bf16(acc4[mi][ni], afh[mi], bfh);
                    mma_bf16(acc4[mi][ni], afh[mi], bfl);
                    mma_bf16(acc4[mi][ni], afl[mi], bfh);
                }
            }
        }
        __syncthreads();
    }

    #pragma unroll
    for (int mi = 0; mi < 2; mi++)
        #pragma unroll
        for (int ni = 0; ni < 4; ni++) {
            int r = row0 + wm + mi * 16 + (lane >> 2);
            int c = wn3 + ni * 8 + (lane & 3) * 2;
            float v0 = lrelu(acc4[mi][ni][0]), v1 = lrelu(acc4[mi][ni][1]);
            float v2 = lrelu(acc4[mi][ni][2]), v3 = lrelu(acc4[mi][ni][3]);
            if (r < M)
                *(__half2*)(OUT + (size_t)r * 128 + c) = __floats2half2_rn(v0, v1);
            if (r + 8 < M)
                *(__half2*)(OUT + (size_t)(r + 8) * 128 + c) = __floats2half2_rn(v2, v3);
        }
}

// ---------------- CSR SpMM: warp per row, fp16 gather, fp32 accum ----------
template <bool FINAL>
__global__ void __launch_bounds__(256) csr_spmm_kernel(const __half* __restrict__ x,
                                                       float* __restrict__ out, int Nn) {
    int w = (blockIdx.x * blockDim.x + threadIdx.x) >> 5;
    int lane = threadIdx.x & 31;
    if (w >= Nn) return;
    int s = g_off[w], e = g_off[w + 1];
    float4 acc = make_float4(0.f, 0.f, 0.f, 0.f);
    for (int base = s; base < e; base += 32) {
        int idx = base + lane;
        int c = 0;
        float v = 0.f;
        if (idx < e) {
            c = g_ecol[idx];
            v = g_eval[idx];
        }
        int n = min(32, e - base);
        for (int j = 0; j < n; j++) {
            int cj = __shfl_sync(0xffffffffu, c, j);
            float vj = __shfl_sync(0xffffffffu, v, j);
            uint2 raw = *(const uint2*)(x + (size_t)cj * 128 + lane * 4);
            float2 f0 = __half22float2(*(__half2*)&raw.x);
            float2 f1 = __half22float2(*(__half2*)&raw.y);
            acc.x += vj * f0.x;
            acc.y += vj * f0.y;
            acc.z += vj * f1.x;
            acc.w += vj * f1.y;
        }
    }
    if (FINAL) {
        acc.x = lrelu(acc.x); acc.y = lrelu(acc.y);
        acc.z = lrelu(acc.z); acc.w = lrelu(acc.w);
        if (lane < 16)
            *(float4*)(out + (size_t)w * 64 + lane * 4) = acc;
        else
            *(float4*)(out + (size_t)Nn * 64 + (size_t)w * 64 + (lane - 16) * 4) = acc;
    } else {
        *(float4*)(out + (size_t)w * 128 + lane * 4) = acc;
    }
}

// ---------------------------------------------------------------------------
extern "C" void kernel_launch(void* const* d_in, const int* in_sizes, int n_in,
                              void* d_out, int out_size) {
    const float* ns_emb = (const float*)d_in[0];
    const int* erow = (const int*)d_in[1];
    const int* ecol = (const int*)d_in[2];
    const float* eval_ = (const float*)d_in[3];
    const float* cond = (const float*)d_in[4];
    const float* Wh = (const float*)d_in[5];
    const float* Wmu = (const float*)d_in[6];
    const float* Wvar = (const float*)d_in[7];
    const float* Wq = (const float*)d_in[8];
    const float* Wk = (const float*)d_in[9];
    const float* Wv = (const float*)d_in[10];
    const float* Wo = (const float*)d_in[11];

    int N = in_sizes[0] / 256;
    int E = in_sizes[1];

    __half *supp1, *supp2;
    float *acc1;
    cudaGetSymbolAddress((void**)&supp1, g_supp1);
    cudaGetSymbolAddress((void**)&acc1, g_acc1);
    cudaGetSymbolAddress((void**)&supp2, g_supp2);

    cudaFuncSetAttribute(attn_fused_kernel,
                         cudaFuncAttributeMaxDynamicSharedMemorySize, SMEM_FUSED);

    int gm = (N + 127) / 128;
    int gm64 = (N + 63) / 64;
    int nchunks = (N + 255) / 256;
    int spmm_blocks = (N * 32 + 255) / 256;

    // ---- fork a side stream (prep + CSR build) overlapping gemm1 ----------
    cudaStream_t s2;
    cudaStreamCreate(&s2);
    cudaEvent_t e1, e2;
    cudaEventCreateWithFlags(&e1, cudaEventDisableTiming);
    cudaEventCreateWithFlags(&e2, cudaEventDisableTiming);

    cudaEventRecord(e1, 0);
    cudaStreamWaitEvent(s2, e1, 0);

    // side stream: prep + CSR build (g_cnt is zero on entry; scanA re-zeros)
    hist_kernel<<<1024, 256, 0, s2>>>(erow, E);
    prep_kernel<<<128, 256, 0, s2>>>(cond, Wk, Wv, Wmu, Wvar);
    fold_kernel<<<256, 256, 0, s2>>>(Wq, Wo);
    scanA_kernel<<<nchunks, 256, 0, s2>>>(N);
    scanB_kernel<<<1, 256, 0, s2>>>(nchunks);
    scanC_kernel<<<256, 256, 0, s2>>>(N, E);
    scatter_kernel<<<1024, 256, 0, s2>>>(erow, ecol, eval_, E);
    cudaEventRecord(e2, s2);

    // main stream: gemm1 (Wh split inline) -> fp16 supp1
    gemm1_kernel<<<gm, 512>>>(ns_emb, Wh, supp1, N);

    // join: spmm needs CSR + supp1
    cudaStreamWaitEvent(0, e2, 0);

    // acc1 = spmm(supp1)  -- fp16 gather, fp32 out
    csr_spmm_kernel<false><<<spmm_blocks, 256>>>(supp1, acc1, N);
    // supp2 = leaky( softmax(leaky(acc1)@Mcat) @ Pcat @ Wcat ) -> fp16
    attn_fused_kernel<<<gm64, 256, SMEM_FUSED>>>(acc1, supp2, N);
    // out = leaky(spmm(supp2)) split into mu|var  (fp32 output)
    csr_spmm_kernel<true><<<spmm_blocks, 256>>>(supp2, (float*)d_out, N);

    cudaEventDestroy(e1);
    cudaEventDestroy(e2);
    cudaStreamDestroy(s2);
}

// round 13
// speedup vs baseline: 1.2504x; 1.0596x over previous
#include <cuda_runtime.h>
#include <cuda_bf16.h>
#include <cuda_fp16.h>
#include <math.h>

#define NMAX 50000
#define EMAX 600000

// ---------------- scratch (device globals; no allocation allowed) ----------
__device__ __align__(16) __half g_supp1[NMAX * 128];   // fp16: halves gather BW
__device__ __align__(16) float  g_acc1 [NMAX * 128];
__device__ __align__(16) __half g_supp2[NMAX * 128];   // fp16
__device__ __align__(16) float  g_Kb   [128 * 64];
__device__ __align__(16) float  g_Vb   [128 * 64];
__device__ __align__(16) float  g_Pc   [256 * 128];    // Pcat fp32 (pre-PW)
__device__ __align__(16) float  g_Wc   [128 * 128];    // Wcat fp32 (pre-PW)
// CSR build (g_cnt starts zeroed at module load; scanA re-zeros it each call)
__device__ int   g_cnt [NMAX];
__device__ int   g_off [NMAX + 1];
__device__ int   g_cur [NMAX];
__device__ int   g_bsum[256];
__device__ int   g_boff[256];
__device__ __align__(16) int   g_ecol[EMAX];
__device__ __align__(16) float g_eval[EMAX];
// pre-split bf16 weights (hi/lo)
__device__ __align__(16) __nv_bfloat16 g_Mh [128 * 256], g_Ml [128 * 256];
__device__ __align__(16) __nv_bfloat16 g_PWh[256 * 128], g_PWl[256 * 128];  // Pcat@Wcat

__device__ __forceinline__ float lrelu(float x) { return x > 0.f ? x : 0.01f * x; }

__device__ __forceinline__ void split_bf16(float x, __nv_bfloat16& h, __nv_bfloat16& l) {
    h = __float2bfloat16(x);
    l = __float2bfloat16(x - __bfloat162float(h));
}

__device__ __forceinline__ void mma_bf16(float* d, const unsigned* a, const unsigned* b) {
    asm volatile(
        "mma.sync.aligned.m16n8k16.row.col.f32.bf16.bf16.f32 "
        "{%0,%1,%2,%3}, {%4,%5,%6,%7}, {%8,%9}, {%0,%1,%2,%3};\n"
        : "+f"(d[0]), "+f"(d[1]), "+f"(d[2]), "+f"(d[3])
        : "r"(a[0]), "r"(a[1]), "r"(a[2]), "r"(a[3]), "r"(b[0]), "r"(b[1]));
}

__device__ __forceinline__ void ldsm_x4(unsigned* r, const __nv_bfloat16* p) {
    unsigned addr = (unsigned)__cvta_generic_to_shared(p);
    asm volatile("ldmatrix.sync.aligned.m8n8.x4.shared.b16 {%0,%1,%2,%3}, [%4];\n"
                 : "=r"(r[0]), "=r"(r[1]), "=r"(r[2]), "=r"(r[3]) : "r"(addr));
}

__device__ __forceinline__ void ldsm_x2t(unsigned* r, const __nv_bfloat16* p) {
    unsigned addr = (unsigned)__cvta_generic_to_shared(p);
    asm volatile("ldmatrix.sync.aligned.m8n8.x2.trans.shared.b16 {%0,%1}, [%2];\n"
                 : "=r"(r[0]), "=r"(r[1]) : "r"(addr));
}

// ---------------- prep: K/V projections + Wcat (fp32) -----------------------
__global__ void prep_kernel(const float* __restrict__ cond,
                            const float* __restrict__ Wk,
                            const float* __restrict__ Wv,
                            const float* __restrict__ Wmu,
                            const float* __restrict__ Wvar) {
    int o = blockIdx.x * blockDim.x + threadIdx.x;  // 32768 threads
    if (o < 8192) {
        int key = o >> 6, d = o & 63;
        float s = 0.f;
        #pragma unroll 4
        for (int m = 0; m < 128; m++) s += cond[key * 128 + m] * Wk[m * 64 + d];
        g_Kb[o] = s;
    } else if (o < 16384) {
        int o2 = o - 8192;
        int key = o2 >> 6, d = o2 & 63;
        float s = 0.f;
        #pragma unroll 4
        for (int m = 0; m < 128; m++) s += cond[key * 128 + m] * Wv[m * 64 + d];
        g_Vb[o2] = s;
    } else {
        int i = o - 16384;  // 0..16383 = 128*128
        int k = i >> 7, n = i & 127;
        g_Wc[i] = (n < 64) ? Wmu[k * 64 + n] : Wvar[k * 64 + (n - 64)];
    }
}

// ---------------- fold heads: Mcat (split), Pcat (fp32) ---------------------
__global__ void fold_kernel(const float* __restrict__ Wq,
                            const float* __restrict__ Wo) {
    const float scale = 0.17677669529663687f;  // 1/sqrt(32)
    int o = blockIdx.x * blockDim.x + threadIdx.x;  // 65536
    if (o < 32768) {
        int c = o >> 8, hk = o & 255;
        int h = hk >> 7, key = hk & 127;
        float s = 0.f;
        #pragma unroll 8
        for (int d = 0; d < 32; d++)
            s += Wq[c * 64 + h * 32 + d] * g_Kb[key * 64 + h * 32 + d];
        split_bf16(s * scale, g_Mh[o], g_Ml[o]);
    } else {
        int o2 = o - 32768;
        int hk = o2 >> 7, j = o2 & 127;
        int h = hk >> 7, key = hk & 127;
        float s = 0.f;
        #pragma unroll 8
        for (int d = 0; d < 32; d++)
            s += g_Vb[key * 64 + h * 32 + d] * Wo[(h * 32 + d) * 128 + j];
        g_Pc[o2] = s;
    }
}

// ---------------- PW = Pcat @ Wcat  [256,128], split bf16 -------------------
__global__ void pw_kernel() {
    int idx = blockIdx.x * blockDim.x + threadIdx.x;  // 32768
    int i = idx >> 7, j = idx & 127;
    float s = 0.f;
    #pragma unroll 8
    for (int m = 0; m < 128; m++) s += g_Pc[i * 128 + m] * g_Wc[m * 128 + j];
    split_bf16(s, g_PWh[idx], g_PWl[idx]);
}

// ---------------- CSR build -------------------------------------------------
__global__ void hist_kernel(const int* __restrict__ rows, int E) {
    int idx = blockIdx.x * blockDim.x + threadIdx.x;
    int stride = gridDim.x * blockDim.x;
    for (int i = idx; i < E; i += stride) atomicAdd(&g_cnt[rows[i]], 1);
}

__global__ void scanA_kernel(int Nn) {
    __shared__ int s[256];
    int t = threadIdx.x, i = blockIdx.x * 256 + t;
    int v = (i < Nn) ? g_cnt[i] : 0;
    s[t] = v;
    __syncthreads();
    #pragma unroll
    for (int o = 1; o < 256; o <<= 1) {
        int x = (t >= o) ? s[t - o] : 0;
        __syncthreads();
        s[t] += x;
        __syncthreads();
    }
    if (i < Nn) {
        g_off[i] = s[t] - v;
        g_cnt[i] = 0;  // re-zero for next call (invariant across graph replays)
    }
    if (t == 255) g_bsum[blockIdx.x] = s[255];
}

__global__ void scanB_kernel(int nb) {
    __shared__ int s[256];
    int t = threadIdx.x;
    int v = (t < nb) ? g_bsum[t] : 0;
    s[t] = v;
    __syncthreads();
    #pragma unroll
    for (int o = 1; o < 256; o <<= 1) {
        int x = (t >= o) ? s[t - o] : 0;
        __syncthreads();
        s[t] += x;
        __syncthreads();
    }
    g_boff[t] = s[t] - v;
}

__global__ void scanC_kernel(int Nn, int E) {
    int idx = blockIdx.x * blockDim.x + threadIdx.x;
    int stride = gridDim.x * blockDim.x;
    for (int i = idx; i < Nn; i += stride) {
        int o = g_off[i] + g_boff[i >> 8];
        g_off[i] = o;
        g_cur[i] = o;
    }
    if (idx == 0) g_off[Nn] = E;
}

__global__ void scatter_kernel(const int* __restrict__ rows,
                               const int* __restrict__ cols,
                               const float* __restrict__ vals, int E) {
    int idx = blockIdx.x * blockDim.x + threadIdx.x;
    int stride = gridDim.x * blockDim.x;
    for (int i = idx; i < E; i += stride) {
        int r = rows[i];
        int p = atomicAdd(&g_cur[r], 1);
        g_ecol[p] = cols[i];
        g_eval[p] = vals[i];
    }
}

// ============================================================================
// GEMM1: supp1 = leaky(ns_emb[M,256] @ Wh[256,128]) -> fp16 output
// ============================================================================
__global__ void __launch_bounds__(512) gemm1_kernel(const float* __restrict__ A,
                                                    const float* __restrict__ Wg,
                                                    __half* __restrict__ C, int M) {
    constexpr int K = 256, NC = 128, LDA = 40, LDB = 136;
    __shared__ __nv_bfloat16 Ah[128][LDA], Al[128][LDA];
    __shared__ __nv_bfloat16 Bh[32][LDB], Bl[32][LDB];
    int tid = threadIdx.x;
    int warp = tid >> 5, lane = tid & 31;
    int wm = (warp & 3) * 32;
    int wn = (warp >> 2) * 32;
    int row0 = blockIdx.x * 128;
    int r_l = lane & 15, c_l = (lane >> 4) << 3;

    float acc[2][4][4];
    #pragma unroll
    for (int mi = 0; mi < 2; mi++)
        #pragma unroll
        for (int ni = 0; ni < 4; ni++)
            #pragma unroll
            for (int t = 0; t < 4; t++) acc[mi][ni][t] = 0.f;

    float4 pa[2], pb[2];

    auto loadA = [&](int k0) {
        #pragma unroll
        for (int i = 0; i < 2; i++) {
            int v = tid + i * 512;
            int row = v >> 3, q = (v & 7) << 2;
            int gr = row0 + row;
            pa[i] = make_float4(0.f, 0.f, 0.f, 0.f);
            if (gr < M) pa[i] = *(const float4*)(A + (size_t)gr * K + k0 + q);
        }
    };
    auto loadB = [&](int k0) {
        #pragma unroll
        for (int i = 0; i < 2; i++) {
            int v = tid + i * 512;
            int br = v >> 5, bc = (v & 31) << 2;
            pb[i] = *(const float4*)(Wg + (size_t)(k0 + br) * NC + bc);
        }
    };

    loadA(0);
    loadB(0);
    for (int it = 0; it < K / 32; it++) {
        #pragma unroll
        for (int i = 0; i < 2; i++) {
            int v = tid + i * 512;
            int row = v >> 3, q = (v & 7) << 2;
            split_bf16(pa[i].x, Ah[row][q + 0], Al[row][q + 0]);
            split_bf16(pa[i].y, Ah[row][q + 1], Al[row][q + 1]);
            split_bf16(pa[i].z, Ah[row][q + 2], Al[row][q + 2]);
            split_bf16(pa[i].w, Ah[row][q + 3], Al[row][q + 3]);
        }
        #pragma unroll
        for (int i = 0; i < 2; i++) {
            int v = tid + i * 512;
            int br = v >> 5, bc = (v & 31) << 2;
            split_bf16(pb[i].x, Bh[br][bc + 0], Bl[br][bc + 0]);
            split_bf16(pb[i].y, Bh[br][bc + 1], Bl[br][bc + 1]);
            split_bf16(pb[i].z, Bh[br][bc + 2], Bl[br][bc + 2]);
            split_bf16(pb[i].w, Bh[br][bc + 3], Bl[br][bc + 3]);
        }
        __syncthreads();
        if (it < K / 32 - 1) {
            loadA((it + 1) * 32);
            loadB((it + 1) * 32);
        }
        #pragma unroll
        for (int s = 0; s < 2; s++) {
            int ks = s * 16;
            unsigned afh[2][4], afl[2][4];
            #pragma unroll
            for (int mi = 0; mi < 2; mi++) {
                ldsm_x4(afh[mi], &Ah[wm + mi * 16 + r_l][ks + c_l]);
                ldsm_x4(afl[mi], &Al[wm + mi * 16 + r_l][ks + c_l]);
            }
            #pragma unroll
            for (int ni = 0; ni < 4; ni++) {
                unsigned bfh[2], bfl[2];
                ldsm_x2t(bfh, &Bh[ks + r_l][wn + ni * 8]);
                ldsm_x2t(bfl, &Bl[ks + r_l][wn + ni * 8]);
                #pragma unroll
                for (int mi = 0; mi < 2; mi++) {
                    mma_bf16(acc[mi][ni], afh[mi], bfh);
                    mma_bf16(acc[mi][ni], afh[mi], bfl);
                    mma_bf16(acc[mi][ni], afl[mi], bfh);
                }
            }
        }
        __syncthreads();
    }
    #pragma unroll
    for (int mi = 0; mi < 2; mi++)
        #pragma unroll
        for (int ni = 0; ni < 4; ni++) {
            int r = row0 + wm + mi * 16 + (lane >> 2);
            int c = wn + ni * 8 + (lane & 3) * 2;
            float v0 = lrelu(acc[mi][ni][0]), v1 = lrelu(acc[mi][ni][1]);
            float v2 = lrelu(acc[mi][ni][2]), v3 = lrelu(acc[mi][ni][3]);
            if (r < M)
                *(__half2*)(C + (size_t)r * NC + c) = __floats2half2_rn(v0, v1);
            if (r + 8 < M)
                *(__half2*)(C + (size_t)(r + 8) * NC + c) = __floats2half2_rn(v2, v3);
        }
}

// ============================================================================
// FUSED: supp2 = leaky( softmax( leaky(acc1)@Mcat ) @ PW ) -> fp16
// (GEMM4 folded into PW = Pcat@Wcat offline.)
// 64-row tiles, 2 CTAs/SM. Register prefetch on GEMM3 B tiles.
// ============================================================================
#define SMEM_FUSED 103424

__global__ void __launch_bounds__(256, 2) attn_fused_kernel(const float* __restrict__ ACC1,
                                                            __half* __restrict__ OUT, int M) {
    extern __shared__ char smem_raw[];
    __nv_bfloat16* Sh = (__nv_bfloat16*)smem_raw;               // [64][264]
    __nv_bfloat16* Sl = Sh + 64 * 264;
    __nv_bfloat16* Bh = (__nv_bfloat16*)(smem_raw + 67584);     // [32][264]
    __nv_bfloat16* Bl = Bh + 32 * 264;
    float* smax = (float*)(smem_raw + 101376);                  // [64][4]
    float* ssum = smax + 256;
    __nv_bfloat16* Xh = Sh;                                     // overlay [64][136]
    __nv_bfloat16* Xl = Sh + 64 * 136;

    int tid = threadIdx.x;
    int warp = tid >> 5, lane = tid & 31;
    int wm = (warp >> 2) * 32;
    int wc = warp & 3;
    int row0 = blockIdx.x * 64;
    int r_l = lane & 15, c_l = (lane >> 4) << 3;

    // ---------- load X = leaky(acc1 tile), split bf16 ----------
    #pragma unroll
    for (int i = 0; i < 8; i++) {
        int v = tid + i * 256;
        int row = v >> 5, q = (v & 31) << 2;
        int gr = row0 + row;
        float4 a4 = make_float4(0.f, 0.f, 0.f, 0.f);
        if (gr < M) a4 = *(const float4*)(ACC1 + (size_t)gr * 128 + q);
        a4.x = lrelu(a4.x); a4.y = lrelu(a4.y);
        a4.z = lrelu(a4.z); a4.w = lrelu(a4.w);
        split_bf16(a4.x, Xh[row * 136 + q + 0], Xl[row * 136 + q + 0]);
        split_bf16(a4.y, Xh[row * 136 + q + 1], Xl[row * 136 + q + 1]);
        split_bf16(a4.z, Xh[row * 136 + q + 2], Xl[row * 136 + q + 2]);
        split_bf16(a4.w, Xh[row * 136 + q + 3], Xl[row * 136 + q + 3]);
    }
    __syncthreads();

    // GEMM2: L = X @ Mcat   (64x256, K=128)
    int wn2 = wc * 64;
    float accA[2][8][4];
    #pragma unroll
    for (int mi = 0; mi < 2; mi++)
        #pragma unroll
        for (int ni = 0; ni < 8; ni++)
            #pragma unroll
            for (int t = 0; t < 4; t++) accA[mi][ni][t] = 0.f;

    for (int it = 0; it < 4; it++) {
        int k0 = it * 32;
        #pragma unroll
        for (int i = 0; i < 4; i++) {
            int s = tid + i * 256;
            int br = s >> 5, bc = (s & 31) << 3;
            *(uint4*)&Bh[br * 264 + bc] = *(const uint4*)(g_Mh + (size_t)(k0 + br) * 256 + bc);
            *(uint4*)&Bl[br * 264 + bc] = *(const uint4*)(g_Ml + (size_t)(k0 + br) * 256 + bc);
        }
        __syncthreads();
        #pragma unroll
        for (int s = 0; s < 2; s++) {
            int ks = k0 + s * 16;
            unsigned afh[2][4], afl[2][4];
            #pragma unroll
            for (int mi = 0; mi < 2; mi++) {
                ldsm_x4(afh[mi], &Xh[(wm + mi * 16 + r_l) * 136 + ks + c_l]);
                ldsm_x4(afl[mi], &Xl[(wm + mi * 16 + r_l) * 136 + ks + c_l]);
            }
            #pragma unroll
            for (int ni = 0; ni < 8; ni++) {
                unsigned bfh[2], bfl[2];
                ldsm_x2t(bfh, &Bh[(s * 16 + r_l) * 264 + wn2 + ni * 8]);
                ldsm_x2t(bfl, &Bl[(s * 16 + r_l) * 264 + wn2 + ni * 8]);
                #pragma unroll
                for (int mi = 0; mi < 2; mi++) {
                    mma_bf16(accA[mi][ni], afh[mi], bfh);
                    mma_bf16(accA[mi][ni], afh[mi], bfl);
                    mma_bf16(accA[mi][ni], afl[mi], bfh);
                }
            }
        }
        __syncthreads();
    }

    // softmax
    int hbase = (wc >> 1) << 1;
    #pragma unroll
    for (int mi = 0; mi < 2; mi++)
        #pragma unroll
        for (int half = 0; half < 2; half++) {
            float m = -1e30f;
            #pragma unroll
            for (int ni = 0; ni < 8; ni++)
                m = fmaxf(m, fmaxf(accA[mi][ni][2 * half], accA[mi][ni][2 * half + 1]));
            m = fmaxf(m, __shfl_xor_sync(0xffffffffu, m, 1));
            m = fmaxf(m, __shfl_xor_sync(0xffffffffu, m, 2));
            if ((lane & 3) == 0) {
                int rowg = wm + mi * 16 + (lane >> 2) + 8 * half;
                smax[rowg * 4 + wc] = m;
            }
        }
    __syncthreads();
    #pragma unroll
    for (int mi = 0; mi < 2; mi++)
        #pragma unroll
        for (int half = 0; half < 2; half++) {
            int rowg = wm + mi * 16 + (lane >> 2) + 8 * half;
            float mh = fmaxf(smax[rowg * 4 + hbase], smax[rowg * 4 + hbase + 1]);
            float s = 0.f;
            #pragma unroll
            for (int ni = 0; ni < 8; ni++) {
                float e0 = __expf(accA[mi][ni][2 * half] - mh);
                float e1 = __expf(accA[mi][ni][2 * half + 1] - mh);
                accA[mi][ni][2 * half] = e0;
                accA[mi][ni][2 * half + 1] = e1;
                s += e0 + e1;
            }
            s += __shfl_xor_sync(0xffffffffu, s, 1);
            s += __shfl_xor_sync(0xffffffffu, s, 2);
            if ((lane & 3) == 0) ssum[rowg * 4 + wc] = s;
        }
    __syncthreads();
    #pragma unroll
    for (int mi = 0; mi < 2; mi++)
        #pragma unroll
        for (int half = 0; half < 2; half++) {
            int rowg = wm + mi * 16 + (lane >> 2) + 8 * half;
            float inv = 1.f / (ssum[rowg * 4 + hbase] + ssum[rowg * 4 + hbase + 1]);
            #pragma unroll
            for (int ni = 0; ni < 8; ni++) {
                float w0 = accA[mi][ni][2 * half] * inv;
                float w1 = accA[mi][ni][2 * half + 1] * inv;
                int colg = wn2 + ni * 8 + 2 * (lane & 3);
                __nv_bfloat16 h0, l0, h1, l1;
                split_bf16(w0, h0, l0);
                split_bf16(w1, h1, l1);
                *(__nv_bfloat162*)&Sh[rowg * 264 + colg] = __nv_bfloat162(h0, h1);
                *(__nv_bfloat162*)&Sl[rowg * 264 + colg] = __nv_bfloat162(l0, l1);
            }
        }
    __syncthreads();

    // GEMM3: supp2 = leaky(S @ PW)   (64x128, K=256)  [register prefetch on B]
    int wn3 = wc * 32;
    int brw = tid >> 4, bcw = (tid & 15) << 3;
    float acc3[2][4][4];
    #pragma unroll
    for (int mi = 0; mi < 2; mi++)
        #pragma unroll
        for (int ni = 0; ni < 4; ni++)
            #pragma unroll
            for (int t = 0; t < 4; t++) acc3[mi][ni][t] = 0.f;

    uint4 pph[2], ppl[2];
    auto loadP = [&](int k0) {
        #pragma unroll
        for (int i = 0; i < 2; i++) {
            int br = brw + i * 16;
            pph[i] = *(const uint4*)(g_PWh + (size_t)(k0 + br) * 128 + bcw);
            ppl[i] = *(const uint4*)(g_PWl + (size_t)(k0 + br) * 128 + bcw);
        }
    };

    loadP(0);
    for (int it = 0; it < 8; it++) {
        #pragma unroll
        for (int i = 0; i < 2; i++) {
            int br = brw + i * 16;
            *(uint4*)&Bh[br * 264 + bcw] = pph[i];
            *(uint4*)&Bl[br * 264 + bcw] = ppl[i];
        }
        __syncthreads();
        if (it < 7) loadP((it + 1) * 32);
        #pragma unroll
        for (int s = 0; s < 2; s++) {
            int ks = it * 32 + s * 16;
            unsigned afh[2][4], afl[2][4];
            #pragma unroll
            for (int mi = 0; mi < 2; mi++) {
                ldsm_x4(afh[mi], &Sh[(wm + mi * 16 + r_l) * 264 + ks + c_l]);
                ldsm_x4(afl[mi], &Sl[(wm + mi * 16 + r_l) * 264 + ks + c_l]);
            }
            #pragma unroll
            for (int ni = 0; ni < 4; ni++) {
                unsigned bfh[2], bfl[2];
                ldsm_x2t(bfh, &Bh[(s * 16 + r_l) * 264 + wn3 + ni * 8]);
                ldsm_x2t(bfl, &Bl[(s * 16 + r_l) * 264 + wn3 + ni * 8]);
                #pragma unroll
                for (int mi = 0; mi < 2; mi++) {
                    mma_bf16(acc3[mi][ni], afh[mi], bfh);
                    mma_bf16(acc3[mi][ni], afh[mi], bfl);
                    mma_bf16(acc3[mi][ni], afl[mi], bfh);
                }
            }
        }
        __syncthreads();
    }

    // epilogue: leaky + fp16 store
    #pragma unroll
    for (int mi = 0; mi < 2; mi++)
        #pragma unroll
        for (int ni = 0; ni < 4; ni++) {
            int r = row0 + wm + mi * 16 + (lane >> 2);
            int c = wn3 + ni * 8 + (lane & 3) * 2;
            float v0 = lrelu(acc3[mi][ni][0]), v1 = lrelu(acc3[mi][ni][1]);
            float v2 = lrelu(acc3[mi][ni][2]), v3 = lrelu(acc3[mi][ni][3]);
            if (r < M)
                *(__half2*)(OUT + (size_t)r * 128 + c) = __floats2half2_rn(v0, v1);
            if (r + 8 < M)
                *(__half2*)(OUT + (size_t)(r + 8) * 128 + c) = __floats2half2_rn(v2, v3);
        }
}

// ---------------- CSR SpMM: warp per row, fp16 gather, fp32 accum ----------
template <bool FINAL>
__global__ void __launch_bounds__(256) csr_spmm_kernel(const __half* __restrict__ x,
                                                       float* __restrict__ out, int Nn) {
    int w = (blockIdx.x * blockDim.x + threadIdx.x) >> 5;
    int lane = threadIdx.x & 31;
    if (w >= Nn) return;
    int s = g_off[w], e = g_off[w + 1];
    float4 acc = make_float4(0.f, 0.f, 0.f, 0.f);
    for (int base = s; base < e; base += 32) {
        int idx = base + lane;
        int c = 0;
        float v = 0.f;
        if (idx < e) {
            c = g_ecol[idx];
            v = g_eval[idx];
        }
        int n = min(32, e - base);
        for (int j = 0; j < n; j++) {
            int cj = __shfl_sync(0xffffffffu, c, j);
            float vj = __shfl_sync(0xffffffffu, v, j);
            uint2 raw = *(const uint2*)(x + (size_t)cj * 128 + lane * 4);
            float2 f0 = __half22float2(*(__half2*)&raw.x);
            float2 f1 = __half22float2(*(__half2*)&raw.y);
            acc.x += vj * f0.x;
            acc.y += vj * f0.y;
            acc.z += vj * f1.x;
            acc.w += vj * f1.y;
        }
    }
    if (FINAL) {
        acc.x = lrelu(acc.x); acc.y = lrelu(acc.y);
        acc.z = lrelu(acc.z); acc.w = lrelu(acc.w);
        if (lane < 16)
            *(float4*)(out + (size_t)w * 64 + lane * 4) = acc;
        else
            *(float4*)(out + (size_t)Nn * 64 + (size_t)w * 64 + (lane - 16) * 4) = acc;
    } else {
        *(float4*)(out + (size_t)w * 128 + lane * 4) = acc;
    }
}

// ---------------------------------------------------------------------------
extern "C" void kernel_launch(void* const* d_in, const int* in_sizes, int n_in,
                              void* d_out, int out_size) {
    const float* ns_emb = (const float*)d_in[0];
    const int* erow = (const int*)d_in[1];
    const int* ecol = (const int*)d_in[2];
    const float* eval_ = (const float*)d_in[3];
    const float* cond = (const float*)d_in[4];
    const float* Wh = (const float*)d_in[5];
    const float* Wmu = (const float*)d_in[6];
    const float* Wvar = (const float*)d_in[7];
    const float* Wq = (const float*)d_in[8];
    const float* Wk = (const float*)d_in[9];
    const float* Wv = (const float*)d_in[10];
    const float* Wo = (const float*)d_in[11];

    int N = in_sizes[0] / 256;
    int E = in_sizes[1];

    __half *supp1, *supp2;
    float *acc1;
    cudaGetSymbolAddress((void**)&supp1, g_supp1);
    cudaGetSymbolAddress((void**)&acc1, g_acc1);
    cudaGetSymbolAddress((void**)&supp2, g_supp2);

    cudaFuncSetAttribute(attn_fused_kernel,
                         cudaFuncAttributeMaxDynamicSharedMemorySize, SMEM_FUSED);

    int gm = (N + 127) / 128;
    int gm64 = (N + 63) / 64;
    int nchunks = (N + 255) / 256;
    int spmm_blocks = (N * 32 + 255) / 256;

    // ---- fork a side stream (prep + CSR build) overlapping gemm1 ----------
    cudaStream_t s2;
    cudaStreamCreate(&s2);
    cudaEvent_t e1, e2;
    cudaEventCreateWithFlags(&e1, cudaEventDisableTiming);
    cudaEventCreateWithFlags(&e2, cudaEventDisableTiming);

    cudaEventRecord(e1, 0);
    cudaStreamWaitEvent(s2, e1, 0);

    // side stream: prep + weight folds + CSR build
    hist_kernel<<<1024, 256, 0, s2>>>(erow, E);
    prep_kernel<<<128, 256, 0, s2>>>(cond, Wk, Wv, Wmu, Wvar);
    fold_kernel<<<256, 256, 0, s2>>>(Wq, Wo);
    pw_kernel<<<128, 256, 0, s2>>>();
    scanA_kernel<<<nchunks, 256, 0, s2>>>(N);
    scanB_kernel<<<1, 256, 0, s2>>>(nchunks);
    scanC_kernel<<<256, 256, 0, s2>>>(N, E);
    scatter_kernel<<<1024, 256, 0, s2>>>(erow, ecol, eval_, E);
    cudaEventRecord(e2, s2);

    // main stream: gemm1 (Wh split inline) -> fp16 supp1
    gemm1_kernel<<<gm, 512>>>(ns_emb, Wh, supp1, N);

    // join: spmm needs CSR + supp1
    cudaStreamWaitEvent(0, e2, 0);

    // acc1 = spmm(supp1)  -- fp16 gather, fp32 out
    csr_spmm_kernel<false><<<spmm_blocks, 256>>>(supp1, acc1, N);
    // supp2 = leaky( softmax(leaky(acc1)@Mcat) @ PW ) -> fp16
    attn_fused_kernel<<<gm64, 256, SMEM_FUSED>>>(acc1, supp2, N);
    // out = leaky(spmm(supp2)) split into mu|var  (fp32 output)
    csr_spmm_kernel<true><<<spmm_blocks, 256>>>(supp2, (float*)d_out, N);

    cudaEventDestroy(e1);
    cudaEventDestroy(e2);
    cudaStreamDestroy(s2);
}

// round 15
// speedup vs baseline: 1.3792x; 1.1031x over previous
#include <cuda_runtime.h>
#include <cuda_bf16.h>
#include <cuda_fp16.h>
#include <math.h>

#define NMAX 50000
#define EMAX 600000

// ---------------- scratch (device globals; no allocation allowed) ----------
__device__ __align__(16) __half g_supp1[NMAX * 128];   // fp16: halves gather BW
__device__ __align__(16) float  g_acc1 [NMAX * 128];
__device__ __align__(16) __half g_supp2[NMAX * 128];   // fp16
__device__ __align__(16) float  g_Kb   [128 * 64];
__device__ __align__(16) float  g_Vb   [128 * 64];
__device__ __align__(16) float  g_Pc   [256 * 128];    // Pcat fp32 (pre-PW)
__device__ __align__(16) float  g_Wc   [128 * 128];    // Wcat fp32 (pre-PW)
// CSR build (g_cnt starts zeroed at module load; scanA re-zeros it each call)
__device__ int   g_cnt [NMAX];
__device__ int   g_off [NMAX + 1];
__device__ int   g_cur [NMAX];
__device__ int   g_bsum[256];
__device__ int   g_boff[256];
__device__ __align__(16) int   g_ecol[EMAX];
__device__ __align__(16) float g_eval[EMAX];
// pre-split bf16 weights (hi/lo)
__device__ __align__(16) __nv_bfloat16 g_Mh [128 * 256], g_Ml [128 * 256];
__device__ __align__(16) __nv_bfloat16 g_PWh[256 * 128], g_PWl[256 * 128];  // Pcat@Wcat

__device__ __forceinline__ float lrelu(float x) { return x > 0.f ? x : 0.01f * x; }

__device__ __forceinline__ void split_bf16(float x, __nv_bfloat16& h, __nv_bfloat16& l) {
    h = __float2bfloat16(x);
    l = __float2bfloat16(x - __bfloat162float(h));
}

__device__ __forceinline__ void mma_bf16(float* d, const unsigned* a, const unsigned* b) {
    asm volatile(
        "mma.sync.aligned.m16n8k16.row.col.f32.bf16.bf16.f32 "
        "{%0,%1,%2,%3}, {%4,%5,%6,%7}, {%8,%9}, {%0,%1,%2,%3};\n"
        : "+f"(d[0]), "+f"(d[1]), "+f"(d[2]), "+f"(d[3])
        : "r"(a[0]), "r"(a[1]), "r"(a[2]), "r"(a[3]), "r"(b[0]), "r"(b[1]));
}

__device__ __forceinline__ void ldsm_x4(unsigned* r, const __nv_bfloat16* p) {
    unsigned addr = (unsigned)__cvta_generic_to_shared(p);
    asm volatile("ldmatrix.sync.aligned.m8n8.x4.shared.b16 {%0,%1,%2,%3}, [%4];\n"
                 : "=r"(r[0]), "=r"(r[1]), "=r"(r[2]), "=r"(r[3]) : "r"(addr));
}

__device__ __forceinline__ void ldsm_x2t(unsigned* r, const __nv_bfloat16* p) {
    unsigned addr = (unsigned)__cvta_generic_to_shared(p);
    asm volatile("ldmatrix.sync.aligned.m8n8.x2.trans.shared.b16 {%0,%1}, [%2];\n"
                 : "=r"(r[0]), "=r"(r[1]) : "r"(addr));
}

// ---------------- prep: K/V projections + Wcat (fp32), 4-way ILP ------------
__global__ void prep_kernel(const float* __restrict__ cond,
                            const float* __restrict__ Wk,
                            const float* __restrict__ Wv,
                            const float* __restrict__ Wmu,
                            const float* __restrict__ Wvar) {
    int o = blockIdx.x * blockDim.x + threadIdx.x;  // 32768 threads
    if (o < 8192) {
        int key = o >> 6, d = o & 63;
        float s0 = 0.f, s1 = 0.f, s2 = 0.f, s3 = 0.f;
        #pragma unroll 8
        for (int m = 0; m < 128; m += 4) {
            s0 += cond[key * 128 + m + 0] * Wk[(m + 0) * 64 + d];
            s1 += cond[key * 128 + m + 1] * Wk[(m + 1) * 64 + d];
            s2 += cond[key * 128 + m + 2] * Wk[(m + 2) * 64 + d];
            s3 += cond[key * 128 + m + 3] * Wk[(m + 3) * 64 + d];
        }
        g_Kb[o] = (s0 + s1) + (s2 + s3);
    } else if (o < 16384) {
        int o2 = o - 8192;
        int key = o2 >> 6, d = o2 & 63;
        float s0 = 0.f, s1 = 0.f, s2 = 0.f, s3 = 0.f;
        #pragma unroll 8
        for (int m = 0; m < 128; m += 4) {
            s0 += cond[key * 128 + m + 0] * Wv[(m + 0) * 64 + d];
            s1 += cond[key * 128 + m + 1] * Wv[(m + 1) * 64 + d];
            s2 += cond[key * 128 + m + 2] * Wv[(m + 2) * 64 + d];
            s3 += cond[key * 128 + m + 3] * Wv[(m + 3) * 64 + d];
        }
        g_Vb[o2] = (s0 + s1) + (s2 + s3);
    } else {
        int i = o - 16384;  // 0..16383 = 128*128
        int k = i >> 7, n = i & 127;
        g_Wc[i] = (n < 64) ? Wmu[k * 64 + n] : Wvar[k * 64 + (n - 64)];
    }
}

// ---------------- fold heads: Mcat (split), Pcat (fp32) ---------------------
__global__ void fold_kernel(const float* __restrict__ Wq,
                            const float* __restrict__ Wo) {
    const float scale = 0.17677669529663687f;  // 1/sqrt(32)
    int o = blockIdx.x * blockDim.x + threadIdx.x;  // 65536
    if (o < 32768) {
        int c = o >> 8, hk = o & 255;
        int h = hk >> 7, key = hk & 127;
        float s0 = 0.f, s1 = 0.f, s2 = 0.f, s3 = 0.f;
        #pragma unroll
        for (int d = 0; d < 32; d += 4) {
            s0 += Wq[c * 64 + h * 32 + d + 0] * g_Kb[key * 64 + h * 32 + d + 0];
            s1 += Wq[c * 64 + h * 32 + d + 1] * g_Kb[key * 64 + h * 32 + d + 1];
            s2 += Wq[c * 64 + h * 32 + d + 2] * g_Kb[key * 64 + h * 32 + d + 2];
            s3 += Wq[c * 64 + h * 32 + d + 3] * g_Kb[key * 64 + h * 32 + d + 3];
        }
        split_bf16(((s0 + s1) + (s2 + s3)) * scale, g_Mh[o], g_Ml[o]);
    } else {
        int o2 = o - 32768;
        int hk = o2 >> 7, j = o2 & 127;
        int h = hk >> 7, key = hk & 127;
        float s0 = 0.f, s1 = 0.f, s2 = 0.f, s3 = 0.f;
        #pragma unroll
        for (int d = 0; d < 32; d += 4) {
            s0 += g_Vb[key * 64 + h * 32 + d + 0] * Wo[(h * 32 + d + 0) * 128 + j];
            s1 += g_Vb[key * 64 + h * 32 + d + 1] * Wo[(h * 32 + d + 1) * 128 + j];
            s2 += g_Vb[key * 64 + h * 32 + d + 2] * Wo[(h * 32 + d + 2) * 128 + j];
            s3 += g_Vb[key * 64 + h * 32 + d + 3] * Wo[(h * 32 + d + 3) * 128 + j];
        }
        g_Pc[o2] = (s0 + s1) + (s2 + s3);
    }
}

// ---------------- PW = Pcat @ Wcat  [256,128], split bf16, 4-way ILP --------
__global__ void pw_kernel() {
    int idx = blockIdx.x * blockDim.x + threadIdx.x;  // 32768
    int i = idx >> 7, j = idx & 127;
    float s0 = 0.f, s1 = 0.f, s2 = 0.f, s3 = 0.f;
    #pragma unroll 8
    for (int m = 0; m < 128; m += 4) {
        s0 += g_Pc[i * 128 + m + 0] * g_Wc[(m + 0) * 128 + j];
        s1 += g_Pc[i * 128 + m + 1] * g_Wc[(m + 1) * 128 + j];
        s2 += g_Pc[i * 128 + m + 2] * g_Wc[(m + 2) * 128 + j];
        s3 += g_Pc[i * 128 + m + 3] * g_Wc[(m + 3) * 128 + j];
    }
    split_bf16((s0 + s1) + (s2 + s3), g_PWh[idx], g_PWl[idx]);
}

// ---------------- CSR build -------------------------------------------------
__global__ void hist_kernel(const int* __restrict__ rows, int E) {
    int idx = blockIdx.x * blockDim.x + threadIdx.x;
    int stride = gridDim.x * blockDim.x;
    for (int i = idx; i < E; i += stride) atomicAdd(&g_cnt[rows[i]], 1);
}

__global__ void scanA_kernel(int Nn) {
    __shared__ int s[256];
    int t = threadIdx.x, i = blockIdx.x * 256 + t;
    int v = (i < Nn) ? g_cnt[i] : 0;
    s[t] = v;
    __syncthreads();
    #pragma unroll
    for (int o = 1; o < 256; o <<= 1) {
        int x = (t >= o) ? s[t - o] : 0;
        __syncthreads();
        s[t] += x;
        __syncthreads();
    }
    if (i < Nn) {
        g_off[i] = s[t] - v;
        g_cnt[i] = 0;  // re-zero for next call (invariant across graph replays)
    }
    if (t == 255) g_bsum[blockIdx.x] = s[255];
}

__global__ void scanB_kernel(int nb) {
    __shared__ int s[256];
    int t = threadIdx.x;
    int v = (t < nb) ? g_bsum[t] : 0;
    s[t] = v;
    __syncthreads();
    #pragma unroll
    for (int o = 1; o < 256; o <<= 1) {
        int x = (t >= o) ? s[t - o] : 0;
        __syncthreads();
        s[t] += x;
        __syncthreads();
    }
    g_boff[t] = s[t] - v;
}

__global__ void scanC_kernel(int Nn, int E) {
    int idx = blockIdx.x * blockDim.x + threadIdx.x;
    int stride = gridDim.x * blockDim.x;
    for (int i = idx; i < Nn; i += stride) {
        int o = g_off[i] + g_boff[i >> 8];
        g_off[i] = o;
        g_cur[i] = o;
    }
    if (idx == 0) g_off[Nn] = E;
}

__global__ void scatter_kernel(const int* __restrict__ rows,
                               const int* __restrict__ cols,
                               const float* __restrict__ vals, int E) {
    int idx = blockIdx.x * blockDim.x + threadIdx.x;
    int stride = gridDim.x * blockDim.x;
    for (int i = idx; i < E; i += stride) {
        int r = rows[i];
        int p = atomicAdd(&g_cur[r], 1);
        g_ecol[p] = cols[i];
        g_eval[p] = vals[i];
    }
}

// ============================================================================
// GEMM1: supp1 = leaky(ns_emb[M,256] @ Wh[256,128]) -> fp16 output
// ============================================================================
__global__ void __launch_bounds__(512) gemm1_kernel(const float* __restrict__ A,
                                                    const float* __restrict__ Wg,
                                                    __half* __restrict__ C, int M) {
    constexpr int K = 256, NC = 128, LDA = 40, LDB = 136;
    __shared__ __nv_bfloat16 Ah[128][LDA], Al[128][LDA];
    __shared__ __nv_bfloat16 Bh[32][LDB], Bl[32][LDB];
    int tid = threadIdx.x;
    int warp = tid >> 5, lane = tid & 31;
    int wm = (warp & 3) * 32;
    int wn = (warp >> 2) * 32;
    int row0 = blockIdx.x * 128;
    int r_l = lane & 15, c_l = (lane >> 4) << 3;

    float acc[2][4][4];
    #pragma unroll
    for (int mi = 0; mi < 2; mi++)
        #pragma unroll
        for (int ni = 0; ni < 4; ni++)
            #pragma unroll
            for (int t = 0; t < 4; t++) acc[mi][ni][t] = 0.f;

    float4 pa[2], pb[2];

    auto loadA = [&](int k0) {
        #pragma unroll
        for (int i = 0; i < 2; i++) {
            int v = tid + i * 512;
            int row = v >> 3, q = (v & 7) << 2;
            int gr = row0 + row;
            pa[i] = make_float4(0.f, 0.f, 0.f, 0.f);
            if (gr < M) pa[i] = *(const float4*)(A + (size_t)gr * K + k0 + q);
        }
    };
    auto loadB = [&](int k0) {
        #pragma unroll
        for (int i = 0; i < 2; i++) {
            int v = tid + i * 512;
            int br = v >> 5, bc = (v & 31) << 2;
            pb[i] = *(const float4*)(Wg + (size_t)(k0 + br) * NC + bc);
        }
    };

    loadA(0);
    loadB(0);
    for (int it = 0; it < K / 32; it++) {
        #pragma unroll
        for (int i = 0; i < 2; i++) {
            int v = tid + i * 512;
            int row = v >> 3, q = (v & 7) << 2;
            split_bf16(pa[i].x, Ah[row][q + 0], Al[row][q + 0]);
            split_bf16(pa[i].y, Ah[row][q + 1], Al[row][q + 1]);
            split_bf16(pa[i].z, Ah[row][q + 2], Al[row][q + 2]);
            split_bf16(pa[i].w, Ah[row][q + 3], Al[row][q + 3]);
        }
        #pragma unroll
        for (int i = 0; i < 2; i++) {
            int v = tid + i * 512;
            int br = v >> 5, bc = (v & 31) << 2;
            split_bf16(pb[i].x, Bh[br][bc + 0], Bl[br][bc + 0]);
            split_bf16(pb[i].y, Bh[br][bc + 1], Bl[br][bc + 1]);
            split_bf16(pb[i].z, Bh[br][bc + 2], Bl[br][bc + 2]);
            split_bf16(pb[i].w, Bh[br][bc + 3], Bl[br][bc + 3]);
        }
        __syncthreads();
        if (it < K / 32 - 1) {
            loadA((it + 1) * 32);
            loadB((it + 1) * 32);
        }
        #pragma unroll
        for (int s = 0; s < 2; s++) {
            int ks = s * 16;
            unsigned afh[2][4], afl[2][4];
            #pragma unroll
            for (int mi = 0; mi < 2; mi++) {
                ldsm_x4(afh[mi], &Ah[wm + mi * 16 + r_l][ks + c_l]);
                ldsm_x4(afl[mi], &Al[wm + mi * 16 + r_l][ks + c_l]);
            }
            #pragma unroll
            for (int ni = 0; ni < 4; ni++) {
                unsigned bfh[2], bfl[2];
                ldsm_x2t(bfh, &Bh[ks + r_l][wn + ni * 8]);
                ldsm_x2t(bfl, &Bl[ks + r_l][wn + ni * 8]);
                #pragma unroll
                for (int mi = 0; mi < 2; mi++) {
                    mma_bf16(acc[mi][ni], afh[mi], bfh);
                    mma_bf16(acc[mi][ni], afh[mi], bfl);
                    mma_bf16(acc[mi][ni], afl[mi], bfh);
                }
            }
        }
        __syncthreads();
    }
    #pragma unroll
    for (int mi = 0; mi < 2; mi++)
        #pragma unroll
        for (int ni = 0; ni < 4; ni++) {
            int r = row0 + wm + mi * 16 + (lane >> 2);
            int c = wn + ni * 8 + (lane & 3) * 2;
            float v0 = lrelu(acc[mi][ni][0]), v1 = lrelu(acc[mi][ni][1]);
            float v2 = lrelu(acc[mi][ni][2]), v3 = lrelu(acc[mi][ni][3]);
            if (r < M)
                *(__half2*)(C + (size_t)r * NC + c) = __floats2half2_rn(v0, v1);
            if (r + 8 < M)
                *(__half2*)(C + (size_t)(r + 8) * NC + c) = __floats2half2_rn(v2, v3);
        }
}

// ============================================================================
// FUSED: supp2 = leaky( softmax( leaky(acc1)@Mcat ) @ PW ) -> fp16
// 64-row tiles, 2 CTAs/SM. Register prefetch on GEMM3 B tiles.
// ============================================================================
#define SMEM_FUSED 103424

__global__ void __launch_bounds__(256, 2) attn_fused_kernel(const float* __restrict__ ACC1,
                                                            __half* __restrict__ OUT, int M) {
    extern __shared__ char smem_raw[];
    __nv_bfloat16* Sh = (__nv_bfloat16*)smem_raw;               // [64][264]
    __nv_bfloat16* Sl = Sh + 64 * 264;
    __nv_bfloat16* Bh = (__nv_bfloat16*)(smem_raw + 67584);     // [32][264]
    __nv_bfloat16* Bl = Bh + 32 * 264;
    float* smax = (float*)(smem_raw + 101376);                  // [64][4]
    float* ssum = smax + 256;
    __nv_bfloat16* Xh = Sh;                                     // overlay [64][136]
    __nv_bfloat16* Xl = Sh + 64 * 136;

    int tid = threadIdx.x;
    int warp = tid >> 5, lane = tid & 31;
    int wm = (warp >> 2) * 32;
    int wc = warp & 3;
    int row0 = blockIdx.x * 64;
    int r_l = lane & 15, c_l = (lane >> 4) << 3;

    // ---------- load X = leaky(acc1 tile), split bf16 ----------
    #pragma unroll
    for (int i = 0; i < 8; i++) {
        int v = tid + i * 256;
        int row = v >> 5, q = (v & 31) << 2;
        int gr = row0 + row;
        float4 a4 = make_float4(0.f, 0.f, 0.f, 0.f);
        if (gr < M) a4 = *(const float4*)(ACC1 + (size_t)gr * 128 + q);
        a4.x = lrelu(a4.x); a4.y = lrelu(a4.y);
        a4.z = lrelu(a4.z); a4.w = lrelu(a4.w);
        split_bf16(a4.x, Xh[row * 136 + q + 0], Xl[row * 136 + q + 0]);
        split_bf16(a4.y, Xh[row * 136 + q + 1], Xl[row * 136 + q + 1]);
        split_bf16(a4.z, Xh[row * 136 + q + 2], Xl[row * 136 + q + 2]);
        split_bf16(a4.w, Xh[row * 136 + q + 3], Xl[row * 136 + q + 3]);
    }
    __syncthreads();

    // GEMM2: L = X @ Mcat   (64x256, K=128)
    int wn2 = wc * 64;
    float accA[2][8][4];
    #pragma unroll
    for (int mi = 0; mi < 2; mi++)
        #pragma unroll
        for (int ni = 0; ni < 8; ni++)
            #pragma unroll
            for (int t = 0; t < 4; t++) accA[mi][ni][t] = 0.f;

    for (int it = 0; it < 4; it++) {
        int k0 = it * 32;
        #pragma unroll
        for (int i = 0; i < 4; i++) {
            int s = tid + i * 256;
            int br = s >> 5, bc = (s & 31) << 3;
            *(uint4*)&Bh[br * 264 + bc] = *(const uint4*)(g_Mh + (size_t)(k0 + br) * 256 + bc);
            *(uint4*)&Bl[br * 264 + bc] = *(const uint4*)(g_Ml + (size_t)(k0 + br) * 256 + bc);
        }
        __syncthreads();
        #pragma unroll
        for (int s = 0; s < 2; s++) {
            int ks = k0 + s * 16;
            unsigned afh[2][4], afl[2][4];
            #pragma unroll
            for (int mi = 0; mi < 2; mi++) {
                ldsm_x4(afh[mi], &Xh[(wm + mi * 16 + r_l) * 136 + ks + c_l]);
                ldsm_x4(afl[mi], &Xl[(wm + mi * 16 + r_l) * 136 + ks + c_l]);
            }
            #pragma unroll
            for (int ni = 0; ni < 8; ni++) {
                unsigned bfh[2], bfl[2];
                ldsm_x2t(bfh, &Bh[(s * 16 + r_l) * 264 + wn2 + ni * 8]);
                ldsm_x2t(bfl, &Bl[(s * 16 + r_l) * 264 + wn2 + ni * 8]);
                #pragma unroll
                for (int mi = 0; mi < 2; mi++) {
                    mma_bf16(accA[mi][ni], afh[mi], bfh);
                    mma_bf16(accA[mi][ni], afh[mi], bfl);
                    mma_bf16(accA[mi][ni], afl[mi], bfh);
                }
            }
        }
        __syncthreads();
    }

    // softmax
    int hbase = (wc >> 1) << 1;
    #pragma unroll
    for (int mi = 0; mi < 2; mi++)
        #pragma unroll
        for (int half = 0; half < 2; half++) {
            float m = -1e30f;
            #pragma unroll
            for (int ni = 0; ni < 8; ni++)
                m = fmaxf(m, fmaxf(accA[mi][ni][2 * half], accA[mi][ni][2 * half + 1]));
            m = fmaxf(m, __shfl_xor_sync(0xffffffffu, m, 1));
            m = fmaxf(m, __shfl_xor_sync(0xffffffffu, m, 2));
            if ((lane & 3) == 0) {
                int rowg = wm + mi * 16 + (lane >> 2) + 8 * half;
                smax[rowg * 4 + wc] = m;
            }
        }
    __syncthreads();
    #pragma unroll
    for (int mi = 0; mi < 2; mi++)
        #pragma unroll
        for (int half = 0; half < 2; half++) {
            int rowg = wm + mi * 16 + (lane >> 2) + 8 * half;
            float mh = fmaxf(smax[rowg * 4 + hbase], smax[rowg * 4 + hbase + 1]);
            float s = 0.f;
            #pragma unroll
            for (int ni = 0; ni < 8; ni++) {
                float e0 = __expf(accA[mi][ni][2 * half] - mh);
                float e1 = __expf(accA[mi][ni][2 * half + 1] - mh);
                accA[mi][ni][2 * half] = e0;
                accA[mi][ni][2 * half + 1] = e1;
                s += e0 + e1;
            }
            s += __shfl_xor_sync(0xffffffffu, s, 1);
            s += __shfl_xor_sync(0xffffffffu, s, 2);
            if ((lane & 3) == 0) ssum[rowg * 4 + wc] = s;
        }
    __syncthreads();
    #pragma unroll
    for (int mi = 0; mi < 2; mi++)
        #pragma unroll
        for (int half = 0; half < 2; half++) {
            int rowg = wm + mi * 16 + (lane >> 2) + 8 * half;
            float inv = 1.f / (ssum[rowg * 4 + hbase] + ssum[rowg * 4 + hbase + 1]);
            #pragma unroll
            for (int ni = 0; ni < 8; ni++) {
                float w0 = accA[mi][ni][2 * half] * inv;
                float w1 = accA[mi][ni][2 * half + 1] * inv;
                int colg = wn2 + ni * 8 + 2 * (lane & 3);
                __nv_bfloat16 h0, l0, h1, l1;
                split_bf16(w0, h0, l0);
                split_bf16(w1, h1, l1);
                *(__nv_bfloat162*)&Sh[rowg * 264 + colg] = __nv_bfloat162(h0, h1);
                *(__nv_bfloat162*)&Sl[rowg * 264 + colg] = __nv_bfloat162(l0, l1);
            }
        }
    __syncthreads();

    // GEMM3: supp2 = leaky(S @ PW)   (64x128, K=256)  [register prefetch on B]
    int wn3 = wc * 32;
    int brw = tid >> 4, bcw = (tid & 15) << 3;
    float acc3[2][4][4];
    #pragma unroll
    for (int mi = 0; mi < 2; mi++)
        #pragma unroll
        for (int ni = 0; ni < 4; ni++)
            #pragma unroll
            for (int t = 0; t < 4; t++) acc3[mi][ni][t] = 0.f;

    uint4 pph[2], ppl[2];
    auto loadP = [&](int k0) {
        #pragma unroll
        for (int i = 0; i < 2; i++) {
            int br = brw + i * 16;
            pph[i] = *(const uint4*)(g_PWh + (size_t)(k0 + br) * 128 + bcw);
            ppl[i] = *(const uint4*)(g_PWl + (size_t)(k0 + br) * 128 + bcw);
        }
    };

    loadP(0);
    for (int it = 0; it < 8; it++) {
        #pragma unroll
        for (int i = 0; i < 2; i++) {
            int br = brw + i * 16;
            *(uint4*)&Bh[br * 264 + bcw] = pph[i];
            *(uint4*)&Bl[br * 264 + bcw] = ppl[i];
        }
        __syncthreads();
        if (it < 7) loadP((it + 1) * 32);
        #pragma unroll
        for (int s = 0; s < 2; s++) {
            int ks = it * 32 + s * 16;
            unsigned afh[2][4], afl[2][4];
            #pragma unroll
            for (int mi = 0; mi < 2; mi++) {
                ldsm_x4(afh[mi], &Sh[(wm + mi * 16 + r_l) * 264 + ks + c_l]);
                ldsm_x4(afl[mi], &Sl[(wm + mi * 16 + r_l) * 264 + ks + c_l]);
            }
            #pragma unroll
            for (int ni = 0; ni < 4; ni++) {
                unsigned bfh[2], bfl[2];
                ldsm_x2t(bfh, &Bh[(s * 16 + r_l) * 264 + wn3 + ni * 8]);
                ldsm_x2t(bfl, &Bl[(s * 16 + r_l) * 264 + wn3 + ni * 8]);
                #pragma unroll
                for (int mi = 0; mi < 2; mi++) {
                    mma_bf16(acc3[mi][ni], afh[mi], bfh);
                    mma_bf16(acc3[mi][ni], afh[mi], bfl);
                    mma_bf16(acc3[mi][ni], afl[mi], bfh);
                }
            }
        }
        __syncthreads();
    }

    // epilogue: leaky + fp16 store
    #pragma unroll
    for (int mi = 0; mi < 2; mi++)
        #pragma unroll
        for (int ni = 0; ni < 4; ni++) {
            int r = row0 + wm + mi * 16 + (lane >> 2);
            int c = wn3 + ni * 8 + (lane & 3) * 2;
            float v0 = lrelu(acc3[mi][ni][0]), v1 = lrelu(acc3[mi][ni][1]);
            float v2 = lrelu(acc3[mi][ni][2]), v3 = lrelu(acc3[mi][ni][3]);
            if (r < M)
                *(__half2*)(OUT + (size_t)r * 128 + c) = __floats2half2_rn(v0, v1);
            if (r + 8 < M)
                *(__half2*)(OUT + (size_t)(r + 8) * 128 + c) = __floats2half2_rn(v2, v3);
        }
}

// ---------------- CSR SpMM: warp per row, fp16 gather, fp32 accum ----------
template <bool FINAL>
__global__ void __launch_bounds__(256) csr_spmm_kernel(const __half* __restrict__ x,
                                                       float* __restrict__ out, int Nn) {
    int w = (blockIdx.x * blockDim.x + threadIdx.x) >> 5;
    int lane = threadIdx.x & 31;
    if (w >= Nn) return;
    int s = g_off[w], e = g_off[w + 1];
    float4 acc = make_float4(0.f, 0.f, 0.f, 0.f);
    for (int base = s; base < e; base += 32) {
        int idx = base + lane;
        int c = 0;
        float v = 0.f;
        if (idx < e) {
            c = g_ecol[idx];
            v = g_eval[idx];
        }
        int n = min(32, e - base);
        for (int j = 0; j < n; j++) {
            int cj = __shfl_sync(0xffffffffu, c, j);
            float vj = __shfl_sync(0xffffffffu, v, j);
            uint2 raw = *(const uint2*)(x + (size_t)cj * 128 + lane * 4);
            float2 f0 = __half22float2(*(__half2*)&raw.x);
            float2 f1 = __half22float2(*(__half2*)&raw.y);
            acc.x += vj * f0.x;
            acc.y += vj * f0.y;
            acc.z += vj * f1.x;
            acc.w += vj * f1.y;
        }
    }
    if (FINAL) {
        acc.x = lrelu(acc.x); acc.y = lrelu(acc.y);
        acc.z = lrelu(acc.z); acc.w = lrelu(acc.w);
        if (lane < 16)
            *(float4*)(out + (size_t)w * 64 + lane * 4) = acc;
        else
            *(float4*)(out + (size_t)Nn * 64 + (size_t)w * 64 + (lane - 16) * 4) = acc;
    } else {
        *(float4*)(out + (size_t)w * 128 + lane * 4) = acc;
    }
}

// ---------------------------------------------------------------------------
extern "C" void kernel_launch(void* const* d_in, const int* in_sizes, int n_in,
                              void* d_out, int out_size) {
    const float* ns_emb = (const float*)d_in[0];
    const int* erow = (const int*)d_in[1];
    const int* ecol = (const int*)d_in[2];
    const float* eval_ = (const float*)d_in[3];
    const float* cond = (const float*)d_in[4];
    const float* Wh = (const float*)d_in[5];
    const float* Wmu = (const float*)d_in[6];
    const float* Wvar = (const float*)d_in[7];
    const float* Wq = (const float*)d_in[8];
    const float* Wk = (const float*)d_in[9];
    const float* Wv = (const float*)d_in[10];
    const float* Wo = (const float*)d_in[11];

    int N = in_sizes[0] / 256;
    int E = in_sizes[1];

    __half *supp1, *supp2;
    float *acc1;
    cudaGetSymbolAddress((void**)&supp1, g_supp1);
    cudaGetSymbolAddress((void**)&acc1, g_acc1);
    cudaGetSymbolAddress((void**)&supp2, g_supp2);

    cudaFuncSetAttribute(attn_fused_kernel,
                         cudaFuncAttributeMaxDynamicSharedMemorySize, SMEM_FUSED);

    int gm = (N + 127) / 128;
    int gm64 = (N + 63) / 64;
    int nchunks = (N + 255) / 256;
    int spmm_blocks = (N * 32 + 255) / 256;

    // ---- fork two side streams: s2 = CSR build, s3 = weight folds ---------
    cudaStream_t s2, s3;
    cudaStreamCreate(&s2);
    cudaStreamCreate(&s3);
    cudaEvent_t e1, e2, e3;
    cudaEventCreateWithFlags(&e1, cudaEventDisableTiming);
    cudaEventCreateWithFlags(&e2, cudaEventDisableTiming);
    cudaEventCreateWithFlags(&e3, cudaEventDisableTiming);

    cudaEventRecord(e1, 0);
    cudaStreamWaitEvent(s2, e1, 0);
    cudaStreamWaitEvent(s3, e1, 0);

    // s2: CSR build chain (g_cnt is zero on entry; scanA re-zeros)
    hist_kernel<<<1024, 256, 0, s2>>>(erow, E);
    scanA_kernel<<<nchunks, 256, 0, s2>>>(N);
    scanB_kernel<<<1, 256, 0, s2>>>(nchunks);
    scanC_kernel<<<256, 256, 0, s2>>>(N, E);
    scatter_kernel<<<1024, 256, 0, s2>>>(erow, ecol, eval_, E);
    cudaEventRecord(e2, s2);

    // s3: weight fold chain
    prep_kernel<<<128, 256, 0, s3>>>(cond, Wk, Wv, Wmu, Wvar);
    fold_kernel<<<256, 256, 0, s3>>>(Wq, Wo);
    pw_kernel<<<128, 256, 0, s3>>>();
    cudaEventRecord(e3, s3);

    // main stream: gemm1 (Wh split inline) -> fp16 supp1
    gemm1_kernel<<<gm, 512>>>(ns_emb, Wh, supp1, N);

    // spmm1 needs CSR only
    cudaStreamWaitEvent(0, e2, 0);
    csr_spmm_kernel<false><<<spmm_blocks, 256>>>(supp1, acc1, N);

    // fused needs folded weights
    cudaStreamWaitEvent(0, e3, 0);
    attn_fused_kernel<<<gm64, 256, SMEM_FUSED>>>(acc1, supp2, N);

    // out = leaky(spmm(supp2)) split into mu|var  (fp32 output)
    csr_spmm_kernel<true><<<spmm_blocks, 256>>>(supp2, (float*)d_out, N);

    cudaEventDestroy(e1);
    cudaEventDestroy(e2);
    cudaEventDestroy(e3);
    cudaStreamDestroy(s2);
    cudaStreamDestroy(s3);
}

// round 16
// speedup vs baseline: 1.3950x; 1.0114x over previous
#include <cuda_runtime.h>
#include <cuda_bf16.h>
#include <cuda_fp16.h>
#include <math.h>

#define NMAX 50000
#define EMAX 600000

// ---------------- scratch (device globals; no allocation allowed) ----------
__device__ __align__(16) __half g_supp1[NMAX * 128];   // fp16: halves gather BW
__device__ __align__(16) __half g_acc1 [NMAX * 128];   // fp16 now
__device__ __align__(16) __half g_supp2[NMAX * 128];   // fp16
__device__ __align__(16) float  g_Kb   [128 * 64];
__device__ __align__(16) float  g_Vb   [128 * 64];
__device__ __align__(16) float  g_Pc   [256 * 128];    // Pcat fp32 (pre-PW)
__device__ __align__(16) float  g_Wc   [128 * 128];    // Wcat fp32 (pre-PW)
// CSR build (g_cnt starts zeroed at module load; scanA re-zeros it each call)
__device__ int   g_cnt [NMAX];
__device__ int   g_off [NMAX + 1];
__device__ int   g_cur [NMAX];
__device__ int   g_bsum[256];
__device__ __align__(16) int   g_ecol[EMAX];
__device__ __align__(16) float g_eval[EMAX];
// pre-split bf16 weights (hi/lo)
__device__ __align__(16) __nv_bfloat16 g_Mh [128 * 256], g_Ml [128 * 256];
__device__ __align__(16) __nv_bfloat16 g_PWh[256 * 128], g_PWl[256 * 128];  // Pcat@Wcat

__device__ __forceinline__ float lrelu(float x) { return x > 0.f ? x : 0.01f * x; }

__device__ __forceinline__ void split_bf16(float x, __nv_bfloat16& h, __nv_bfloat16& l) {
    h = __float2bfloat16(x);
    l = __float2bfloat16(x - __bfloat162float(h));
}

__device__ __forceinline__ void mma_bf16(float* d, const unsigned* a, const unsigned* b) {
    asm volatile(
        "mma.sync.aligned.m16n8k16.row.col.f32.bf16.bf16.f32 "
        "{%0,%1,%2,%3}, {%4,%5,%6,%7}, {%8,%9}, {%0,%1,%2,%3};\n"
        : "+f"(d[0]), "+f"(d[1]), "+f"(d[2]), "+f"(d[3])
        : "r"(a[0]), "r"(a[1]), "r"(a[2]), "r"(a[3]), "r"(b[0]), "r"(b[1]));
}

__device__ __forceinline__ void ldsm_x4(unsigned* r, const __nv_bfloat16* p) {
    unsigned addr = (unsigned)__cvta_generic_to_shared(p);
    asm volatile("ldmatrix.sync.aligned.m8n8.x4.shared.b16 {%0,%1,%2,%3}, [%4];\n"
                 : "=r"(r[0]), "=r"(r[1]), "=r"(r[2]), "=r"(r[3]) : "r"(addr));
}

__device__ __forceinline__ void ldsm_x2t(unsigned* r, const __nv_bfloat16* p) {
    unsigned addr = (unsigned)__cvta_generic_to_shared(p);
    asm volatile("ldmatrix.sync.aligned.m8n8.x2.trans.shared.b16 {%0,%1}, [%2];\n"
                 : "=r"(r[0]), "=r"(r[1]) : "r"(addr));
}

// ---------------- prep: K/V projections + Wcat (fp32), 4-way ILP ------------
__global__ void prep_kernel(const float* __restrict__ cond,
                            const float* __restrict__ Wk,
                            const float* __restrict__ Wv,
                            const float* __restrict__ Wmu,
                            const float* __restrict__ Wvar) {
    int o = blockIdx.x * blockDim.x + threadIdx.x;  // 32768 threads
    if (o < 8192) {
        int key = o >> 6, d = o & 63;
        float s0 = 0.f, s1 = 0.f, s2 = 0.f, s3 = 0.f;
        #pragma unroll 8
        for (int m = 0; m < 128; m += 4) {
            s0 += cond[key * 128 + m + 0] * Wk[(m + 0) * 64 + d];
            s1 += cond[key * 128 + m + 1] * Wk[(m + 1) * 64 + d];
            s2 += cond[key * 128 + m + 2] * Wk[(m + 2) * 64 + d];
            s3 += cond[key * 128 + m + 3] * Wk[(m + 3) * 64 + d];
        }
        g_Kb[o] = (s0 + s1) + (s2 + s3);
    } else if (o < 16384) {
        int o2 = o - 8192;
        int key = o2 >> 6, d = o2 & 63;
        float s0 = 0.f, s1 = 0.f, s2 = 0.f, s3 = 0.f;
        #pragma unroll 8
        for (int m = 0; m < 128; m += 4) {
            s0 += cond[key * 128 + m + 0] * Wv[(m + 0) * 64 + d];
            s1 += cond[key * 128 + m + 1] * Wv[(m + 1) * 64 + d];
            s2 += cond[key * 128 + m + 2] * Wv[(m + 2) * 64 + d];
            s3 += cond[key * 128 + m + 3] * Wv[(m + 3) * 64 + d];
        }
        g_Vb[o2] = (s0 + s1) + (s2 + s3);
    } else {
        int i = o - 16384;  // 0..16383 = 128*128
        int k = i >> 7, n = i & 127;
        g_Wc[i] = (n < 64) ? Wmu[k * 64 + n] : Wvar[k * 64 + (n - 64)];
    }
}

// ---------------- fold heads: Mcat (split), Pcat (fp32) ---------------------
__global__ void fold_kernel(const float* __restrict__ Wq,
                            const float* __restrict__ Wo) {
    const float scale = 0.17677669529663687f;  // 1/sqrt(32)
    int o = blockIdx.x * blockDim.x + threadIdx.x;  // 65536
    if (o < 32768) {
        int c = o >> 8, hk = o & 255;
        int h = hk >> 7, key = hk & 127;
        float s0 = 0.f, s1 = 0.f, s2 = 0.f, s3 = 0.f;
        #pragma unroll
        for (int d = 0; d < 32; d += 4) {
            s0 += Wq[c * 64 + h * 32 + d + 0] * g_Kb[key * 64 + h * 32 + d + 0];
            s1 += Wq[c * 64 + h * 32 + d + 1] * g_Kb[key * 64 + h * 32 + d + 1];
            s2 += Wq[c * 64 + h * 32 + d + 2] * g_Kb[key * 64 + h * 32 + d + 2];
            s3 += Wq[c * 64 + h * 32 + d + 3] * g_Kb[key * 64 + h * 32 + d + 3];
        }
        split_bf16(((s0 + s1) + (s2 + s3)) * scale, g_Mh[o], g_Ml[o]);
    } else {
        int o2 = o - 32768;
        int hk = o2 >> 7, j = o2 & 127;
        int h = hk >> 7, key = hk & 127;
        float s0 = 0.f, s1 = 0.f, s2 = 0.f, s3 = 0.f;
        #pragma unroll
        for (int d = 0; d < 32; d += 4) {
            s0 += g_Vb[key * 64 + h * 32 + d + 0] * Wo[(h * 32 + d + 0) * 128 + j];
            s1 += g_Vb[key * 64 + h * 32 + d + 1] * Wo[(h * 32 + d + 1) * 128 + j];
            s2 += g_Vb[key * 64 + h * 32 + d + 2] * Wo[(h * 32 + d + 2) * 128 + j];
            s3 += g_Vb[key * 64 + h * 32 + d + 3] * Wo[(h * 32 + d + 3) * 128 + j];
        }
        g_Pc[o2] = (s0 + s1) + (s2 + s3);
    }
}

// ---------------- PW = Pcat @ Wcat  [256,128], split bf16, 4-way ILP --------
__global__ void pw_kernel() {
    int idx = blockIdx.x * blockDim.x + threadIdx.x;  // 32768
    int i = idx >> 7, j = idx & 127;
    float s0 = 0.f, s1 = 0.f, s2 = 0.f, s3 = 0.f;
    #pragma unroll 8
    for (int m = 0; m < 128; m += 4) {
        s0 += g_Pc[i * 128 + m + 0] * g_Wc[(m + 0) * 128 + j];
        s1 += g_Pc[i * 128 + m + 1] * g_Wc[(m + 1) * 128 + j];
        s2 += g_Pc[i * 128 + m + 2] * g_Wc[(m + 2) * 128 + j];
        s3 += g_Pc[i * 128 + m + 3] * g_Wc[(m + 3) * 128 + j];
    }
    split_bf16((s0 + s1) + (s2 + s3), g_PWh[idx], g_PWl[idx]);
}

// ---------------- CSR build -------------------------------------------------
__global__ void hist_kernel(const int* __restrict__ rows, int E) {
    int idx = blockIdx.x * blockDim.x + threadIdx.x;
    int stride = gridDim.x * blockDim.x;
    int E4 = E >> 2;
    const int4* rows4 = (const int4*)rows;
    for (int i = idx; i < E4; i += stride) {
        int4 r = rows4[i];
        atomicAdd(&g_cnt[r.x], 1);
        atomicAdd(&g_cnt[r.y], 1);
        atomicAdd(&g_cnt[r.z], 1);
        atomicAdd(&g_cnt[r.w], 1);
    }
    for (int i = (E4 << 2) + idx; i < E; i += stride) atomicAdd(&g_cnt[rows[i]], 1);
}

__global__ void scanA_kernel(int Nn) {
    __shared__ int s[256];
    int t = threadIdx.x, i = blockIdx.x * 256 + t;
    int v = (i < Nn) ? g_cnt[i] : 0;
    s[t] = v;
    __syncthreads();
    #pragma unroll
    for (int o = 1; o < 256; o <<= 1) {
        int x = (t >= o) ? s[t - o] : 0;
        __syncthreads();
        s[t] += x;
        __syncthreads();
    }
    if (i < Nn) {
        g_off[i] = s[t] - v;
        g_cnt[i] = 0;  // re-zero for next call (invariant across graph replays)
    }
    if (t == 255) g_bsum[blockIdx.x] = s[255];
}

// merged scanB+scanC: each block redundantly scans the <=256 chunk sums,
// applies its own chunk's exclusive prefix, and initializes cursors.
__global__ void scanBC_kernel(int Nn, int E, int nb) {
    __shared__ int s[256];
    __shared__ int boff;
    int t = threadIdx.x;
    int v = (t < nb) ? g_bsum[t] : 0;
    s[t] = v;
    __syncthreads();
    #pragma unroll
    for (int o = 1; o < 256; o <<= 1) {
        int x = (t >= o) ? s[t - o] : 0;
        __syncthreads();
        s[t] += x;
        __syncthreads();
    }
    if (t == blockIdx.x) boff = s[t] - v;  // exclusive prefix of this chunk
    __syncthreads();
    int i = blockIdx.x * 256 + t;
    if (i < Nn) {
        int o = g_off[i] + boff;
        g_off[i] = o;
        g_cur[i] = o;
    }
    if (blockIdx.x == 0 && t == 0) g_off[Nn] = E;
}

__global__ void scatter_kernel(const int* __restrict__ rows,
                               const int* __restrict__ cols,
                               const float* __restrict__ vals, int E) {
    int idx = blockIdx.x * blockDim.x + threadIdx.x;
    int stride = gridDim.x * blockDim.x;
    for (int i = idx; i < E; i += stride) {
        int r = rows[i];
        int p = atomicAdd(&g_cur[r], 1);
        g_ecol[p] = cols[i];
        g_eval[p] = vals[i];
    }
}

// ============================================================================
// GEMM1: supp1 = leaky(ns_emb[M,256] @ Wh[256,128]) -> fp16 output
// ============================================================================
__global__ void __launch_bounds__(512) gemm1_kernel(const float* __restrict__ A,
                                                    const float* __restrict__ Wg,
                                                    __half* __restrict__ C, int M) {
    constexpr int K = 256, NC = 128, LDA = 40, LDB = 136;
    __shared__ __nv_bfloat16 Ah[128][LDA], Al[128][LDA];
    __shared__ __nv_bfloat16 Bh[32][LDB], Bl[32][LDB];
    int tid = threadIdx.x;
    int warp = tid >> 5, lane = tid & 31;
    int wm = (warp & 3) * 32;
    int wn = (warp >> 2) * 32;
    int row0 = blockIdx.x * 128;
    int r_l = lane & 15, c_l = (lane >> 4) << 3;

    float acc[2][4][4];
    #pragma unroll
    for (int mi = 0; mi < 2; mi++)
        #pragma unroll
        for (int ni = 0; ni < 4; ni++)
            #pragma unroll
            for (int t = 0; t < 4; t++) acc[mi][ni][t] = 0.f;

    float4 pa[2], pb[2];

    auto loadA = [&](int k0) {
        #pragma unroll
        for (int i = 0; i < 2; i++) {
            int v = tid + i * 512;
            int row = v >> 3, q = (v & 7) << 2;
            int gr = row0 + row;
            pa[i] = make_float4(0.f, 0.f, 0.f, 0.f);
            if (gr < M) pa[i] = *(const float4*)(A + (size_t)gr * K + k0 + q);
        }
    };
    auto loadB = [&](int k0) {
        #pragma unroll
        for (int i = 0; i < 2; i++) {
            int v = tid + i * 512;
            int br = v >> 5, bc = (v & 31) << 2;
            pb[i] = *(const float4*)(Wg + (size_t)(k0 + br) * NC + bc);
        }
    };

    loadA(0);
    loadB(0);
    for (int it = 0; it < K / 32; it++) {
        #pragma unroll
        for (int i = 0; i < 2; i++) {
            int v = tid + i * 512;
            int row = v >> 3, q = (v & 7) << 2;
            split_bf16(pa[i].x, Ah[row][q + 0], Al[row][q + 0]);
            split_bf16(pa[i].y, Ah[row][q + 1], Al[row][q + 1]);
            split_bf16(pa[i].z, Ah[row][q + 2], Al[row][q + 2]);
            split_bf16(pa[i].w, Ah[row][q + 3], Al[row][q + 3]);
        }
        #pragma unroll
        for (int i = 0; i < 2; i++) {
            int v = tid + i * 512;
            int br = v >> 5, bc = (v & 31) << 2;
            split_bf16(pb[i].x, Bh[br][bc + 0], Bl[br][bc + 0]);
            split_bf16(pb[i].y, Bh[br][bc + 1], Bl[br][bc + 1]);
            split_bf16(pb[i].z, Bh[br][bc + 2], Bl[br][bc + 2]);
            split_bf16(pb[i].w, Bh[br][bc + 3], Bl[br][bc + 3]);
        }
        __syncthreads();
        if (it < K / 32 - 1) {
            loadA((it + 1) * 32);
            loadB((it + 1) * 32);
        }
        #pragma unroll
        for (int s = 0; s < 2; s++) {
            int ks = s * 16;
            unsigned afh[2][4], afl[2][4];
            #pragma unroll
            for (int mi = 0; mi < 2; mi++) {
                ldsm_x4(afh[mi], &Ah[wm + mi * 16 + r_l][ks + c_l]);
                ldsm_x4(afl[mi], &Al[wm + mi * 16 + r_l][ks + c_l]);
            }
            #pragma unroll
            for (int ni = 0; ni < 4; ni++) {
                unsigned bfh[2], bfl[2];
                ldsm_x2t(bfh, &Bh[ks + r_l][wn + ni * 8]);
                ldsm_x2t(bfl, &Bl[ks + r_l][wn + ni * 8]);
                #pragma unroll
                for (int mi = 0; mi < 2; mi++) {
                    mma_bf16(acc[mi][ni], afh[mi], bfh);
                    mma_bf16(acc[mi][ni], afh[mi], bfl);
                    mma_bf16(acc[mi][ni], afl[mi], bfh);
                }
            }
        }
        __syncthreads();
    }
    #pragma unroll
    for (int mi = 0; mi < 2; mi++)
        #pragma unroll
        for (int ni = 0; ni < 4; ni++) {
            int r = row0 + wm + mi * 16 + (lane >> 2);
            int c = wn + ni * 8 + (lane & 3) * 2;
            float v0 = lrelu(acc[mi][ni][0]), v1 = lrelu(acc[mi][ni][1]);
            float v2 = lrelu(acc[mi][ni][2]), v3 = lrelu(acc[mi][ni][3]);
            if (r < M)
                *(__half2*)(C + (size_t)r * NC + c) = __floats2half2_rn(v0, v1);
            if (r + 8 < M)
                *(__half2*)(C + (size_t)(r + 8) * NC + c) = __floats2half2_rn(v2, v3);
        }
}

// ============================================================================
// FUSED: supp2 = leaky( softmax( leaky(acc1)@Mcat ) @ PW ) -> fp16
// 64-row tiles, 2 CTAs/SM. Register prefetch on GEMM3 B tiles. acc1 is fp16.
// ============================================================================
#define SMEM_FUSED 103424

__global__ void __launch_bounds__(256, 2) attn_fused_kernel(const __half* __restrict__ ACC1,
                                                            __half* __restrict__ OUT, int M) {
    extern __shared__ char smem_raw[];
    __nv_bfloat16* Sh = (__nv_bfloat16*)smem_raw;               // [64][264]
    __nv_bfloat16* Sl = Sh + 64 * 264;
    __nv_bfloat16* Bh = (__nv_bfloat16*)(smem_raw + 67584);     // [32][264]
    __nv_bfloat16* Bl = Bh + 32 * 264;
    float* smax = (float*)(smem_raw + 101376);                  // [64][4]
    float* ssum = smax + 256;
    __nv_bfloat16* Xh = Sh;                                     // overlay [64][136]
    __nv_bfloat16* Xl = Sh + 64 * 136;

    int tid = threadIdx.x;
    int warp = tid >> 5, lane = tid & 31;
    int wm = (warp >> 2) * 32;
    int wc = warp & 3;
    int row0 = blockIdx.x * 64;
    int r_l = lane & 15, c_l = (lane >> 4) << 3;

    // ---------- load X = leaky(acc1 tile, fp16), split bf16 ----------
    #pragma unroll
    for (int i = 0; i < 8; i++) {
        int v = tid + i * 256;
        int row = v >> 5, q = (v & 31) << 2;
        int gr = row0 + row;
        float4 a4 = make_float4(0.f, 0.f, 0.f, 0.f);
        if (gr < M) {
            uint2 raw = *(const uint2*)(ACC1 + (size_t)gr * 128 + q);
            float2 f0 = __half22float2(*(__half2*)&raw.x);
            float2 f1 = __half22float2(*(__half2*)&raw.y);
            a4 = make_float4(f0.x, f0.y, f1.x, f1.y);
        }
        a4.x = lrelu(a4.x); a4.y = lrelu(a4.y);
        a4.z = lrelu(a4.z); a4.w = lrelu(a4.w);
        split_bf16(a4.x, Xh[row * 136 + q + 0], Xl[row * 136 + q + 0]);
        split_bf16(a4.y, Xh[row * 136 + q + 1], Xl[row * 136 + q + 1]);
        split_bf16(a4.z, Xh[row * 136 + q + 2], Xl[row * 136 + q + 2]);
        split_bf16(a4.w, Xh[row * 136 + q + 3], Xl[row * 136 + q + 3]);
    }
    __syncthreads();

    // GEMM2: L = X @ Mcat   (64x256, K=128)
    int wn2 = wc * 64;
    float accA[2][8][4];
    #pragma unroll
    for (int mi = 0; mi < 2; mi++)
        #pragma unroll
        for (int ni = 0; ni < 8; ni++)
            #pragma unroll
            for (int t = 0; t < 4; t++) accA[mi][ni][t] = 0.f;

    for (int it = 0; it < 4; it++) {
        int k0 = it * 32;
        #pragma unroll
        for (int i = 0; i < 4; i++) {
            int s = tid + i * 256;
            int br = s >> 5, bc = (s & 31) << 3;
            *(uint4*)&Bh[br * 264 + bc] = *(const uint4*)(g_Mh + (size_t)(k0 + br) * 256 + bc);
            *(uint4*)&Bl[br * 264 + bc] = *(const uint4*)(g_Ml + (size_t)(k0 + br) * 256 + bc);
        }
        __syncthreads();
        #pragma unroll
        for (int s = 0; s < 2; s++) {
            int ks = k0 + s * 16;
            unsigned afh[2][4], afl[2][4];
            #pragma unroll
            for (int mi = 0; mi < 2; mi++) {
                ldsm_x4(afh[mi], &Xh[(wm + mi * 16 + r_l) * 136 + ks + c_l]);
                ldsm_x4(afl[mi], &Xl[(wm + mi * 16 + r_l) * 136 + ks + c_l]);
            }
            #pragma unroll
            for (int ni = 0; ni < 8; ni++) {
                unsigned bfh[2], bfl[2];
                ldsm_x2t(bfh, &Bh[(s * 16 + r_l) * 264 + wn2 + ni * 8]);
                ldsm_x2t(bfl, &Bl[(s * 16 + r_l) * 264 + wn2 + ni * 8]);
                #pragma unroll
                for (int mi = 0; mi < 2; mi++) {
                    mma_bf16(accA[mi][ni], afh[mi], bfh);
                    mma_bf16(accA[mi][ni], afh[mi], bfl);
                    mma_bf16(accA[mi][ni], afl[mi], bfh);
                }
            }
        }
        __syncthreads();
    }

    // softmax
    int hbase = (wc >> 1) << 1;
    #pragma unroll
    for (int mi = 0; mi < 2; mi++)
        #pragma unroll
        for (int half = 0; half < 2; half++) {
            float m = -1e30f;
            #pragma unroll
            for (int ni = 0; ni < 8; ni++)
                m = fmaxf(m, fmaxf(accA[mi][ni][2 * half], accA[mi][ni][2 * half + 1]));
            m = fmaxf(m, __shfl_xor_sync(0xffffffffu, m, 1));
            m = fmaxf(m, __shfl_xor_sync(0xffffffffu, m, 2));
            if ((lane & 3) == 0) {
                int rowg = wm + mi * 16 + (lane >> 2) + 8 * half;
                smax[rowg * 4 + wc] = m;
            }
        }
    __syncthreads();
    #pragma unroll
    for (int mi = 0; mi < 2; mi++)
        #pragma unroll
        for (int half = 0; half < 2; half++) {
            int rowg = wm + mi * 16 + (lane >> 2) + 8 * half;
            float mh = fmaxf(smax[rowg * 4 + hbase], smax[rowg * 4 + hbase + 1]);
            float s = 0.f;
            #pragma unroll
            for (int ni = 0; ni < 8; ni++) {
                float e0 = __expf(accA[mi][ni][2 * half] - mh);
                float e1 = __expf(accA[mi][ni][2 * half + 1] - mh);
                accA[mi][ni][2 * half] = e0;
                accA[mi][ni][2 * half + 1] = e1;
                s += e0 + e1;
            }
            s += __shfl_xor_sync(0xffffffffu, s, 1);
            s += __shfl_xor_sync(0xffffffffu, s, 2);
            if ((lane & 3) == 0) ssum[rowg * 4 + wc] = s;
        }
    __syncthreads();
    #pragma unroll
    for (int mi = 0; mi < 2; mi++)
        #pragma unroll
        for (int half = 0; half < 2; half++) {
            int rowg = wm + mi * 16 + (lane >> 2) + 8 * half;
            float inv = 1.f / (ssum[rowg * 4 + hbase] + ssum[rowg * 4 + hbase + 1]);
            #pragma unroll
            for (int ni = 0; ni < 8; ni++) {
                float w0 = accA[mi][ni][2 * half] * inv;
                float w1 = accA[mi][ni][2 * half + 1] * inv;
                int colg = wn2 + ni * 8 + 2 * (lane & 3);
                __nv_bfloat16 h0, l0, h1, l1;
                split_bf16(w0, h0, l0);
                split_bf16(w1, h1, l1);
                *(__nv_bfloat162*)&Sh[rowg * 264 + colg] = __nv_bfloat162(h0, h1);
                *(__nv_bfloat162*)&Sl[rowg * 264 + colg] = __nv_bfloat162(l0, l1);
            }
        }
    __syncthreads();

    // GEMM3: supp2 = leaky(S @ PW)   (64x128, K=256)  [register prefetch on B]
    int wn3 = wc * 32;
    int brw = tid >> 4, bcw = (tid & 15) << 3;
    float acc3[2][4][4];
    #pragma unroll
    for (int mi = 0; mi < 2; mi++)
        #pragma unroll
        for (int ni = 0; ni < 4; ni++)
            #pragma unroll
            for (int t = 0; t < 4; t++) acc3[mi][ni][t] = 0.f;

    uint4 pph[2], ppl[2];
    auto loadP = [&](int k0) {
        #pragma unroll
        for (int i = 0; i < 2; i++) {
            int br = brw + i * 16;
            pph[i] = *(const uint4*)(g_PWh + (size_t)(k0 + br) * 128 + bcw);
            ppl[i] = *(const uint4*)(g_PWl + (size_t)(k0 + br) * 128 + bcw);
        }
    };

    loadP(0);
    for (int it = 0; it < 8; it++) {
        #pragma unroll
        for (int i = 0; i < 2; i++) {
            int br = brw + i * 16;
            *(uint4*)&Bh[br * 264 + bcw] = pph[i];
            *(uint4*)&Bl[br * 264 + bcw] = ppl[i];
        }
        __syncthreads();
        if (it < 7) loadP((it + 1) * 32);
        #pragma unroll
        for (int s = 0; s < 2; s++) {
            int ks = it * 32 + s * 16;
            unsigned afh[2][4], afl[2][4];
            #pragma unroll
            for (int mi = 0; mi < 2; mi++) {
                ldsm_x4(afh[mi], &Sh[(wm + mi * 16 + r_l) * 264 + ks + c_l]);
                ldsm_x4(afl[mi], &Sl[(wm + mi * 16 + r_l) * 264 + ks + c_l]);
            }
            #pragma unroll
            for (int ni = 0; ni < 4; ni++) {
                unsigned bfh[2], bfl[2];
                ldsm_x2t(bfh, &Bh[(s * 16 + r_l) * 264 + wn3 + ni * 8]);
                ldsm_x2t(bfl, &Bl[(s * 16 + r_l) * 264 + wn3 + ni * 8]);
                #pragma unroll
                for (int mi = 0; mi < 2; mi++) {
                    mma_bf16(acc3[mi][ni], afh[mi], bfh);
                    mma_bf16(acc3[mi][ni], afh[mi], bfl);
                    mma_bf16(acc3[mi][ni], afl[mi], bfh);
                }
            }
        }
        __syncthreads();
    }

    // epilogue: leaky + fp16 store
    #pragma unroll
    for (int mi = 0; mi < 2; mi++)
        #pragma unroll
        for (int ni = 0; ni < 4; ni++) {
            int r = row0 + wm + mi * 16 + (lane >> 2);
            int c = wn3 + ni * 8 + (lane & 3) * 2;
            float v0 = lrelu(acc3[mi][ni][0]), v1 = lrelu(acc3[mi][ni][1]);
            float v2 = lrelu(acc3[mi][ni][2]), v3 = lrelu(acc3[mi][ni][3]);
            if (r < M)
                *(__half2*)(OUT + (size_t)r * 128 + c) = __floats2half2_rn(v0, v1);
            if (r + 8 < M)
                *(__half2*)(OUT + (size_t)(r + 8) * 128 + c) = __floats2half2_rn(v2, v3);
        }
}

// ---------------- CSR SpMM: warp per row, fp16 gather, fp32 accum ----------
// FINAL=false: writes fp16 (acc1); FINAL=true: writes fp32 mu|var to d_out.
template <bool FINAL>
__global__ void __launch_bounds__(256) csr_spmm_kernel(const __half* __restrict__ x,
                                                       void* __restrict__ outv, int Nn) {
    int w = (blockIdx.x * blockDim.x + threadIdx.x) >> 5;
    int lane = threadIdx.x & 31;
    if (w >= Nn) return;
    int s = g_off[w], e = g_off[w + 1];
    float4 acc = make_float4(0.f, 0.f, 0.f, 0.f);
    for (int base = s; base < e; base += 32) {
        int idx = base + lane;
        int c = 0;
        float v = 0.f;
        if (idx < e) {
            c = g_ecol[idx];
            v = g_eval[idx];
        }
        int n = min(32, e - base);
        for (int j = 0; j < n; j++) {
            int cj = __shfl_sync(0xffffffffu, c, j);
            float vj = __shfl_sync(0xffffffffu, v, j);
            uint2 raw = *(const uint2*)(x + (size_t)cj * 128 + lane * 4);
            float2 f0 = __half22float2(*(__half2*)&raw.x);
            float2 f1 = __half22float2(*(__half2*)&raw.y);
            acc.x += vj * f0.x;
            acc.y += vj * f0.y;
            acc.z += vj * f1.x;
            acc.w += vj * f1.y;
        }
    }
    if (FINAL) {
        float* out = (float*)outv;
        acc.x = lrelu(acc.x); acc.y = lrelu(acc.y);
        acc.z = lrelu(acc.z); acc.w = lrelu(acc.w);
        if (lane < 16)
            *(float4*)(out + (size_t)w * 64 + lane * 4) = acc;
        else
            *(float4*)(out + (size_t)Nn * 64 + (size_t)w * 64 + (lane - 16) * 4) = acc;
    } else {
        __half* out = (__half*)outv;
        __half2 p0 = __floats2half2_rn(acc.x, acc.y);
        __half2 p1 = __floats2half2_rn(acc.z, acc.w);
        uint2 packed;
        packed.x = *(unsigned*)&p0;
        packed.y = *(unsigned*)&p1;
        *(uint2*)(out + (size_t)w * 128 + lane * 4) = packed;
    }
}

// ---------------------------------------------------------------------------
extern "C" void kernel_launch(void* const* d_in, const int* in_sizes, int n_in,
                              void* d_out, int out_size) {
    const float* ns_emb = (const float*)d_in[0];
    const int* erow = (const int*)d_in[1];
    const int* ecol = (const int*)d_in[2];
    const float* eval_ = (const float*)d_in[3];
    const float* cond = (const float*)d_in[4];
    const float* Wh = (const float*)d_in[5];
    const float* Wmu = (const float*)d_in[6];
    const float* Wvar = (const float*)d_in[7];
    const float* Wq = (const float*)d_in[8];
    const float* Wk = (const float*)d_in[9];
    const float* Wv = (const float*)d_in[10];
    const float* Wo = (const float*)d_in[11];

    int N = in_sizes[0] / 256;
    int E = in_sizes[1];

    __half *supp1, *acc1, *supp2;
    cudaGetSymbolAddress((void**)&supp1, g_supp1);
    cudaGetSymbolAddress((void**)&acc1, g_acc1);
    cudaGetSymbolAddress((void**)&supp2, g_supp2);

    cudaFuncSetAttribute(attn_fused_kernel,
                         cudaFuncAttributeMaxDynamicSharedMemorySize, SMEM_FUSED);

    int gm = (N + 127) / 128;
    int gm64 = (N + 63) / 64;
    int nchunks = (N + 255) / 256;
    int spmm_blocks = (N * 32 + 255) / 256;

    // ---- fork two side streams: s2 = CSR build, s3 = weight folds ---------
    cudaStream_t s2, s3;
    cudaStreamCreate(&s2);
    cudaStreamCreate(&s3);
    cudaEvent_t e1, e2, e3;
    cudaEventCreateWithFlags(&e1, cudaEventDisableTiming);
    cudaEventCreateWithFlags(&e2, cudaEventDisableTiming);
    cudaEventCreateWithFlags(&e3, cudaEventDisableTiming);

    cudaEventRecord(e1, 0);
    cudaStreamWaitEvent(s2, e1, 0);
    cudaStreamWaitEvent(s3, e1, 0);

    // s2: CSR build chain (g_cnt is zero on entry; scanA re-zeros)
    hist_kernel<<<1024, 256, 0, s2>>>(erow, E);
    scanA_kernel<<<nchunks, 256, 0, s2>>>(N);
    scanBC_kernel<<<nchunks, 256, 0, s2>>>(N, E, nchunks);
    scatter_kernel<<<1024, 256, 0, s2>>>(erow, ecol, eval_, E);
    cudaEventRecord(e2, s2);

    // s3: weight fold chain
    prep_kernel<<<128, 256, 0, s3>>>(cond, Wk, Wv, Wmu, Wvar);
    fold_kernel<<<256, 256, 0, s3>>>(Wq, Wo);
    pw_kernel<<<128, 256, 0, s3>>>();
    cudaEventRecord(e3, s3);

    // main stream: gemm1 (Wh split inline) -> fp16 supp1
    gemm1_kernel<<<gm, 512>>>(ns_emb, Wh, supp1, N);

    // spmm1 needs CSR only
    cudaStreamWaitEvent(0, e2, 0);
    csr_spmm_kernel<false><<<spmm_blocks, 256>>>(supp1, acc1, N);

    // fused needs folded weights
    cudaStreamWaitEvent(0, e3, 0);
    attn_fused_kernel<<<gm64, 256, SMEM_FUSED>>>(acc1, supp2, N);

    // out = leaky(spmm(supp2)) split into mu|var  (fp32 output)
    csr_spmm_kernel<true><<<spmm_blocks, 256>>>(supp2, (float*)d_out, N);

    cudaEventDestroy(e1);
    cudaEventDestroy(e2);
    cudaEventDestroy(e3);
    cudaStreamDestroy(s2);
    cudaStreamDestroy(s3);
}

// round 17
// speedup vs baseline: 1.4122x; 1.0123x over previous
#include <cuda_runtime.h>
#include <cuda_bf16.h>
#include <cuda_fp16.h>
#include <math.h>

#define NMAX 50000
#define EMAX 600000

// ---------------- scratch (device globals; no allocation allowed) ----------
__device__ __align__(16) __half g_supp1[NMAX * 128];   // fp16: halves gather BW
__device__ __align__(16) __half g_acc1 [NMAX * 128];   // fp16
__device__ __align__(16) __half g_supp2[NMAX * 128];   // fp16
__device__ __align__(16) float  g_Kb   [128 * 64];
__device__ __align__(16) float  g_Vb   [128 * 64];
__device__ __align__(16) float  g_Pc   [256 * 128];    // Pcat fp32 (pre-PW)
__device__ __align__(16) float  g_Wc   [128 * 128];    // Wcat fp32 (pre-PW)
// CSR build (g_cnt starts zeroed at module load; scanA re-zeros it each call)
__device__ int   g_cnt [NMAX];
__device__ int   g_off [NMAX + 1];
__device__ int   g_cur [NMAX];
__device__ int   g_bsum[256];
__device__ __align__(16) int2  g_edge[EMAX];           // packed (col, val-bits)
// pre-split bf16 weights (hi/lo)
__device__ __align__(16) __nv_bfloat16 g_Mh [128 * 256], g_Ml [128 * 256];
__device__ __align__(16) __nv_bfloat16 g_PWh[256 * 128], g_PWl[256 * 128];  // Pcat@Wcat

__device__ __forceinline__ float lrelu(float x) { return x > 0.f ? x : 0.01f * x; }

__device__ __forceinline__ void split_bf16(float x, __nv_bfloat16& h, __nv_bfloat16& l) {
    h = __float2bfloat16(x);
    l = __float2bfloat16(x - __bfloat162float(h));
}

__device__ __forceinline__ void mma_bf16(float* d, const unsigned* a, const unsigned* b) {
    asm volatile(
        "mma.sync.aligned.m16n8k16.row.col.f32.bf16.bf16.f32 "
        "{%0,%1,%2,%3}, {%4,%5,%6,%7}, {%8,%9}, {%0,%1,%2,%3};\n"
        : "+f"(d[0]), "+f"(d[1]), "+f"(d[2]), "+f"(d[3])
        : "r"(a[0]), "r"(a[1]), "r"(a[2]), "r"(a[3]), "r"(b[0]), "r"(b[1]));
}

__device__ __forceinline__ void ldsm_x4(unsigned* r, const __nv_bfloat16* p) {
    unsigned addr = (unsigned)__cvta_generic_to_shared(p);
    asm volatile("ldmatrix.sync.aligned.m8n8.x4.shared.b16 {%0,%1,%2,%3}, [%4];\n"
                 : "=r"(r[0]), "=r"(r[1]), "=r"(r[2]), "=r"(r[3]) : "r"(addr));
}

__device__ __forceinline__ void ldsm_x2t(unsigned* r, const __nv_bfloat16* p) {
    unsigned addr = (unsigned)__cvta_generic_to_shared(p);
    asm volatile("ldmatrix.sync.aligned.m8n8.x2.trans.shared.b16 {%0,%1}, [%2];\n"
                 : "=r"(r[0]), "=r"(r[1]) : "r"(addr));
}

// ---------------- prep: K/V projections + Wcat (fp32), 4-way ILP ------------
__global__ void prep_kernel(const float* __restrict__ cond,
                            const float* __restrict__ Wk,
                            const float* __restrict__ Wv,
                            const float* __restrict__ Wmu,
                            const float* __restrict__ Wvar) {
    int o = blockIdx.x * blockDim.x + threadIdx.x;  // 32768 threads
    if (o < 8192) {
        int key = o >> 6, d = o & 63;
        float s0 = 0.f, s1 = 0.f, s2 = 0.f, s3 = 0.f;
        #pragma unroll 8
        for (int m = 0; m < 128; m += 4) {
            s0 += cond[key * 128 + m + 0] * Wk[(m + 0) * 64 + d];
            s1 += cond[key * 128 + m + 1] * Wk[(m + 1) * 64 + d];
            s2 += cond[key * 128 + m + 2] * Wk[(m + 2) * 64 + d];
            s3 += cond[key * 128 + m + 3] * Wk[(m + 3) * 64 + d];
        }
        g_Kb[o] = (s0 + s1) + (s2 + s3);
    } else if (o < 16384) {
        int o2 = o - 8192;
        int key = o2 >> 6, d = o2 & 63;
        float s0 = 0.f, s1 = 0.f, s2 = 0.f, s3 = 0.f;
        #pragma unroll 8
        for (int m = 0; m < 128; m += 4) {
            s0 += cond[key * 128 + m + 0] * Wv[(m + 0) * 64 + d];
            s1 += cond[key * 128 + m + 1] * Wv[(m + 1) * 64 + d];
            s2 += cond[key * 128 + m + 2] * Wv[(m + 2) * 64 + d];
            s3 += cond[key * 128 + m + 3] * Wv[(m + 3) * 64 + d];
        }
        g_Vb[o2] = (s0 + s1) + (s2 + s3);
    } else {
        int i = o - 16384;  // 0..16383 = 128*128
        int k = i >> 7, n = i & 127;
        g_Wc[i] = (n < 64) ? Wmu[k * 64 + n] : Wvar[k * 64 + (n - 64)];
    }
}

// ---------------- fold heads: Mcat (split), Pcat (fp32) ---------------------
__global__ void fold_kernel(const float* __restrict__ Wq,
                            const float* __restrict__ Wo) {
    const float scale = 0.17677669529663687f;  // 1/sqrt(32)
    int o = blockIdx.x * blockDim.x + threadIdx.x;  // 65536
    if (o < 32768) {
        int c = o >> 8, hk = o & 255;
        int h = hk >> 7, key = hk & 127;
        float s0 = 0.f, s1 = 0.f, s2 = 0.f, s3 = 0.f;
        #pragma unroll
        for (int d = 0; d < 32; d += 4) {
            s0 += Wq[c * 64 + h * 32 + d + 0] * g_Kb[key * 64 + h * 32 + d + 0];
            s1 += Wq[c * 64 + h * 32 + d + 1] * g_Kb[key * 64 + h * 32 + d + 1];
            s2 += Wq[c * 64 + h * 32 + d + 2] * g_Kb[key * 64 + h * 32 + d + 2];
            s3 += Wq[c * 64 + h * 32 + d + 3] * g_Kb[key * 64 + h * 32 + d + 3];
        }
        split_bf16(((s0 + s1) + (s2 + s3)) * scale, g_Mh[o], g_Ml[o]);
    } else {
        int o2 = o - 32768;
        int hk = o2 >> 7, j = o2 & 127;
        int h = hk >> 7, key = hk & 127;
        float s0 = 0.f, s1 = 0.f, s2 = 0.f, s3 = 0.f;
        #pragma unroll
        for (int d = 0; d < 32; d += 4) {
            s0 += g_Vb[key * 64 + h * 32 + d + 0] * Wo[(h * 32 + d + 0) * 128 + j];
            s1 += g_Vb[key * 64 + h * 32 + d + 1] * Wo[(h * 32 + d + 1) * 128 + j];
            s2 += g_Vb[key * 64 + h * 32 + d + 2] * Wo[(h * 32 + d + 2) * 128 + j];
            s3 += g_Vb[key * 64 + h * 32 + d + 3] * Wo[(h * 32 + d + 3) * 128 + j];
        }
        g_Pc[o2] = (s0 + s1) + (s2 + s3);
    }
}

// ---------------- PW = Pcat @ Wcat  [256,128], split bf16, 4-way ILP --------
__global__ void pw_kernel() {
    int idx = blockIdx.x * blockDim.x + threadIdx.x;  // 32768
    int i = idx >> 7, j = idx & 127;
    float s0 = 0.f, s1 = 0.f, s2 = 0.f, s3 = 0.f;
    #pragma unroll 8
    for (int m = 0; m < 128; m += 4) {
        s0 += g_Pc[i * 128 + m + 0] * g_Wc[(m + 0) * 128 + j];
        s1 += g_Pc[i * 128 + m + 1] * g_Wc[(m + 1) * 128 + j];
        s2 += g_Pc[i * 128 + m + 2] * g_Wc[(m + 2) * 128 + j];
        s3 += g_Pc[i * 128 + m + 3] * g_Wc[(m + 3) * 128 + j];
    }
    split_bf16((s0 + s1) + (s2 + s3), g_PWh[idx], g_PWl[idx]);
}

// ---------------- CSR build -------------------------------------------------
__global__ void hist_kernel(const int* __restrict__ rows, int E) {
    int idx = blockIdx.x * blockDim.x + threadIdx.x;
    int stride = gridDim.x * blockDim.x;
    int E4 = E >> 2;
    const int4* rows4 = (const int4*)rows;
    for (int i = idx; i < E4; i += stride) {
        int4 r = rows4[i];
        atomicAdd(&g_cnt[r.x], 1);
        atomicAdd(&g_cnt[r.y], 1);
        atomicAdd(&g_cnt[r.z], 1);
        atomicAdd(&g_cnt[r.w], 1);
    }
    for (int i = (E4 << 2) + idx; i < E; i += stride) atomicAdd(&g_cnt[rows[i]], 1);
}

__global__ void scanA_kernel(int Nn) {
    __shared__ int s[256];
    int t = threadIdx.x, i = blockIdx.x * 256 + t;
    int v = (i < Nn) ? g_cnt[i] : 0;
    s[t] = v;
    __syncthreads();
    #pragma unroll
    for (int o = 1; o < 256; o <<= 1) {
        int x = (t >= o) ? s[t - o] : 0;
        __syncthreads();
        s[t] += x;
        __syncthreads();
    }
    if (i < Nn) {
        g_off[i] = s[t] - v;
        g_cnt[i] = 0;  // re-zero for next call (invariant across graph replays)
    }
    if (t == 255) g_bsum[blockIdx.x] = s[255];
}

// merged scanB+scanC
__global__ void scanBC_kernel(int Nn, int E, int nb) {
    __shared__ int s[256];
    __shared__ int boff;
    int t = threadIdx.x;
    int v = (t < nb) ? g_bsum[t] : 0;
    s[t] = v;
    __syncthreads();
    #pragma unroll
    for (int o = 1; o < 256; o <<= 1) {
        int x = (t >= o) ? s[t - o] : 0;
        __syncthreads();
        s[t] += x;
        __syncthreads();
    }
    if (t == blockIdx.x) boff = s[t] - v;
    __syncthreads();
    int i = blockIdx.x * 256 + t;
    if (i < Nn) {
        int o = g_off[i] + boff;
        g_off[i] = o;
        g_cur[i] = o;
    }
    if (blockIdx.x == 0 && t == 0) g_off[Nn] = E;
}

__global__ void scatter_kernel(const int* __restrict__ rows,
                               const int* __restrict__ cols,
                               const float* __restrict__ vals, int E) {
    int idx = blockIdx.x * blockDim.x + threadIdx.x;
    int stride = gridDim.x * blockDim.x;
    for (int i = idx; i < E; i += stride) {
        int r = rows[i];
        int p = atomicAdd(&g_cur[r], 1);
        int2 e;
        e.x = cols[i];
        e.y = __float_as_int(vals[i]);
        g_edge[p] = e;  // single 8B store
    }
}

// ============================================================================
// GEMM1: supp1 = leaky(ns_emb[M,256] @ Wh[256,128]) -> fp16 output
// ============================================================================
__global__ void __launch_bounds__(512) gemm1_kernel(const float* __restrict__ A,
                                                    const float* __restrict__ Wg,
                                                    __half* __restrict__ C, int M) {
    constexpr int K = 256, NC = 128, LDA = 40, LDB = 136;
    __shared__ __nv_bfloat16 Ah[128][LDA], Al[128][LDA];
    __shared__ __nv_bfloat16 Bh[32][LDB], Bl[32][LDB];
    int tid = threadIdx.x;
    int warp = tid >> 5, lane = tid & 31;
    int wm = (warp & 3) * 32;
    int wn = (warp >> 2) * 32;
    int row0 = blockIdx.x * 128;
    int r_l = lane & 15, c_l = (lane >> 4) << 3;

    float acc[2][4][4];
    #pragma unroll
    for (int mi = 0; mi < 2; mi++)
        #pragma unroll
        for (int ni = 0; ni < 4; ni++)
            #pragma unroll
            for (int t = 0; t < 4; t++) acc[mi][ni][t] = 0.f;

    float4 pa[2], pb[2];

    auto loadA = [&](int k0) {
        #pragma unroll
        for (int i = 0; i < 2; i++) {
            int v = tid + i * 512;
            int row = v >> 3, q = (v & 7) << 2;
            int gr = row0 + row;
            pa[i] = make_float4(0.f, 0.f, 0.f, 0.f);
            if (gr < M) pa[i] = *(const float4*)(A + (size_t)gr * K + k0 + q);
        }
    };
    auto loadB = [&](int k0) {
        #pragma unroll
        for (int i = 0; i < 2; i++) {
            int v = tid + i * 512;
            int br = v >> 5, bc = (v & 31) << 2;
            pb[i] = *(const float4*)(Wg + (size_t)(k0 + br) * NC + bc);
        }
    };

    loadA(0);
    loadB(0);
    for (int it = 0; it < K / 32; it++) {
        #pragma unroll
        for (int i = 0; i < 2; i++) {
            int v = tid + i * 512;
            int row = v >> 3, q = (v & 7) << 2;
            split_bf16(pa[i].x, Ah[row][q + 0], Al[row][q + 0]);
            split_bf16(pa[i].y, Ah[row][q + 1], Al[row][q + 1]);
            split_bf16(pa[i].z, Ah[row][q + 2], Al[row][q + 2]);
            split_bf16(pa[i].w, Ah[row][q + 3], Al[row][q + 3]);
        }
        #pragma unroll
        for (int i = 0; i < 2; i++) {
            int v = tid + i * 512;
            int br = v >> 5, bc = (v & 31) << 2;
            split_bf16(pb[i].x, Bh[br][bc + 0], Bl[br][bc + 0]);
            split_bf16(pb[i].y, Bh[br][bc + 1], Bl[br][bc + 1]);
            split_bf16(pb[i].z, Bh[br][bc + 2], Bl[br][bc + 2]);
            split_bf16(pb[i].w, Bh[br][bc + 3], Bl[br][bc + 3]);
        }
        __syncthreads();
        if (it < K / 32 - 1) {
            loadA((it + 1) * 32);
            loadB((it + 1) * 32);
        }
        #pragma unroll
        for (int s = 0; s < 2; s++) {
            int ks = s * 16;
            unsigned afh[2][4], afl[2][4];
            #pragma unroll
            for (int mi = 0; mi < 2; mi++) {
                ldsm_x4(afh[mi], &Ah[wm + mi * 16 + r_l][ks + c_l]);
                ldsm_x4(afl[mi], &Al[wm + mi * 16 + r_l][ks + c_l]);
            }
            #pragma unroll
            for (int ni = 0; ni < 4; ni++) {
                unsigned bfh[2], bfl[2];
                ldsm_x2t(bfh, &Bh[ks + r_l][wn + ni * 8]);
                ldsm_x2t(bfl, &Bl[ks + r_l][wn + ni * 8]);
                #pragma unroll
                for (int mi = 0; mi < 2; mi++) {
                    mma_bf16(acc[mi][ni], afh[mi], bfh);
                    mma_bf16(acc[mi][ni], afh[mi], bfl);
                    mma_bf16(acc[mi][ni], afl[mi], bfh);
                }
            }
        }
        __syncthreads();
    }
    #pragma unroll
    for (int mi = 0; mi < 2; mi++)
        #pragma unroll
        for (int ni = 0; ni < 4; ni++) {
            int r = row0 + wm + mi * 16 + (lane >> 2);
            int c = wn + ni * 8 + (lane & 3) * 2;
            float v0 = lrelu(acc[mi][ni][0]), v1 = lrelu(acc[mi][ni][1]);
            float v2 = lrelu(acc[mi][ni][2]), v3 = lrelu(acc[mi][ni][3]);
            if (r < M)
                *(__half2*)(C + (size_t)r * NC + c) = __floats2half2_rn(v0, v1);
            if (r + 8 < M)
                *(__half2*)(C + (size_t)(r + 8) * NC + c) = __floats2half2_rn(v2, v3);
        }
}

// ============================================================================
// FUSED: supp2 = leaky( softmax( leaky(acc1)@Mcat ) @ PW ) -> fp16
// ============================================================================
#define SMEM_FUSED 103424

__global__ void __launch_bounds__(256, 2) attn_fused_kernel(const __half* __restrict__ ACC1,
                                                            __half* __restrict__ OUT, int M) {
    extern __shared__ char smem_raw[];
    __nv_bfloat16* Sh = (__nv_bfloat16*)smem_raw;               // [64][264]
    __nv_bfloat16* Sl = Sh + 64 * 264;
    __nv_bfloat16* Bh = (__nv_bfloat16*)(smem_raw + 67584);     // [32][264]
    __nv_bfloat16* Bl = Bh + 32 * 264;
    float* smax = (float*)(smem_raw + 101376);                  // [64][4]
    float* ssum = smax + 256;
    __nv_bfloat16* Xh = Sh;                                     // overlay [64][136]
    __nv_bfloat16* Xl = Sh + 64 * 136;

    int tid = threadIdx.x;
    int warp = tid >> 5, lane = tid & 31;
    int wm = (warp >> 2) * 32;
    int wc = warp & 3;
    int row0 = blockIdx.x * 64;
    int r_l = lane & 15, c_l = (lane >> 4) << 3;

    // ---------- load X = leaky(acc1 tile, fp16), split bf16 ----------
    #pragma unroll
    for (int i = 0; i < 8; i++) {
        int v = tid + i * 256;
        int row = v >> 5, q = (v & 31) << 2;
        int gr = row0 + row;
        float4 a4 = make_float4(0.f, 0.f, 0.f, 0.f);
        if (gr < M) {
            uint2 raw = *(const uint2*)(ACC1 + (size_t)gr * 128 + q);
            float2 f0 = __half22float2(*(__half2*)&raw.x);
            float2 f1 = __half22float2(*(__half2*)&raw.y);
            a4 = make_float4(f0.x, f0.y, f1.x, f1.y);
        }
        a4.x = lrelu(a4.x); a4.y = lrelu(a4.y);
        a4.z = lrelu(a4.z); a4.w = lrelu(a4.w);
        split_bf16(a4.x, Xh[row * 136 + q + 0], Xl[row * 136 + q + 0]);
        split_bf16(a4.y, Xh[row * 136 + q + 1], Xl[row * 136 + q + 1]);
        split_bf16(a4.z, Xh[row * 136 + q + 2], Xl[row * 136 + q + 2]);
        split_bf16(a4.w, Xh[row * 136 + q + 3], Xl[row * 136 + q + 3]);
    }
    __syncthreads();

    // GEMM2: L = X @ Mcat   (64x256, K=128)
    int wn2 = wc * 64;
    float accA[2][8][4];
    #pragma unroll
    for (int mi = 0; mi < 2; mi++)
        #pragma unroll
        for (int ni = 0; ni < 8; ni++)
            #pragma unroll
            for (int t = 0; t < 4; t++) accA[mi][ni][t] = 0.f;

    for (int it = 0; it < 4; it++) {
        int k0 = it * 32;
        #pragma unroll
        for (int i = 0; i < 4; i++) {
            int s = tid + i * 256;
            int br = s >> 5, bc = (s & 31) << 3;
            *(uint4*)&Bh[br * 264 + bc] = *(const uint4*)(g_Mh + (size_t)(k0 + br) * 256 + bc);
            *(uint4*)&Bl[br * 264 + bc] = *(const uint4*)(g_Ml + (size_t)(k0 + br) * 256 + bc);
        }
        __syncthreads();
        #pragma unroll
        for (int s = 0; s < 2; s++) {
            int ks = k0 + s * 16;
            unsigned afh[2][4], afl[2][4];
            #pragma unroll
            for (int mi = 0; mi < 2; mi++) {
                ldsm_x4(afh[mi], &Xh[(wm + mi * 16 + r_l) * 136 + ks + c_l]);
                ldsm_x4(afl[mi], &Xl[(wm + mi * 16 + r_l) * 136 + ks + c_l]);
            }
            #pragma unroll
            for (int ni = 0; ni < 8; ni++) {
                unsigned bfh[2], bfl[2];
                ldsm_x2t(bfh, &Bh[(s * 16 + r_l) * 264 + wn2 + ni * 8]);
                ldsm_x2t(bfl, &Bl[(s * 16 + r_l) * 264 + wn2 + ni * 8]);
                #pragma unroll
                for (int mi = 0; mi < 2; mi++) {
                    mma_bf16(accA[mi][ni], afh[mi], bfh);
                    mma_bf16(accA[mi][ni], afh[mi], bfl);
                    mma_bf16(accA[mi][ni], afl[mi], bfh);
                }
            }
        }
        __syncthreads();
    }

    // softmax
    int hbase = (wc >> 1) << 1;
    #pragma unroll
    for (int mi = 0; mi < 2; mi++)
        #pragma unroll
        for (int half = 0; half < 2; half++) {
            float m = -1e30f;
            #pragma unroll
            for (int ni = 0; ni < 8; ni++)
                m = fmaxf(m, fmaxf(accA[mi][ni][2 * half], accA[mi][ni][2 * half + 1]));
            m = fmaxf(m, __shfl_xor_sync(0xffffffffu, m, 1));
            m = fmaxf(m, __shfl_xor_sync(0xffffffffu, m, 2));
            if ((lane & 3) == 0) {
                int rowg = wm + mi * 16 + (lane >> 2) + 8 * half;
                smax[rowg * 4 + wc] = m;
            }
        }
    __syncthreads();
    #pragma unroll
    for (int mi = 0; mi < 2; mi++)
        #pragma unroll
        for (int half = 0; half < 2; half++) {
            int rowg = wm + mi * 16 + (lane >> 2) + 8 * half;
            float mh = fmaxf(smax[rowg * 4 + hbase], smax[rowg * 4 + hbase + 1]);
            float s = 0.f;
            #pragma unroll
            for (int ni = 0; ni < 8; ni++) {
                float e0 = __expf(accA[mi][ni][2 * half] - mh);
                float e1 = __expf(accA[mi][ni][2 * half + 1] - mh);
                accA[mi][ni][2 * half] = e0;
                accA[mi][ni][2 * half + 1] = e1;
                s += e0 + e1;
            }
            s += __shfl_xor_sync(0xffffffffu, s, 1);
            s += __shfl_xor_sync(0xffffffffu, s, 2);
            if ((lane & 3) == 0) ssum[rowg * 4 + wc] = s;
        }
    __syncthreads();
    #pragma unroll
    for (int mi = 0; mi < 2; mi++)
        #pragma unroll
        for (int half = 0; half < 2; half++) {
            int rowg = wm + mi * 16 + (lane >> 2) + 8 * half;
            float inv = 1.f / (ssum[rowg * 4 + hbase] + ssum[rowg * 4 + hbase + 1]);
            #pragma unroll
            for (int ni = 0; ni < 8; ni++) {
                float w0 = accA[mi][ni][2 * half] * inv;
                float w1 = accA[mi][ni][2 * half + 1] * inv;
                int colg = wn2 + ni * 8 + 2 * (lane & 3);
                __nv_bfloat16 h0, l0, h1, l1;
                split_bf16(w0, h0, l0);
                split_bf16(w1, h1, l1);
                *(__nv_bfloat162*)&Sh[rowg * 264 + colg] = __nv_bfloat162(h0, h1);
                *(__nv_bfloat162*)&Sl[rowg * 264 + colg] = __nv_bfloat162(l0, l1);
            }
        }
    __syncthreads();

    // GEMM3: supp2 = leaky(S @ PW)   (64x128, K=256)  [register prefetch on B]
    int wn3 = wc * 32;
    int brw = tid >> 4, bcw = (tid & 15) << 3;
    float acc3[2][4][4];
    #pragma unroll
    for (int mi = 0; mi < 2; mi++)
        #pragma unroll
        for (int ni = 0; ni < 4; ni++)
            #pragma unroll
            for (int t = 0; t < 4; t++) acc3[mi][ni][t] = 0.f;

    uint4 pph[2], ppl[2];
    auto loadP = [&](int k0) {
        #pragma unroll
        for (int i = 0; i < 2; i++) {
            int br = brw + i * 16;
            pph[i] = *(const uint4*)(g_PWh + (size_t)(k0 + br) * 128 + bcw);
            ppl[i] = *(const uint4*)(g_PWl + (size_t)(k0 + br) * 128 + bcw);
        }
    };

    loadP(0);
    for (int it = 0; it < 8; it++) {
        #pragma unroll
        for (int i = 0; i < 2; i++) {
            int br = brw + i * 16;
            *(uint4*)&Bh[br * 264 + bcw] = pph[i];
            *(uint4*)&Bl[br * 264 + bcw] = ppl[i];
        }
        __syncthreads();
        if (it < 7) loadP((it + 1) * 32);
        #pragma unroll
        for (int s = 0; s < 2; s++) {
            int ks = it * 32 + s * 16;
            unsigned afh[2][4], afl[2][4];
            #pragma unroll
            for (int mi = 0; mi < 2; mi++) {
                ldsm_x4(afh[mi], &Sh[(wm + mi * 16 + r_l) * 264 + ks + c_l]);
                ldsm_x4(afl[mi], &Sl[(wm + mi * 16 + r_l) * 264 + ks + c_l]);
            }
            #pragma unroll
            for (int ni = 0; ni < 4; ni++) {
                unsigned bfh[2], bfl[2];
                ldsm_x2t(bfh, &Bh[(s * 16 + r_l) * 264 + wn3 + ni * 8]);
                ldsm_x2t(bfl, &Bl[(s * 16 + r_l) * 264 + wn3 + ni * 8]);
                #pragma unroll
                for (int mi = 0; mi < 2; mi++) {
                    mma_bf16(acc3[mi][ni], afh[mi], bfh);
                    mma_bf16(acc3[mi][ni], afh[mi], bfl);
                    mma_bf16(acc3[mi][ni], afl[mi], bfh);
                }
            }
        }
        __syncthreads();
    }

    // epilogue: leaky + fp16 store
    #pragma unroll
    for (int mi = 0; mi < 2; mi++)
        #pragma unroll
        for (int ni = 0; ni < 4; ni++) {
            int r = row0 + wm + mi * 16 + (lane >> 2);
            int c = wn3 + ni * 8 + (lane & 3) * 2;
            float v0 = lrelu(acc3[mi][ni][0]), v1 = lrelu(acc3[mi][ni][1]);
            float v2 = lrelu(acc3[mi][ni][2]), v3 = lrelu(acc3[mi][ni][3]);
            if (r < M)
                *(__half2*)(OUT + (size_t)r * 128 + c) = __floats2half2_rn(v0, v1);
            if (r + 8 < M)
                *(__half2*)(OUT + (size_t)(r + 8) * 128 + c) = __floats2half2_rn(v2, v3);
        }
}

// ---------------- CSR SpMM: warp per row, packed edges, fp16 gather ---------
template <bool FINAL>
__global__ void __launch_bounds__(256) csr_spmm_kernel(const __half* __restrict__ x,
                                                       void* __restrict__ outv, int Nn) {
    int w = (blockIdx.x * blockDim.x + threadIdx.x) >> 5;
    int lane = threadIdx.x & 31;
    if (w >= Nn) return;
    int s = g_off[w], e = g_off[w + 1];
    float4 acc = make_float4(0.f, 0.f, 0.f, 0.f);
    for (int base = s; base < e; base += 32) {
        int idx = base + lane;
        int c = 0;
        float v = 0.f;
        if (idx < e) {
            int2 ed = g_edge[idx];
            c = ed.x;
            v = __int_as_float(ed.y);
        }
        int n = min(32, e - base);
        for (int j = 0; j < n; j++) {
            int cj = __shfl_sync(0xffffffffu, c, j);
            float vj = __shfl_sync(0xffffffffu, v, j);
            uint2 raw = *(const uint2*)(x + (size_t)cj * 128 + lane * 4);
            float2 f0 = __half22float2(*(__half2*)&raw.x);
            float2 f1 = __half22float2(*(__half2*)&raw.y);
            acc.x += vj * f0.x;
            acc.y += vj * f0.y;
            acc.z += vj * f1.x;
            acc.w += vj * f1.y;
        }
    }
    if (FINAL) {
        float* out = (float*)outv;
        acc.x = lrelu(acc.x); acc.y = lrelu(acc.y);
        acc.z = lrelu(acc.z); acc.w = lrelu(acc.w);
        if (lane < 16)
            *(float4*)(out + (size_t)w * 64 + lane * 4) = acc;
        else
            *(float4*)(out + (size_t)Nn * 64 + (size_t)w * 64 + (lane - 16) * 4) = acc;
    } else {
        __half* out = (__half*)outv;
        __half2 p0 = __floats2half2_rn(acc.x, acc.y);
        __half2 p1 = __floats2half2_rn(acc.z, acc.w);
        uint2 packed;
        packed.x = *(unsigned*)&p0;
        packed.y = *(unsigned*)&p1;
        *(uint2*)(out + (size_t)w * 128 + lane * 4) = packed;
    }
}

// ---------------------------------------------------------------------------
extern "C" void kernel_launch(void* const* d_in, const int* in_sizes, int n_in,
                              void* d_out, int out_size) {
    const float* ns_emb = (const float*)d_in[0];
    const int* erow = (const int*)d_in[1];
    const int* ecol = (const int*)d_in[2];
    const float* eval_ = (const float*)d_in[3];
    const float* cond = (const float*)d_in[4];
    const float* Wh = (const float*)d_in[5];
    const float* Wmu = (const float*)d_in[6];
    const float* Wvar = (const float*)d_in[7];
    const float* Wq = (const float*)d_in[8];
    const float* Wk = (const float*)d_in[9];
    const float* Wv = (const float*)d_in[10];
    const float* Wo = (const float*)d_in[11];

    int N = in_sizes[0] / 256;
    int E = in_sizes[1];

    __half *supp1, *acc1, *supp2;
    cudaGetSymbolAddress((void**)&supp1, g_supp1);
    cudaGetSymbolAddress((void**)&acc1, g_acc1);
    cudaGetSymbolAddress((void**)&supp2, g_supp2);

    cudaFuncSetAttribute(attn_fused_kernel,
                         cudaFuncAttributeMaxDynamicSharedMemorySize, SMEM_FUSED);

    int gm = (N + 127) / 128;
    int gm64 = (N + 63) / 64;
    int nchunks = (N + 255) / 256;
    int spmm_blocks = (N * 32 + 255) / 256;

    // ---- fork two side streams: s2 = CSR build, s3 = weight folds ---------
    cudaStream_t s2, s3;
    cudaStreamCreate(&s2);
    cudaStreamCreate(&s3);
    cudaEvent_t e1, e2, e3;
    cudaEventCreateWithFlags(&e1, cudaEventDisableTiming);
    cudaEventCreateWithFlags(&e2, cudaEventDisableTiming);
    cudaEventCreateWithFlags(&e3, cudaEventDisableTiming);

    cudaEventRecord(e1, 0);
    cudaStreamWaitEvent(s2, e1, 0);
    cudaStreamWaitEvent(s3, e1, 0);

    // s2: CSR build chain (g_cnt is zero on entry; scanA re-zeros)
    hist_kernel<<<1024, 256, 0, s2>>>(erow, E);
    scanA_kernel<<<nchunks, 256, 0, s2>>>(N);
    scanBC_kernel<<<nchunks, 256, 0, s2>>>(N, E, nchunks);
    scatter_kernel<<<1024, 256, 0, s2>>>(erow, ecol, eval_, E);
    cudaEventRecord(e2, s2);

    // s3: weight fold chain
    prep_kernel<<<128, 256, 0, s3>>>(cond, Wk, Wv, Wmu, Wvar);
    fold_kernel<<<256, 256, 0, s3>>>(Wq, Wo);
    pw_kernel<<<128, 256, 0, s3>>>();
    cudaEventRecord(e3, s3);

    // main stream: gemm1 (Wh split inline) -> fp16 supp1
    gemm1_kernel<<<gm, 512>>>(ns_emb, Wh, supp1, N);

    // spmm1 needs CSR only
    cudaStreamWaitEvent(0, e2, 0);
    csr_spmm_kernel<false><<<spmm_blocks, 256>>>(supp1, acc1, N);

    // fused needs folded weights
    cudaStreamWaitEvent(0, e3, 0);
    attn_fused_kernel<<<gm64, 256, SMEM_FUSED>>>(acc1, supp2, N);

    // out = leaky(spmm(supp2)) split into mu|var  (fp32 output)
    csr_spmm_kernel<true><<<spmm_blocks, 256>>>(supp2, (float*)d_out, N);

    cudaEventDestroy(e1);
    cudaEventDestroy(e2);
    cudaEventDestroy(e3);
    cudaStreamDestroy(s2);
    cudaStreamDestroy(s3);
}